// round 2
// baseline (speedup 1.0000x reference)
#include <cuda_runtime.h>
#include <math.h>
#include <stdint.h>

// ---------------- problem constants ----------------
#define B_      8
#define Hh      64
#define Ww      64
#define Cc      384
#define HEADS   12
#define WSs     14
#define KD      32
#define Nt      196        // tokens per window (14*14)
#define NW      200        // windows total (8 * 5 * 5)
#define M_ATT   39200      // NW * Nt
#define L_      4096       // H*W
#define M_MLP   32768      // B * L
#define HID     1536
#define DH      384
#define QKVW    1152       // 3*DH
#define SCALE_F 0.17677669529663687f
#define EPS_F   1e-5f

// ---------------- scratch (device globals; no allocations) ----------------
__device__ float g_xn[M_ATT * Cc];            // LN'd windowed x
__device__ float g_qkv[(size_t)M_ATT * QKVW]; // qkv
__device__ float g_attno[M_ATT * Cc];         // attention output
__device__ float g_x1[M_MLP * Cc];            // after attn+residual
__device__ float g_x2[M_MLP * Cc];            // after conv+bn
__device__ float g_h1[(size_t)M_MLP * HID];   // fc1 output
__device__ float g_bias[HEADS * Nt * Nt];     // expanded rel-pos bias

// ---------------- kernel 1: expand bias table ----------------
__global__ void k_bias_expand(const float* __restrict__ ab,
                              const int* __restrict__ bidx, int n_off) {
    int i = blockIdx.x * blockDim.x + threadIdx.x;
    if (i >= HEADS * Nt * Nt) return;
    int h  = i / (Nt * Nt);
    int ij = i - h * (Nt * Nt);
    g_bias[i] = ab[h * n_off + bidx[ij]];
}

// ---------------- kernel 2: window partition + LayerNorm ----------------
__global__ void k_win_ln(const float* __restrict__ x,
                         const float* __restrict__ w,
                         const float* __restrict__ b) {
    int warp = (blockIdx.x * blockDim.x + threadIdx.x) >> 5;
    int lane = threadIdx.x & 31;
    if (warp >= M_ATT) return;
    int wi = warp / Nt, t = warp - wi * Nt;
    int bb = wi / 25; int rem = wi - bb * 25;
    int wy = rem / 5, wx = rem - wy * 5;
    int ty = t / WSs, tx = t - ty * WSs;
    int gy = wy * WSs + ty, gx = wx * WSs + tx;
    bool valid = (gy < Hh) && (gx < Ww);
    const float* src = x + ((size_t)bb * L_ + (size_t)gy * Ww + gx) * Cc;

    float vals[12];
    float s = 0.f, s2 = 0.f;
#pragma unroll
    for (int i = 0; i < 12; i++) {
        float v = valid ? src[lane + i * 32] : 0.f;
        vals[i] = v; s += v; s2 += v * v;
    }
#pragma unroll
    for (int o = 16; o > 0; o >>= 1) {
        s  += __shfl_xor_sync(0xffffffffu, s,  o);
        s2 += __shfl_xor_sync(0xffffffffu, s2, o);
    }
    float mean = s * (1.f / Cc);
    float var  = s2 * (1.f / Cc) - mean * mean;
    float rstd = rsqrtf(var + EPS_F);
    float* dst = g_xn + (size_t)warp * Cc;
#pragma unroll
    for (int i = 0; i < 12; i++) {
        int c = lane + i * 32;
        dst[c] = (vals[i] - mean) * rstd * w[c] + b[c];
    }
}

// ---------------- kernel 7: MLP LayerNorm (g_x2 -> g_xn), device globals
//                  referenced from DEVICE code only (round-1 bug fix) -------
__global__ void k_ln_mlp(const float* __restrict__ w,
                         const float* __restrict__ b) {
    int warp = (blockIdx.x * blockDim.x + threadIdx.x) >> 5;
    int lane = threadIdx.x & 31;
    if (warp >= M_MLP) return;
    const float* src = g_x2 + (size_t)warp * Cc;
    float vals[12];
    float s = 0.f, s2 = 0.f;
#pragma unroll
    for (int i = 0; i < 12; i++) {
        float v = src[lane + i * 32];
        vals[i] = v; s += v; s2 += v * v;
    }
#pragma unroll
    for (int o = 16; o > 0; o >>= 1) {
        s  += __shfl_xor_sync(0xffffffffu, s,  o);
        s2 += __shfl_xor_sync(0xffffffffu, s2, o);
    }
    float mean = s * (1.f / Cc);
    float var  = s2 * (1.f / Cc) - mean * mean;
    float rstd = rsqrtf(var + EPS_F);
    float* dst = g_xn + (size_t)warp * Cc;
#pragma unroll
    for (int i = 0; i < 12; i++) {
        int c = lane + i * 32;
        dst[c] = (vals[i] - mean) * rstd * w[c] + b[c];
    }
}

// ---------------- generic tiled fp32 GEMM: C[M,N] = A[M,K] @ B[N,K]^T + bias ----------------
// EPI: 0 = bias only, 1 = GELU(exact), 2 = proj un-window scatter + residual(x),
//      3 = residual add (res[m,n])
template <int EPI, int M, int Nn, int K>
__device__ __forceinline__ void gemm_body(const float* __restrict__ A,
                                          const float* __restrict__ Bw,
                                          const float* __restrict__ bias,
                                          float* __restrict__ Cout,
                                          const float* __restrict__ res) {
    __shared__ float As[8][128];
    __shared__ float Bs[8][128];
    const int tid = threadIdx.x;
    const int bm = blockIdx.y * 128, bn = blockIdx.x * 128;
    const int lrow = tid >> 1;          // 0..127
    const int lcol = (tid & 1) * 4;     // 0 or 4

    float acc[8][8];
#pragma unroll
    for (int i = 0; i < 8; i++)
#pragma unroll
        for (int j = 0; j < 8; j++) acc[i][j] = 0.f;

    const int tm = (tid >> 4) * 8;
    const int tn = (tid & 15) * 8;

    const bool aval = ((M % 128) == 0) || ((bm + lrow) < M);
    const float* Aptr = A  + (size_t)(bm + lrow) * K + lcol;
    const float* Bptr = Bw + (size_t)(bn + lrow) * K + lcol;

    for (int k0 = 0; k0 < K; k0 += 8) {
        float4 a = aval ? *(const float4*)(Aptr + k0) : make_float4(0.f, 0.f, 0.f, 0.f);
        float4 bb = *(const float4*)(Bptr + k0);
        As[lcol + 0][lrow] = a.x;  As[lcol + 1][lrow] = a.y;
        As[lcol + 2][lrow] = a.z;  As[lcol + 3][lrow] = a.w;
        Bs[lcol + 0][lrow] = bb.x; Bs[lcol + 1][lrow] = bb.y;
        Bs[lcol + 2][lrow] = bb.z; Bs[lcol + 3][lrow] = bb.w;
        __syncthreads();
#pragma unroll
        for (int kk = 0; kk < 8; kk++) {
            float4 a0 = *(const float4*)&As[kk][tm];
            float4 a1 = *(const float4*)&As[kk][tm + 4];
            float4 b0 = *(const float4*)&Bs[kk][tn];
            float4 b1 = *(const float4*)&Bs[kk][tn + 4];
            float av[8] = {a0.x, a0.y, a0.z, a0.w, a1.x, a1.y, a1.z, a1.w};
            float bv[8] = {b0.x, b0.y, b0.z, b0.w, b1.x, b1.y, b1.z, b1.w};
#pragma unroll
            for (int i = 0; i < 8; i++)
#pragma unroll
                for (int j = 0; j < 8; j++) acc[i][j] += av[i] * bv[j];
        }
        __syncthreads();
    }

#pragma unroll
    for (int i = 0; i < 8; i++) {
        int m = bm + tm + i;
        if (((M % 128) == 0) || (m < M)) {
#pragma unroll
            for (int j = 0; j < 8; j++) {
                int nn = bn + tn + j;
                float v = acc[i][j] + bias[nn];
                if (EPI == 0) {
                    Cout[(size_t)m * Nn + nn] = v;
                } else if (EPI == 1) {
                    Cout[(size_t)m * Nn + nn] =
                        0.5f * v * (1.f + erff(v * 0.70710678118654752f));
                } else if (EPI == 2) {
                    int wi = m / Nt, t = m - wi * Nt;
                    int bb2 = wi / 25; int rem = wi - bb2 * 25;
                    int wy = rem / 5, wx = rem - wy * 5;
                    int ty = t / WSs, tx = t - ty * WSs;
                    int gy = wy * WSs + ty, gx = wx * WSs + tx;
                    if (gy < Hh && gx < Ww) {
                        size_t o = ((size_t)bb2 * L_ + (size_t)gy * Ww + gx) * Cc + nn;
                        Cout[o] = res[o] + v;
                    }
                } else {
                    size_t o = (size_t)m * Nn + nn;
                    Cout[o] = v + res[o];
                }
            }
        }
    }
}

__global__ __launch_bounds__(256) void k_gemm_qkv(const float* __restrict__ w,
                                                  const float* __restrict__ b) {
    gemm_body<0, M_ATT, QKVW, Cc>(g_xn, w, b, g_qkv, nullptr);
}
__global__ __launch_bounds__(256) void k_gemm_proj(const float* __restrict__ w,
                                                   const float* __restrict__ b,
                                                   const float* __restrict__ x) {
    gemm_body<2, M_ATT, Cc, DH>(g_attno, w, b, g_x1, x);
}
__global__ __launch_bounds__(256) void k_gemm_fc1(const float* __restrict__ w,
                                                  const float* __restrict__ b) {
    gemm_body<1, M_MLP, HID, Cc>(g_xn, w, b, g_h1, nullptr);
}
__global__ __launch_bounds__(256) void k_gemm_fc2(const float* __restrict__ w,
                                                  const float* __restrict__ b,
                                                  float* __restrict__ out) {
    gemm_body<3, M_MLP, Cc, HID>(g_h1, w, b, out, g_x2);
}

// ---------------- kernel 4: fused attention, one block per (window, head) ----------------
__global__ __launch_bounds__(256) void k_attn() {
    __shared__ float ks[98 * KD];
    __shared__ float vs[98 * KD];
    const int blk = blockIdx.x;
    const int w = blk / HEADS, h = blk - w * HEADS;
    const float* base = g_qkv + (size_t)w * Nt * QKVW + h * 96;
    const int i = threadIdx.x;

    float q[KD], o[KD];
    float mi = -1e30f, li = 0.f;
    const float* brow = g_bias + ((size_t)h * Nt + (i < Nt ? i : 0)) * Nt;
    if (i < Nt) {
        const float* qp = base + (size_t)i * QKVW;
#pragma unroll
        for (int d = 0; d < KD; d++) { q[d] = qp[d]; o[d] = 0.f; }
    }

    for (int c = 0; c < 2; c++) {
        __syncthreads();
        for (int idx = threadIdx.x; idx < 98 * KD; idx += 256) {
            int r = idx >> 5, d = idx & 31;
            const float* rp = base + (size_t)(c * 98 + r) * QKVW;
            ks[idx] = rp[32 + d];
            vs[idx] = rp[64 + d];
        }
        __syncthreads();
        if (i < Nt) {
            for (int jj = 0; jj < 98; jj++) {
                const float* kj = ks + jj * KD;
                float s = 0.f;
#pragma unroll
                for (int d = 0; d < KD; d++) s += q[d] * kj[d];
                s = s * SCALE_F + brow[c * 98 + jj];
                float mnew = fmaxf(mi, s);
                float corr = __expf(mi - mnew);
                float p    = __expf(s - mnew);
                li = li * corr + p;
                const float* vj = vs + jj * KD;
#pragma unroll
                for (int d = 0; d < KD; d++) o[d] = o[d] * corr + p * vj[d];
                mi = mnew;
            }
        }
    }

    if (i < Nt) {
        float inv = 1.f / li;
        float* op = g_attno + ((size_t)(w * Nt + i)) * DH + h * KD;
#pragma unroll
        for (int d = 0; d < KD; d++) op[d] = o[d] * inv;
    }
}

// ---------------- kernel 5: depthwise 3x3 conv + BN (channel-last, float4) ----------------
__global__ void k_conv_bn(const float* __restrict__ cw,
                          const float* __restrict__ bnw,
                          const float* __restrict__ bnb,
                          const float* __restrict__ bnm,
                          const float* __restrict__ bnv) {
    int idx = blockIdx.x * blockDim.x + threadIdx.x;
    const int C4 = Cc / 4;
    const int total = B_ * Hh * Ww * C4;
    if (idx >= total) return;
    int c4 = idx % C4;
    int x  = (idx / C4) % Ww;
    int y  = (idx / (C4 * Ww)) % Hh;
    int b  = idx / (C4 * Ww * Hh);
    int c0 = c4 * 4;

    float4 acc = make_float4(0.f, 0.f, 0.f, 0.f);
#pragma unroll
    for (int ky = 0; ky < 3; ky++) {
        int yy = y + ky - 1;
        if (yy < 0 || yy >= Hh) continue;
#pragma unroll
        for (int kx = 0; kx < 3; kx++) {
            int xx = x + kx - 1;
            if (xx < 0 || xx >= Ww) continue;
            float4 in = *(const float4*)&g_x1[((size_t)b * L_ + (size_t)yy * Ww + xx) * Cc + c0];
            int wo = ky * 3 + kx;
            acc.x += in.x * cw[(c0 + 0) * 9 + wo];
            acc.y += in.y * cw[(c0 + 1) * 9 + wo];
            acc.z += in.z * cw[(c0 + 2) * 9 + wo];
            acc.w += in.w * cw[(c0 + 3) * 9 + wo];
        }
    }
    float4 outv;
    outv.x = (acc.x - bnm[c0 + 0]) * (rsqrtf(bnv[c0 + 0] + 1e-5f) * bnw[c0 + 0]) + bnb[c0 + 0];
    outv.y = (acc.y - bnm[c0 + 1]) * (rsqrtf(bnv[c0 + 1] + 1e-5f) * bnw[c0 + 1]) + bnb[c0 + 1];
    outv.z = (acc.z - bnm[c0 + 2]) * (rsqrtf(bnv[c0 + 2] + 1e-5f) * bnw[c0 + 2]) + bnb[c0 + 2];
    outv.w = (acc.w - bnm[c0 + 3]) * (rsqrtf(bnv[c0 + 3] + 1e-5f) * bnw[c0 + 3]) + bnb[c0 + 3];
    *(float4*)&g_x2[(size_t)idx * 4] = outv;
}

// ---------------- launcher ----------------
extern "C" void kernel_launch(void* const* d_in, const int* in_sizes, int n_in,
                              void* d_out, int out_size) {
    const float* x        = (const float*)d_in[0];
    const float* ln_aw    = (const float*)d_in[1];
    const float* ln_ab    = (const float*)d_in[2];
    const float* qkv_w    = (const float*)d_in[3];
    const float* qkv_b    = (const float*)d_in[4];
    const float* proj_w   = (const float*)d_in[5];
    const float* proj_b   = (const float*)d_in[6];
    const float* attn_bia = (const float*)d_in[7];
    const float* conv_w   = (const float*)d_in[8];
    const float* bn_w     = (const float*)d_in[9];
    const float* bn_b     = (const float*)d_in[10];
    const float* bn_m     = (const float*)d_in[11];
    const float* bn_v     = (const float*)d_in[12];
    const float* ln_mw    = (const float*)d_in[13];
    const float* ln_mb    = (const float*)d_in[14];
    const float* fc1_w    = (const float*)d_in[15];
    const float* fc1_b    = (const float*)d_in[16];
    const float* fc2_w    = (const float*)d_in[17];
    const float* fc2_b    = (const float*)d_in[18];
    const int*   bias_idx = (const int*)d_in[19];
    float* out = (float*)d_out;

    int n_off = in_sizes[7] / HEADS;

    // 1. expand relative-position bias
    {
        int tot = HEADS * Nt * Nt;
        k_bias_expand<<<(tot + 255) / 256, 256>>>(attn_bia, bias_idx, n_off);
    }
    // 2. window partition + LN
    k_win_ln<<<M_ATT / 8, 256>>>(x, ln_aw, ln_ab);
    // 3. QKV GEMM: 39200 x 1152 x 384
    k_gemm_qkv<<<dim3(QKVW / 128, (M_ATT + 127) / 128), 256>>>(qkv_w, qkv_b);
    // 4. fused window attention
    k_attn<<<NW * HEADS, 256>>>();
    // 5. proj GEMM + un-window + residual
    k_gemm_proj<<<dim3(Cc / 128, (M_ATT + 127) / 128), 256>>>(proj_w, proj_b, x);
    // 6. depthwise conv + BN
    {
        int tot = B_ * Hh * Ww * (Cc / 4);
        k_conv_bn<<<(tot + 255) / 256, 256>>>(conv_w, bn_w, bn_b, bn_m, bn_v);
    }
    // 7. MLP LayerNorm (device globals referenced in device code — round-1 fix)
    k_ln_mlp<<<M_MLP / 8, 256>>>(ln_mw, ln_mb);
    // 8. fc1 GEMM + exact GELU
    k_gemm_fc1<<<dim3(HID / 128, M_MLP / 128), 256>>>(fc1_w, fc1_b);
    // 9. fc2 GEMM + residual -> output
    k_gemm_fc2<<<dim3(Cc / 128, M_MLP / 128), 256>>>(fc2_w, fc2_b, out);
}

// round 3
// speedup vs baseline: 2.0667x; 2.0667x over previous
#include <cuda_runtime.h>
#include <math.h>
#include <stdint.h>

// ---------------- problem constants ----------------
#define B_      8
#define Hh      64
#define Ww      64
#define Cc      384
#define HEADS   12
#define WSs     14
#define KD      32
#define Nt      196
#define NW      200
#define M_ATT   39200
#define L_      4096
#define M_MLP   32768
#define HID     1536
#define DH      384
#define QKVW    1152
#define SCALE_F 0.17677669529663687f
#define EPS_F   1e-5f

// ---------------- scratch ----------------
__device__ float g_xn[M_ATT * Cc];
__device__ float g_qkv[(size_t)M_ATT * QKVW];
__device__ float g_attno[M_ATT * Cc];
__device__ float g_x1[M_MLP * Cc];
__device__ float g_x2[M_MLP * Cc];
__device__ float g_h1[(size_t)M_MLP * HID];
__device__ float g_bias[HEADS * Nt * Nt];

// ---------------- helpers ----------------
__device__ __forceinline__ float to_tf32(float x) {
    float r;
    asm("cvt.rna.tf32.f32 %0, %1;" : "=f"(r) : "f"(x));
    return r;
}

__device__ __forceinline__ void mma_tf32(float* c, const uint32_t* a, const uint32_t* b) {
    asm volatile(
        "mma.sync.aligned.m16n8k8.row.col.f32.tf32.tf32.f32 "
        "{%0,%1,%2,%3}, {%4,%5,%6,%7}, {%8,%9}, {%0,%1,%2,%3};\n"
        : "+f"(c[0]), "+f"(c[1]), "+f"(c[2]), "+f"(c[3])
        : "r"(a[0]), "r"(a[1]), "r"(a[2]), "r"(a[3]), "r"(b[0]), "r"(b[1]));
}

// ---------------- kernel 1: expand bias table ----------------
__global__ void k_bias_expand(const float* __restrict__ ab,
                              const int* __restrict__ bidx, int n_off) {
    int i = blockIdx.x * blockDim.x + threadIdx.x;
    if (i >= HEADS * Nt * Nt) return;
    int h  = i / (Nt * Nt);
    int ij = i - h * (Nt * Nt);
    g_bias[i] = ab[h * n_off + bidx[ij]];
}

// ---------------- kernel 2: window partition + LayerNorm ----------------
__global__ void k_win_ln(const float* __restrict__ x,
                         const float* __restrict__ w,
                         const float* __restrict__ b) {
    int warp = (blockIdx.x * blockDim.x + threadIdx.x) >> 5;
    int lane = threadIdx.x & 31;
    if (warp >= M_ATT) return;
    int wi = warp / Nt, t = warp - wi * Nt;
    int bb = wi / 25; int rem = wi - bb * 25;
    int wy = rem / 5, wx = rem - wy * 5;
    int ty = t / WSs, tx = t - ty * WSs;
    int gy = wy * WSs + ty, gx = wx * WSs + tx;
    bool valid = (gy < Hh) && (gx < Ww);
    const float* src = x + ((size_t)bb * L_ + (size_t)gy * Ww + gx) * Cc;

    float vals[12];
    float s = 0.f, s2 = 0.f;
#pragma unroll
    for (int i = 0; i < 12; i++) {
        float v = valid ? src[lane + i * 32] : 0.f;
        vals[i] = v; s += v; s2 += v * v;
    }
#pragma unroll
    for (int o = 16; o > 0; o >>= 1) {
        s  += __shfl_xor_sync(0xffffffffu, s,  o);
        s2 += __shfl_xor_sync(0xffffffffu, s2, o);
    }
    float mean = s * (1.f / Cc);
    float var  = s2 * (1.f / Cc) - mean * mean;
    float rstd = rsqrtf(var + EPS_F);
    float* dst = g_xn + (size_t)warp * Cc;
#pragma unroll
    for (int i = 0; i < 12; i++) {
        int c = lane + i * 32;
        dst[c] = (vals[i] - mean) * rstd * w[c] + b[c];
    }
}

// ---------------- kernel 7: MLP LayerNorm (g_x2 -> g_xn) ----------------
__global__ void k_ln_mlp(const float* __restrict__ w,
                         const float* __restrict__ b) {
    int warp = (blockIdx.x * blockDim.x + threadIdx.x) >> 5;
    int lane = threadIdx.x & 31;
    if (warp >= M_MLP) return;
    const float* src = g_x2 + (size_t)warp * Cc;
    float vals[12];
    float s = 0.f, s2 = 0.f;
#pragma unroll
    for (int i = 0; i < 12; i++) {
        float v = src[lane + i * 32];
        vals[i] = v; s += v; s2 += v * v;
    }
#pragma unroll
    for (int o = 16; o > 0; o >>= 1) {
        s  += __shfl_xor_sync(0xffffffffu, s,  o);
        s2 += __shfl_xor_sync(0xffffffffu, s2, o);
    }
    float mean = s * (1.f / Cc);
    float var  = s2 * (1.f / Cc) - mean * mean;
    float rstd = rsqrtf(var + EPS_F);
    float* dst = g_xn + (size_t)warp * Cc;
#pragma unroll
    for (int i = 0; i < 12; i++) {
        int c = lane + i * 32;
        dst[c] = (vals[i] - mean) * rstd * w[c] + b[c];
    }
}

// ---------------- tensor-core tf32 GEMM: C[M,N] = A[M,K] @ B[N,K]^T + bias --
// 128x128 block tile, BK=16, 8 warps of 64x32, m16n8k8 tf32 mma.
// EPI: 0 bias, 1 GELU, 2 proj un-window+residual, 3 residual add
template <int EPI, int M, int Nn, int K>
__device__ __forceinline__ void gemm_tc_body(const float* __restrict__ A,
                                             const float* __restrict__ Bw,
                                             const float* __restrict__ bias,
                                             float* __restrict__ Cout,
                                             const float* __restrict__ res) {
    __shared__ float As[2][128][20];
    __shared__ float Bs[2][128][20];
    const int tid = threadIdx.x, lane = tid & 31, wid = tid >> 5;
    const int g = lane >> 2, tig = lane & 3;
    const int warp_m = wid >> 2, warp_n = wid & 3;   // 2 x 4
    const int bm = blockIdx.y * 128, bn = blockIdx.x * 128;
    const int arow = tid >> 2, kcol = (tid & 3) * 4;

    float acc[4][4][4];
#pragma unroll
    for (int mt = 0; mt < 4; mt++)
#pragma unroll
        for (int nt = 0; nt < 4; nt++)
#pragma unroll
            for (int r = 0; r < 4; r++) acc[mt][nt][r] = 0.f;

    const int KT = K / 16;
    float4 pa0, pa1, pb0, pb1;
    const float4 z4 = make_float4(0.f, 0.f, 0.f, 0.f);

    // prologue: tile 0
    {
        int r0 = bm + arow, r1 = bm + arow + 64;
        bool v0 = ((M % 128) == 0) || (r0 < M);
        bool v1 = ((M % 128) == 0) || (r1 < M);
        pa0 = v0 ? *(const float4*)(A + (size_t)r0 * K + kcol) : z4;
        pa1 = v1 ? *(const float4*)(A + (size_t)r1 * K + kcol) : z4;
        pb0 = *(const float4*)(Bw + (size_t)(bn + arow) * K + kcol);
        pb1 = *(const float4*)(Bw + (size_t)(bn + arow + 64) * K + kcol);
        As[0][arow][kcol+0] = to_tf32(pa0.x); As[0][arow][kcol+1] = to_tf32(pa0.y);
        As[0][arow][kcol+2] = to_tf32(pa0.z); As[0][arow][kcol+3] = to_tf32(pa0.w);
        As[0][arow+64][kcol+0] = to_tf32(pa1.x); As[0][arow+64][kcol+1] = to_tf32(pa1.y);
        As[0][arow+64][kcol+2] = to_tf32(pa1.z); As[0][arow+64][kcol+3] = to_tf32(pa1.w);
        Bs[0][arow][kcol+0] = to_tf32(pb0.x); Bs[0][arow][kcol+1] = to_tf32(pb0.y);
        Bs[0][arow][kcol+2] = to_tf32(pb0.z); Bs[0][arow][kcol+3] = to_tf32(pb0.w);
        Bs[0][arow+64][kcol+0] = to_tf32(pb1.x); Bs[0][arow+64][kcol+1] = to_tf32(pb1.y);
        Bs[0][arow+64][kcol+2] = to_tf32(pb1.z); Bs[0][arow+64][kcol+3] = to_tf32(pb1.w);
    }
    __syncthreads();

    for (int kt = 0; kt < KT; kt++) {
        const int cur = kt & 1, nxt = cur ^ 1;
        if (kt + 1 < KT) {
            int k0 = (kt + 1) * 16 + kcol;
            int r0 = bm + arow, r1 = bm + arow + 64;
            bool v0 = ((M % 128) == 0) || (r0 < M);
            bool v1 = ((M % 128) == 0) || (r1 < M);
            pa0 = v0 ? *(const float4*)(A + (size_t)r0 * K + k0) : z4;
            pa1 = v1 ? *(const float4*)(A + (size_t)r1 * K + k0) : z4;
            pb0 = *(const float4*)(Bw + (size_t)(bn + arow) * K + k0);
            pb1 = *(const float4*)(Bw + (size_t)(bn + arow + 64) * K + k0);
        }
#pragma unroll
        for (int ks = 0; ks < 2; ks++) {
            const int kb = ks * 8;
            uint32_t afr[4][4], bfr[4][2];
#pragma unroll
            for (int mt = 0; mt < 4; mt++) {
                int r = warp_m * 64 + mt * 16;
                afr[mt][0] = __float_as_uint(As[cur][r + g    ][kb + tig]);
                afr[mt][1] = __float_as_uint(As[cur][r + g + 8][kb + tig]);
                afr[mt][2] = __float_as_uint(As[cur][r + g    ][kb + tig + 4]);
                afr[mt][3] = __float_as_uint(As[cur][r + g + 8][kb + tig + 4]);
            }
#pragma unroll
            for (int nt = 0; nt < 4; nt++) {
                int n = warp_n * 32 + nt * 8;
                bfr[nt][0] = __float_as_uint(Bs[cur][n + g][kb + tig]);
                bfr[nt][1] = __float_as_uint(Bs[cur][n + g][kb + tig + 4]);
            }
#pragma unroll
            for (int mt = 0; mt < 4; mt++)
#pragma unroll
                for (int nt = 0; nt < 4; nt++)
                    mma_tf32(acc[mt][nt], afr[mt], bfr[nt]);
        }
        if (kt + 1 < KT) {
            As[nxt][arow][kcol+0] = to_tf32(pa0.x); As[nxt][arow][kcol+1] = to_tf32(pa0.y);
            As[nxt][arow][kcol+2] = to_tf32(pa0.z); As[nxt][arow][kcol+3] = to_tf32(pa0.w);
            As[nxt][arow+64][kcol+0] = to_tf32(pa1.x); As[nxt][arow+64][kcol+1] = to_tf32(pa1.y);
            As[nxt][arow+64][kcol+2] = to_tf32(pa1.z); As[nxt][arow+64][kcol+3] = to_tf32(pa1.w);
            Bs[nxt][arow][kcol+0] = to_tf32(pb0.x); Bs[nxt][arow][kcol+1] = to_tf32(pb0.y);
            Bs[nxt][arow][kcol+2] = to_tf32(pb0.z); Bs[nxt][arow][kcol+3] = to_tf32(pb0.w);
            Bs[nxt][arow+64][kcol+0] = to_tf32(pb1.x); Bs[nxt][arow+64][kcol+1] = to_tf32(pb1.y);
            Bs[nxt][arow+64][kcol+2] = to_tf32(pb1.z); Bs[nxt][arow+64][kcol+3] = to_tf32(pb1.w);
        }
        __syncthreads();
    }

    // epilogue
#pragma unroll
    for (int mt = 0; mt < 4; mt++) {
#pragma unroll
        for (int nt = 0; nt < 4; nt++) {
#pragma unroll
            for (int r = 0; r < 4; r++) {
                int m  = bm + warp_m * 64 + mt * 16 + g + ((r >> 1) ? 8 : 0);
                int nn = bn + warp_n * 32 + nt * 8 + tig * 2 + (r & 1);
                if (((M % 128) != 0) && (m >= M)) continue;
                float v = acc[mt][nt][r] + bias[nn];
                if (EPI == 0) {
                    Cout[(size_t)m * Nn + nn] = v;
                } else if (EPI == 1) {
                    Cout[(size_t)m * Nn + nn] =
                        0.5f * v * (1.f + erff(v * 0.70710678118654752f));
                } else if (EPI == 2) {
                    int wi = m / Nt, t = m - wi * Nt;
                    int bb2 = wi / 25; int rem = wi - bb2 * 25;
                    int wy = rem / 5, wx = rem - wy * 5;
                    int ty = t / WSs, tx = t - ty * WSs;
                    int gy = wy * WSs + ty, gx = wx * WSs + tx;
                    if (gy < Hh && gx < Ww) {
                        size_t o = ((size_t)bb2 * L_ + (size_t)gy * Ww + gx) * Cc + nn;
                        Cout[o] = res[o] + v;
                    }
                } else {
                    size_t o = (size_t)m * Nn + nn;
                    Cout[o] = v + res[o];
                }
            }
        }
    }
}

__global__ __launch_bounds__(256) void k_gemm_qkv(const float* __restrict__ w,
                                                  const float* __restrict__ b) {
    gemm_tc_body<0, M_ATT, QKVW, Cc>(g_xn, w, b, g_qkv, nullptr);
}
__global__ __launch_bounds__(256) void k_gemm_proj(const float* __restrict__ w,
                                                   const float* __restrict__ b,
                                                   const float* __restrict__ x) {
    gemm_tc_body<2, M_ATT, Cc, DH>(g_attno, w, b, g_x1, x);
}
__global__ __launch_bounds__(256) void k_gemm_fc1(const float* __restrict__ w,
                                                  const float* __restrict__ b) {
    gemm_tc_body<1, M_MLP, HID, Cc>(g_xn, w, b, g_h1, nullptr);
}
__global__ __launch_bounds__(256) void k_gemm_fc2(const float* __restrict__ w,
                                                  const float* __restrict__ b,
                                                  float* __restrict__ out) {
    gemm_tc_body<3, M_MLP, Cc, HID>(g_h1, w, b, out, g_x2);
}

// ---------------- kernel 4: fused attention (float4 smem traffic) ----------
__global__ __launch_bounds__(256) void k_attn() {
    __shared__ float ks[98 * KD];
    __shared__ float vs[98 * KD];
    const int blk = blockIdx.x;
    const int w = blk / HEADS, h = blk - w * HEADS;
    const float* base = g_qkv + (size_t)w * Nt * QKVW + h * 96;
    const int i = threadIdx.x;

    float4 qv[8], o4[8];
    float mi = -1e30f, li = 0.f;
    const float* brow = g_bias + ((size_t)h * Nt + (i < Nt ? i : 0)) * Nt;
    if (i < Nt) {
        const float4* qp = (const float4*)(base + (size_t)i * QKVW);
#pragma unroll
        for (int d = 0; d < 8; d++) {
            qv[d] = qp[d];
            o4[d] = make_float4(0.f, 0.f, 0.f, 0.f);
        }
    }

    for (int c = 0; c < 2; c++) {
        __syncthreads();
        for (int idx = threadIdx.x; idx < 98 * 8; idx += 256) {
            int r = idx >> 3, d = (idx & 7) * 4;
            const float* rp = base + (size_t)(c * 98 + r) * QKVW;
            *(float4*)(ks + r * KD + d) = *(const float4*)(rp + 32 + d);
            *(float4*)(vs + r * KD + d) = *(const float4*)(rp + 64 + d);
        }
        __syncthreads();
        if (i < Nt) {
            for (int jj = 0; jj < 98; jj++) {
                const float4* k4 = (const float4*)(ks + jj * KD);
                float s = 0.f;
#pragma unroll
                for (int d = 0; d < 8; d++) {
                    float4 kk = k4[d];
                    s += qv[d].x * kk.x + qv[d].y * kk.y + qv[d].z * kk.z + qv[d].w * kk.w;
                }
                s = s * SCALE_F + brow[c * 98 + jj];
                float mnew = fmaxf(mi, s);
                float corr = __expf(mi - mnew);
                float p    = __expf(s - mnew);
                li = li * corr + p;
                const float4* v4 = (const float4*)(vs + jj * KD);
#pragma unroll
                for (int d = 0; d < 8; d++) {
                    float4 vv = v4[d];
                    o4[d].x = o4[d].x * corr + p * vv.x;
                    o4[d].y = o4[d].y * corr + p * vv.y;
                    o4[d].z = o4[d].z * corr + p * vv.z;
                    o4[d].w = o4[d].w * corr + p * vv.w;
                }
                mi = mnew;
            }
        }
    }

    if (i < Nt) {
        float inv = 1.f / li;
        float4* op = (float4*)(g_attno + ((size_t)(w * Nt + i)) * DH + h * KD);
#pragma unroll
        for (int d = 0; d < 8; d++) {
            op[d] = make_float4(o4[d].x * inv, o4[d].y * inv, o4[d].z * inv, o4[d].w * inv);
        }
    }
}

// ---------------- kernel 5: depthwise 3x3 conv + BN ----------------
__global__ void k_conv_bn(const float* __restrict__ cw,
                          const float* __restrict__ bnw,
                          const float* __restrict__ bnb,
                          const float* __restrict__ bnm,
                          const float* __restrict__ bnv) {
    int idx = blockIdx.x * blockDim.x + threadIdx.x;
    const int C4 = Cc / 4;
    const int total = B_ * Hh * Ww * C4;
    if (idx >= total) return;
    int c4 = idx % C4;
    int x  = (idx / C4) % Ww;
    int y  = (idx / (C4 * Ww)) % Hh;
    int b  = idx / (C4 * Ww * Hh);
    int c0 = c4 * 4;

    float4 acc = make_float4(0.f, 0.f, 0.f, 0.f);
#pragma unroll
    for (int ky = 0; ky < 3; ky++) {
        int yy = y + ky - 1;
        if (yy < 0 || yy >= Hh) continue;
#pragma unroll
        for (int kx = 0; kx < 3; kx++) {
            int xx = x + kx - 1;
            if (xx < 0 || xx >= Ww) continue;
            float4 in = *(const float4*)&g_x1[((size_t)b * L_ + (size_t)yy * Ww + xx) * Cc + c0];
            int wo = ky * 3 + kx;
            acc.x += in.x * cw[(c0 + 0) * 9 + wo];
            acc.y += in.y * cw[(c0 + 1) * 9 + wo];
            acc.z += in.z * cw[(c0 + 2) * 9 + wo];
            acc.w += in.w * cw[(c0 + 3) * 9 + wo];
        }
    }
    float4 outv;
    outv.x = (acc.x - bnm[c0 + 0]) * (rsqrtf(bnv[c0 + 0] + 1e-5f) * bnw[c0 + 0]) + bnb[c0 + 0];
    outv.y = (acc.y - bnm[c0 + 1]) * (rsqrtf(bnv[c0 + 1] + 1e-5f) * bnw[c0 + 1]) + bnb[c0 + 1];
    outv.z = (acc.z - bnm[c0 + 2]) * (rsqrtf(bnv[c0 + 2] + 1e-5f) * bnw[c0 + 2]) + bnb[c0 + 2];
    outv.w = (acc.w - bnm[c0 + 3]) * (rsqrtf(bnv[c0 + 3] + 1e-5f) * bnw[c0 + 3]) + bnb[c0 + 3];
    *(float4*)&g_x2[(size_t)idx * 4] = outv;
}

// ---------------- launcher ----------------
extern "C" void kernel_launch(void* const* d_in, const int* in_sizes, int n_in,
                              void* d_out, int out_size) {
    const float* x        = (const float*)d_in[0];
    const float* ln_aw    = (const float*)d_in[1];
    const float* ln_ab    = (const float*)d_in[2];
    const float* qkv_w    = (const float*)d_in[3];
    const float* qkv_b    = (const float*)d_in[4];
    const float* proj_w   = (const float*)d_in[5];
    const float* proj_b   = (const float*)d_in[6];
    const float* attn_bia = (const float*)d_in[7];
    const float* conv_w   = (const float*)d_in[8];
    const float* bn_w     = (const float*)d_in[9];
    const float* bn_b     = (const float*)d_in[10];
    const float* bn_m     = (const float*)d_in[11];
    const float* bn_v     = (const float*)d_in[12];
    const float* ln_mw    = (const float*)d_in[13];
    const float* ln_mb    = (const float*)d_in[14];
    const float* fc1_w    = (const float*)d_in[15];
    const float* fc1_b    = (const float*)d_in[16];
    const float* fc2_w    = (const float*)d_in[17];
    const float* fc2_b    = (const float*)d_in[18];
    const int*   bias_idx = (const int*)d_in[19];
    float* out = (float*)d_out;

    int n_off = in_sizes[7] / HEADS;

    {
        int tot = HEADS * Nt * Nt;
        k_bias_expand<<<(tot + 255) / 256, 256>>>(attn_bia, bias_idx, n_off);
    }
    k_win_ln<<<M_ATT / 8, 256>>>(x, ln_aw, ln_ab);
    k_gemm_qkv<<<dim3(QKVW / 128, (M_ATT + 127) / 128), 256>>>(qkv_w, qkv_b);
    k_attn<<<NW * HEADS, 256>>>();
    k_gemm_proj<<<dim3(Cc / 128, (M_ATT + 127) / 128), 256>>>(proj_w, proj_b, x);
    {
        int tot = B_ * Hh * Ww * (Cc / 4);
        k_conv_bn<<<(tot + 255) / 256, 256>>>(conv_w, bn_w, bn_b, bn_m, bn_v);
    }
    k_ln_mlp<<<M_MLP / 8, 256>>>(ln_mw, ln_mb);
    k_gemm_fc1<<<dim3(HID / 128, M_MLP / 128), 256>>>(fc1_w, fc1_b);
    k_gemm_fc2<<<dim3(Cc / 128, M_MLP / 128), 256>>>(fc2_w, fc2_b, out);
}

// round 4
// speedup vs baseline: 2.4984x; 1.2089x over previous
#include <cuda_runtime.h>
#include <math.h>
#include <stdint.h>

// ---------------- problem constants ----------------
#define B_      8
#define Hh      64
#define Ww      64
#define Cc      384
#define HEADS   12
#define WSs     14
#define KD      32
#define Nt      196
#define NW      200
#define M_ATT   39200
#define L_      4096
#define M_MLP   32768
#define HID     1536
#define DH      384
#define QKVW    1152
#define SCALE_F 0.17677669529663687f
#define EPS_F   1e-5f

// attention tiling
#define NTP        208      // Nt padded to 13*16
#define QS_STRIDE  36       // conflict-free for A/B fragment reads
#define VT_STRIDE  212      // conflict-free for V^T B fragment reads
#define SMEM_ATTN  ((2 * NTP * QS_STRIDE + KD * VT_STRIDE) * 4)

// ---------------- scratch ----------------
__device__ float g_xn[M_ATT * Cc];
__device__ float g_qkv[(size_t)M_ATT * QKVW];
__device__ float g_attno[M_ATT * Cc];
__device__ float g_x1[M_MLP * Cc];
__device__ float g_x2[M_MLP * Cc];
__device__ float g_h1[(size_t)M_MLP * HID];
__device__ float g_bias[HEADS * Nt * Nt];

// ---------------- helpers ----------------
__device__ __forceinline__ float to_tf32(float x) {
    float r;
    asm("cvt.rna.tf32.f32 %0, %1;" : "=f"(r) : "f"(x));
    return r;
}

__device__ __forceinline__ void mma_tf32(float* c, const uint32_t* a, const uint32_t* b) {
    asm volatile(
        "mma.sync.aligned.m16n8k8.row.col.f32.tf32.tf32.f32 "
        "{%0,%1,%2,%3}, {%4,%5,%6,%7}, {%8,%9}, {%0,%1,%2,%3};\n"
        : "+f"(c[0]), "+f"(c[1]), "+f"(c[2]), "+f"(c[3])
        : "r"(a[0]), "r"(a[1]), "r"(a[2]), "r"(a[3]), "r"(b[0]), "r"(b[1]));
}

// ---------------- kernel 1: expand bias table ----------------
__global__ void k_bias_expand(const float* __restrict__ ab,
                              const int* __restrict__ bidx, int n_off) {
    int i = blockIdx.x * blockDim.x + threadIdx.x;
    if (i >= HEADS * Nt * Nt) return;
    int h  = i / (Nt * Nt);
    int ij = i - h * (Nt * Nt);
    g_bias[i] = ab[h * n_off + bidx[ij]];
}

// ---------------- kernel 2: window partition + LayerNorm ----------------
__global__ void k_win_ln(const float* __restrict__ x,
                         const float* __restrict__ w,
                         const float* __restrict__ b) {
    int warp = (blockIdx.x * blockDim.x + threadIdx.x) >> 5;
    int lane = threadIdx.x & 31;
    if (warp >= M_ATT) return;
    int wi = warp / Nt, t = warp - wi * Nt;
    int bb = wi / 25; int rem = wi - bb * 25;
    int wy = rem / 5, wx = rem - wy * 5;
    int ty = t / WSs, tx = t - ty * WSs;
    int gy = wy * WSs + ty, gx = wx * WSs + tx;
    bool valid = (gy < Hh) && (gx < Ww);
    const float* src = x + ((size_t)bb * L_ + (size_t)gy * Ww + gx) * Cc;

    float vals[12];
    float s = 0.f, s2 = 0.f;
#pragma unroll
    for (int i = 0; i < 12; i++) {
        float v = valid ? src[lane + i * 32] : 0.f;
        vals[i] = v; s += v; s2 += v * v;
    }
#pragma unroll
    for (int o = 16; o > 0; o >>= 1) {
        s  += __shfl_xor_sync(0xffffffffu, s,  o);
        s2 += __shfl_xor_sync(0xffffffffu, s2, o);
    }
    float mean = s * (1.f / Cc);
    float var  = s2 * (1.f / Cc) - mean * mean;
    float rstd = rsqrtf(var + EPS_F);
    float* dst = g_xn + (size_t)warp * Cc;
#pragma unroll
    for (int i = 0; i < 12; i++) {
        int c = lane + i * 32;
        dst[c] = (vals[i] - mean) * rstd * w[c] + b[c];
    }
}

// ---------------- kernel 7: MLP LayerNorm (g_x2 -> g_xn) ----------------
__global__ void k_ln_mlp(const float* __restrict__ w,
                         const float* __restrict__ b) {
    int warp = (blockIdx.x * blockDim.x + threadIdx.x) >> 5;
    int lane = threadIdx.x & 31;
    if (warp >= M_MLP) return;
    const float* src = g_x2 + (size_t)warp * Cc;
    float vals[12];
    float s = 0.f, s2 = 0.f;
#pragma unroll
    for (int i = 0; i < 12; i++) {
        float v = src[lane + i * 32];
        vals[i] = v; s += v; s2 += v * v;
    }
#pragma unroll
    for (int o = 16; o > 0; o >>= 1) {
        s  += __shfl_xor_sync(0xffffffffu, s,  o);
        s2 += __shfl_xor_sync(0xffffffffu, s2, o);
    }
    float mean = s * (1.f / Cc);
    float var  = s2 * (1.f / Cc) - mean * mean;
    float rstd = rsqrtf(var + EPS_F);
    float* dst = g_xn + (size_t)warp * Cc;
#pragma unroll
    for (int i = 0; i < 12; i++) {
        int c = lane + i * 32;
        dst[c] = (vals[i] - mean) * rstd * w[c] + b[c];
    }
}

// ---------------- tensor-core tf32 GEMM (unchanged from round 3) ----------
template <int EPI, int M, int Nn, int K>
__device__ __forceinline__ void gemm_tc_body(const float* __restrict__ A,
                                             const float* __restrict__ Bw,
                                             const float* __restrict__ bias,
                                             float* __restrict__ Cout,
                                             const float* __restrict__ res) {
    __shared__ float As[2][128][20];
    __shared__ float Bs[2][128][20];
    const int tid = threadIdx.x, lane = tid & 31, wid = tid >> 5;
    const int g = lane >> 2, tig = lane & 3;
    const int warp_m = wid >> 2, warp_n = wid & 3;
    const int bm = blockIdx.y * 128, bn = blockIdx.x * 128;
    const int arow = tid >> 2, kcol = (tid & 3) * 4;

    float acc[4][4][4];
#pragma unroll
    for (int mt = 0; mt < 4; mt++)
#pragma unroll
        for (int nt = 0; nt < 4; nt++)
#pragma unroll
            for (int r = 0; r < 4; r++) acc[mt][nt][r] = 0.f;

    const int KT = K / 16;
    float4 pa0, pa1, pb0, pb1;
    const float4 z4 = make_float4(0.f, 0.f, 0.f, 0.f);

    {
        int r0 = bm + arow, r1 = bm + arow + 64;
        bool v0 = ((M % 128) == 0) || (r0 < M);
        bool v1 = ((M % 128) == 0) || (r1 < M);
        pa0 = v0 ? *(const float4*)(A + (size_t)r0 * K + kcol) : z4;
        pa1 = v1 ? *(const float4*)(A + (size_t)r1 * K + kcol) : z4;
        pb0 = *(const float4*)(Bw + (size_t)(bn + arow) * K + kcol);
        pb1 = *(const float4*)(Bw + (size_t)(bn + arow + 64) * K + kcol);
        As[0][arow][kcol+0] = to_tf32(pa0.x); As[0][arow][kcol+1] = to_tf32(pa0.y);
        As[0][arow][kcol+2] = to_tf32(pa0.z); As[0][arow][kcol+3] = to_tf32(pa0.w);
        As[0][arow+64][kcol+0] = to_tf32(pa1.x); As[0][arow+64][kcol+1] = to_tf32(pa1.y);
        As[0][arow+64][kcol+2] = to_tf32(pa1.z); As[0][arow+64][kcol+3] = to_tf32(pa1.w);
        Bs[0][arow][kcol+0] = to_tf32(pb0.x); Bs[0][arow][kcol+1] = to_tf32(pb0.y);
        Bs[0][arow][kcol+2] = to_tf32(pb0.z); Bs[0][arow][kcol+3] = to_tf32(pb0.w);
        Bs[0][arow+64][kcol+0] = to_tf32(pb1.x); Bs[0][arow+64][kcol+1] = to_tf32(pb1.y);
        Bs[0][arow+64][kcol+2] = to_tf32(pb1.z); Bs[0][arow+64][kcol+3] = to_tf32(pb1.w);
    }
    __syncthreads();

    for (int kt = 0; kt < KT; kt++) {
        const int cur = kt & 1, nxt = cur ^ 1;
        if (kt + 1 < KT) {
            int k0 = (kt + 1) * 16 + kcol;
            int r0 = bm + arow, r1 = bm + arow + 64;
            bool v0 = ((M % 128) == 0) || (r0 < M);
            bool v1 = ((M % 128) == 0) || (r1 < M);
            pa0 = v0 ? *(const float4*)(A + (size_t)r0 * K + k0) : z4;
            pa1 = v1 ? *(const float4*)(A + (size_t)r1 * K + k0) : z4;
            pb0 = *(const float4*)(Bw + (size_t)(bn + arow) * K + k0);
            pb1 = *(const float4*)(Bw + (size_t)(bn + arow + 64) * K + k0);
        }
#pragma unroll
        for (int ks = 0; ks < 2; ks++) {
            const int kb = ks * 8;
            uint32_t afr[4][4], bfr[4][2];
#pragma unroll
            for (int mt = 0; mt < 4; mt++) {
                int r = warp_m * 64 + mt * 16;
                afr[mt][0] = __float_as_uint(As[cur][r + g    ][kb + tig]);
                afr[mt][1] = __float_as_uint(As[cur][r + g + 8][kb + tig]);
                afr[mt][2] = __float_as_uint(As[cur][r + g    ][kb + tig + 4]);
                afr[mt][3] = __float_as_uint(As[cur][r + g + 8][kb + tig + 4]);
            }
#pragma unroll
            for (int nt = 0; nt < 4; nt++) {
                int n = warp_n * 32 + nt * 8;
                bfr[nt][0] = __float_as_uint(Bs[cur][n + g][kb + tig]);
                bfr[nt][1] = __float_as_uint(Bs[cur][n + g][kb + tig + 4]);
            }
#pragma unroll
            for (int mt = 0; mt < 4; mt++)
#pragma unroll
                for (int nt = 0; nt < 4; nt++)
                    mma_tf32(acc[mt][nt], afr[mt], bfr[nt]);
        }
        if (kt + 1 < KT) {
            As[nxt][arow][kcol+0] = to_tf32(pa0.x); As[nxt][arow][kcol+1] = to_tf32(pa0.y);
            As[nxt][arow][kcol+2] = to_tf32(pa0.z); As[nxt][arow][kcol+3] = to_tf32(pa0.w);
            As[nxt][arow+64][kcol+0] = to_tf32(pa1.x); As[nxt][arow+64][kcol+1] = to_tf32(pa1.y);
            As[nxt][arow+64][kcol+2] = to_tf32(pa1.z); As[nxt][arow+64][kcol+3] = to_tf32(pa1.w);
            Bs[nxt][arow][kcol+0] = to_tf32(pb0.x); Bs[nxt][arow][kcol+1] = to_tf32(pb0.y);
            Bs[nxt][arow][kcol+2] = to_tf32(pb0.z); Bs[nxt][arow][kcol+3] = to_tf32(pb0.w);
            Bs[nxt][arow+64][kcol+0] = to_tf32(pb1.x); Bs[nxt][arow+64][kcol+1] = to_tf32(pb1.y);
            Bs[nxt][arow+64][kcol+2] = to_tf32(pb1.z); Bs[nxt][arow+64][kcol+3] = to_tf32(pb1.w);
        }
        __syncthreads();
    }

#pragma unroll
    for (int mt = 0; mt < 4; mt++) {
#pragma unroll
        for (int nt = 0; nt < 4; nt++) {
#pragma unroll
            for (int r = 0; r < 4; r++) {
                int m  = bm + warp_m * 64 + mt * 16 + g + ((r >> 1) ? 8 : 0);
                int nn = bn + warp_n * 32 + nt * 8 + tig * 2 + (r & 1);
                if (((M % 128) != 0) && (m >= M)) continue;
                float v = acc[mt][nt][r] + bias[nn];
                if (EPI == 0) {
                    Cout[(size_t)m * Nn + nn] = v;
                } else if (EPI == 1) {
                    Cout[(size_t)m * Nn + nn] =
                        0.5f * v * (1.f + erff(v * 0.70710678118654752f));
                } else if (EPI == 2) {
                    int wi = m / Nt, t = m - wi * Nt;
                    int bb2 = wi / 25; int rem = wi - bb2 * 25;
                    int wy = rem / 5, wx = rem - wy * 5;
                    int ty = t / WSs, tx = t - ty * WSs;
                    int gy = wy * WSs + ty, gx = wx * WSs + tx;
                    if (gy < Hh && gx < Ww) {
                        size_t o = ((size_t)bb2 * L_ + (size_t)gy * Ww + gx) * Cc + nn;
                        Cout[o] = res[o] + v;
                    }
                } else {
                    size_t o = (size_t)m * Nn + nn;
                    Cout[o] = v + res[o];
                }
            }
        }
    }
}

__global__ __launch_bounds__(256) void k_gemm_qkv(const float* __restrict__ w,
                                                  const float* __restrict__ b) {
    gemm_tc_body<0, M_ATT, QKVW, Cc>(g_xn, w, b, g_qkv, nullptr);
}
__global__ __launch_bounds__(256) void k_gemm_proj(const float* __restrict__ w,
                                                   const float* __restrict__ b,
                                                   const float* __restrict__ x) {
    gemm_tc_body<2, M_ATT, Cc, DH>(g_attno, w, b, g_x1, x);
}
__global__ __launch_bounds__(256) void k_gemm_fc1(const float* __restrict__ w,
                                                  const float* __restrict__ b) {
    gemm_tc_body<1, M_MLP, HID, Cc>(g_xn, w, b, g_h1, nullptr);
}
__global__ __launch_bounds__(256) void k_gemm_fc2(const float* __restrict__ w,
                                                  const float* __restrict__ b,
                                                  float* __restrict__ out) {
    gemm_tc_body<3, M_MLP, Cc, HID>(g_h1, w, b, out, g_x2);
}

// ---------------- kernel 4: tensor-core attention ----------------
// one block per (window, head); 8 warps; full-row softmax in registers.
__global__ __launch_bounds__(256) void k_attn() {
    extern __shared__ float sm[];
    float* qs = sm;                            // [NTP][36], q * SCALE, tf32
    float* ks = sm + NTP * QS_STRIDE;          // [NTP][36], tf32
    float* vt = ks + NTP * QS_STRIDE;          // [KD][212], V^T, tf32

    const int blk = blockIdx.x;
    const int w = blk / HEADS, h = blk - w * HEADS;
    const float* base = g_qkv + (size_t)w * Nt * QKVW + h * 96;
    const int tid = threadIdx.x, lane = tid & 31, wid = tid >> 5;
    const int g = lane >> 2, tig = lane & 3;

    // stage Q*scale, K, V^T (tf32-rounded); zero pad rows >= 196
    for (int idx = tid; idx < NTP * 8; idx += 256) {
        int r = idx >> 3, d4 = (idx & 7) * 4;
        float4 q4, k4, v4;
        if (r < Nt) {
            const float* rp = base + (size_t)r * QKVW;
            q4 = *(const float4*)(rp + d4);
            k4 = *(const float4*)(rp + 32 + d4);
            v4 = *(const float4*)(rp + 64 + d4);
        } else {
            q4 = k4 = v4 = make_float4(0.f, 0.f, 0.f, 0.f);
        }
        float* qd = qs + r * QS_STRIDE + d4;
        qd[0] = to_tf32(q4.x * SCALE_F); qd[1] = to_tf32(q4.y * SCALE_F);
        qd[2] = to_tf32(q4.z * SCALE_F); qd[3] = to_tf32(q4.w * SCALE_F);
        float* kd = ks + r * QS_STRIDE + d4;
        kd[0] = to_tf32(k4.x); kd[1] = to_tf32(k4.y);
        kd[2] = to_tf32(k4.z); kd[3] = to_tf32(k4.w);
        vt[(d4 + 0) * VT_STRIDE + r] = to_tf32(v4.x);
        vt[(d4 + 1) * VT_STRIDE + r] = to_tf32(v4.y);
        vt[(d4 + 2) * VT_STRIDE + r] = to_tf32(v4.z);
        vt[(d4 + 3) * VT_STRIDE + r] = to_tf32(v4.w);
    }
    __syncthreads();

    const float* bias_h = g_bias + (size_t)h * Nt * Nt;

    for (int tt = wid; tt < 13; tt += 8) {
        const int row0 = tt * 16 + g, row1 = row0 + 8;

        // Q fragments for all 4 k-steps
        uint32_t aq[4][4];
#pragma unroll
        for (int kk = 0; kk < 4; kk++) {
            aq[kk][0] = __float_as_uint(qs[(tt*16 + g    ) * QS_STRIDE + kk*8 + tig]);
            aq[kk][1] = __float_as_uint(qs[(tt*16 + g + 8) * QS_STRIDE + kk*8 + tig]);
            aq[kk][2] = __float_as_uint(qs[(tt*16 + g    ) * QS_STRIDE + kk*8 + tig + 4]);
            aq[kk][3] = __float_as_uint(qs[(tt*16 + g + 8) * QS_STRIDE + kk*8 + tig + 4]);
        }

        // S = (Q*scale) @ K^T : 26 col-tiles of 8
        float acc[26][4];
#pragma unroll
        for (int nt = 0; nt < 26; nt++) {
            acc[nt][0] = acc[nt][1] = acc[nt][2] = acc[nt][3] = 0.f;
#pragma unroll
            for (int kk = 0; kk < 4; kk++) {
                uint32_t b[2];
                b[0] = __float_as_uint(ks[(nt*8 + g) * QS_STRIDE + kk*8 + tig]);
                b[1] = __float_as_uint(ks[(nt*8 + g) * QS_STRIDE + kk*8 + tig + 4]);
                mma_tf32(acc[nt], aq[kk], b);
            }
        }

        // add bias, mask invalid cols, row max
        const bool r0v = row0 < Nt, r1v = row1 < Nt;
        float m0 = -1e30f, m1 = -1e30f;
#pragma unroll
        for (int nt = 0; nt < 26; nt++) {
            int col = nt * 8 + tig * 2;
            bool cv = col < Nt;   // col even; col<196 implies col+1 <= 195
            float2 b0 = (cv && r0v) ? *(const float2*)(bias_h + (size_t)row0 * Nt + col)
                                    : make_float2(0.f, 0.f);
            float2 b1 = (cv && r1v) ? *(const float2*)(bias_h + (size_t)row1 * Nt + col)
                                    : make_float2(0.f, 0.f);
            acc[nt][0] = cv ? acc[nt][0] + b0.x : -1e30f;
            acc[nt][1] = cv ? acc[nt][1] + b0.y : -1e30f;
            acc[nt][2] = cv ? acc[nt][2] + b1.x : -1e30f;
            acc[nt][3] = cv ? acc[nt][3] + b1.y : -1e30f;
            m0 = fmaxf(m0, fmaxf(acc[nt][0], acc[nt][1]));
            m1 = fmaxf(m1, fmaxf(acc[nt][2], acc[nt][3]));
        }
        m0 = fmaxf(m0, __shfl_xor_sync(0xffffffffu, m0, 1));
        m0 = fmaxf(m0, __shfl_xor_sync(0xffffffffu, m0, 2));
        m1 = fmaxf(m1, __shfl_xor_sync(0xffffffffu, m1, 1));
        m1 = fmaxf(m1, __shfl_xor_sync(0xffffffffu, m1, 2));

        // exp + row sum
        float l0 = 0.f, l1 = 0.f;
#pragma unroll
        for (int nt = 0; nt < 26; nt++) {
            acc[nt][0] = __expf(acc[nt][0] - m0); l0 += acc[nt][0];
            acc[nt][1] = __expf(acc[nt][1] - m0); l0 += acc[nt][1];
            acc[nt][2] = __expf(acc[nt][2] - m1); l1 += acc[nt][2];
            acc[nt][3] = __expf(acc[nt][3] - m1); l1 += acc[nt][3];
        }
        l0 += __shfl_xor_sync(0xffffffffu, l0, 1);
        l0 += __shfl_xor_sync(0xffffffffu, l0, 2);
        l1 += __shfl_xor_sync(0xffffffffu, l1, 1);
        l1 += __shfl_xor_sync(0xffffffffu, l1, 2);

        // O = P @ V  (C-fragment -> A-fragment via intra-quad shuffles)
        float oacc[4][4];
#pragma unroll
        for (int nt = 0; nt < 4; nt++)
            oacc[nt][0] = oacc[nt][1] = oacc[nt][2] = oacc[nt][3] = 0.f;

        const int srcA = (lane & ~3) | (tig >> 1);
        const int srcB = (lane & ~3) | (2 + (tig >> 1));
        const bool odd = (tig & 1) != 0;
#pragma unroll
        for (int kk = 0; kk < 26; kk++) {
            float v00 = __shfl_sync(0xffffffffu, acc[kk][0], srcA);
            float v01 = __shfl_sync(0xffffffffu, acc[kk][1], srcA);
            float v20 = __shfl_sync(0xffffffffu, acc[kk][2], srcA);
            float v21 = __shfl_sync(0xffffffffu, acc[kk][3], srcA);
            float w00 = __shfl_sync(0xffffffffu, acc[kk][0], srcB);
            float w01 = __shfl_sync(0xffffffffu, acc[kk][1], srcB);
            float w20 = __shfl_sync(0xffffffffu, acc[kk][2], srcB);
            float w21 = __shfl_sync(0xffffffffu, acc[kk][3], srcB);
            uint32_t pa[4];
            pa[0] = __float_as_uint(to_tf32(odd ? v01 : v00));
            pa[1] = __float_as_uint(to_tf32(odd ? v21 : v20));
            pa[2] = __float_as_uint(to_tf32(odd ? w01 : w00));
            pa[3] = __float_as_uint(to_tf32(odd ? w21 : w20));
#pragma unroll
            for (int nt = 0; nt < 4; nt++) {
                uint32_t b[2];
                b[0] = __float_as_uint(vt[(nt*8 + g) * VT_STRIDE + kk*8 + tig]);
                b[1] = __float_as_uint(vt[(nt*8 + g) * VT_STRIDE + kk*8 + tig + 4]);
                mma_tf32(oacc[nt], pa, b);
            }
        }

        const float inv0 = 1.f / l0, inv1 = 1.f / l1;
        if (r0v) {
            float* op = g_attno + ((size_t)(w * Nt + row0)) * DH + h * KD;
#pragma unroll
            for (int nt = 0; nt < 4; nt++)
                *(float2*)(op + nt * 8 + tig * 2) =
                    make_float2(oacc[nt][0] * inv0, oacc[nt][1] * inv0);
        }
        if (r1v) {
            float* op = g_attno + ((size_t)(w * Nt + row1)) * DH + h * KD;
#pragma unroll
            for (int nt = 0; nt < 4; nt++)
                *(float2*)(op + nt * 8 + tig * 2) =
                    make_float2(oacc[nt][2] * inv1, oacc[nt][3] * inv1);
        }
    }
}

// ---------------- kernel 5: depthwise 3x3 conv + BN ----------------
__global__ void k_conv_bn(const float* __restrict__ cw,
                          const float* __restrict__ bnw,
                          const float* __restrict__ bnb,
                          const float* __restrict__ bnm,
                          const float* __restrict__ bnv) {
    int idx = blockIdx.x * blockDim.x + threadIdx.x;
    const int C4 = Cc / 4;
    const int total = B_ * Hh * Ww * C4;
    if (idx >= total) return;
    int c4 = idx % C4;
    int x  = (idx / C4) % Ww;
    int y  = (idx / (C4 * Ww)) % Hh;
    int b  = idx / (C4 * Ww * Hh);
    int c0 = c4 * 4;

    float4 acc = make_float4(0.f, 0.f, 0.f, 0.f);
#pragma unroll
    for (int ky = 0; ky < 3; ky++) {
        int yy = y + ky - 1;
        if (yy < 0 || yy >= Hh) continue;
#pragma unroll
        for (int kx = 0; kx < 3; kx++) {
            int xx = x + kx - 1;
            if (xx < 0 || xx >= Ww) continue;
            float4 in = *(const float4*)&g_x1[((size_t)b * L_ + (size_t)yy * Ww + xx) * Cc + c0];
            int wo = ky * 3 + kx;
            acc.x += in.x * cw[(c0 + 0) * 9 + wo];
            acc.y += in.y * cw[(c0 + 1) * 9 + wo];
            acc.z += in.z * cw[(c0 + 2) * 9 + wo];
            acc.w += in.w * cw[(c0 + 3) * 9 + wo];
        }
    }
    float4 outv;
    outv.x = (acc.x - bnm[c0 + 0]) * (rsqrtf(bnv[c0 + 0] + 1e-5f) * bnw[c0 + 0]) + bnb[c0 + 0];
    outv.y = (acc.y - bnm[c0 + 1]) * (rsqrtf(bnv[c0 + 1] + 1e-5f) * bnw[c0 + 1]) + bnb[c0 + 1];
    outv.z = (acc.z - bnm[c0 + 2]) * (rsqrtf(bnv[c0 + 2] + 1e-5f) * bnw[c0 + 2]) + bnb[c0 + 2];
    outv.w = (acc.w - bnm[c0 + 3]) * (rsqrtf(bnv[c0 + 3] + 1e-5f) * bnw[c0 + 3]) + bnb[c0 + 3];
    *(float4*)&g_x2[(size_t)idx * 4] = outv;
}

// ---------------- launcher ----------------
extern "C" void kernel_launch(void* const* d_in, const int* in_sizes, int n_in,
                              void* d_out, int out_size) {
    const float* x        = (const float*)d_in[0];
    const float* ln_aw    = (const float*)d_in[1];
    const float* ln_ab    = (const float*)d_in[2];
    const float* qkv_w    = (const float*)d_in[3];
    const float* qkv_b    = (const float*)d_in[4];
    const float* proj_w   = (const float*)d_in[5];
    const float* proj_b   = (const float*)d_in[6];
    const float* attn_bia = (const float*)d_in[7];
    const float* conv_w   = (const float*)d_in[8];
    const float* bn_w     = (const float*)d_in[9];
    const float* bn_b     = (const float*)d_in[10];
    const float* bn_m     = (const float*)d_in[11];
    const float* bn_v     = (const float*)d_in[12];
    const float* ln_mw    = (const float*)d_in[13];
    const float* ln_mb    = (const float*)d_in[14];
    const float* fc1_w    = (const float*)d_in[15];
    const float* fc1_b    = (const float*)d_in[16];
    const float* fc2_w    = (const float*)d_in[17];
    const float* fc2_b    = (const float*)d_in[18];
    const int*   bias_idx = (const int*)d_in[19];
    float* out = (float*)d_out;

    int n_off = in_sizes[7] / HEADS;

    {
        int tot = HEADS * Nt * Nt;
        k_bias_expand<<<(tot + 255) / 256, 256>>>(attn_bia, bias_idx, n_off);
    }
    k_win_ln<<<M_ATT / 8, 256>>>(x, ln_aw, ln_ab);
    k_gemm_qkv<<<dim3(QKVW / 128, (M_ATT + 127) / 128), 256>>>(qkv_w, qkv_b);

    cudaFuncSetAttribute(k_attn, cudaFuncAttributeMaxDynamicSharedMemorySize, SMEM_ATTN);
    k_attn<<<NW * HEADS, 256, SMEM_ATTN>>>();

    k_gemm_proj<<<dim3(Cc / 128, (M_ATT + 127) / 128), 256>>>(proj_w, proj_b, x);
    {
        int tot = B_ * Hh * Ww * (Cc / 4);
        k_conv_bn<<<(tot + 255) / 256, 256>>>(conv_w, bn_w, bn_b, bn_m, bn_v);
    }
    k_ln_mlp<<<M_MLP / 8, 256>>>(ln_mw, ln_mb);
    k_gemm_fc1<<<dim3(HID / 128, M_MLP / 128), 256>>>(fc1_w, fc1_b);
    k_gemm_fc2<<<dim3(Cc / 128, M_MLP / 128), 256>>>(fc2_w, fc2_b, out);
}

// round 5
// speedup vs baseline: 2.6415x; 1.0573x over previous
#include <cuda_runtime.h>
#include <math.h>
#include <stdint.h>

// ---------------- problem constants ----------------
#define B_      8
#define Hh      64
#define Ww      64
#define Cc      384
#define HEADS   12
#define WSs     14
#define KD      32
#define Nt      196
#define NW      200
#define M_ATT   39200
#define L_      4096
#define M_MLP   32768
#define HID     1536
#define DH      384
#define QKVW    1152
#define SCALE_F 0.17677669529663687f
#define EPS_F   1e-5f

// attention tiling
#define NTP        208
#define QS_STRIDE  36
#define VT_STRIDE  212
#define SMEM_ATTN  ((2 * NTP * QS_STRIDE + KD * VT_STRIDE) * 4)

// gemm smem: 3 stages x (A[128][20] + B[128][20]) floats
#define GSTAGE      (128 * 20)
#define SMEM_GEMM   (3 * GSTAGE * 2 * 4)

// ---------------- scratch ----------------
__device__ float g_xn[M_ATT * Cc];
__device__ float g_qkv[(size_t)M_ATT * QKVW];
__device__ float g_attno[M_ATT * Cc];
__device__ float g_x1[M_MLP * Cc];
__device__ float g_x2[M_MLP * Cc];
__device__ float g_h1[(size_t)M_MLP * HID];
__device__ float g_bias[HEADS * Nt * Nt];
// pre-rounded (tf32) weights
__device__ float g_wq[QKVW * Cc];
__device__ float g_wp[Cc * DH];
__device__ float g_w1[HID * Cc];
__device__ float g_w2[Cc * HID];

// ---------------- helpers ----------------
__device__ __forceinline__ float to_tf32(float x) {
    float r;
    asm("cvt.rna.tf32.f32 %0, %1;" : "=f"(r) : "f"(x));
    return r;
}

__device__ __forceinline__ void mma_tf32(float* c, const uint32_t* a, const uint32_t* b) {
    asm volatile(
        "mma.sync.aligned.m16n8k8.row.col.f32.tf32.tf32.f32 "
        "{%0,%1,%2,%3}, {%4,%5,%6,%7}, {%8,%9}, {%0,%1,%2,%3};\n"
        : "+f"(c[0]), "+f"(c[1]), "+f"(c[2]), "+f"(c[3])
        : "r"(a[0]), "r"(a[1]), "r"(a[2]), "r"(a[3]), "r"(b[0]), "r"(b[1]));
}

__device__ __forceinline__ void cp_async16(uint32_t saddr, const void* gptr, int srcbytes) {
    asm volatile("cp.async.cg.shared.global [%0], [%1], 16, %2;\n"
                 :: "r"(saddr), "l"(gptr), "r"(srcbytes));
}

// ---------------- weight rounding (float4) ----------------
__global__ void k_round4(const float4* __restrict__ src, float4* __restrict__ dst, int n4) {
    int i = blockIdx.x * blockDim.x + threadIdx.x;
    if (i >= n4) return;
    float4 v = src[i];
    dst[i] = make_float4(to_tf32(v.x), to_tf32(v.y), to_tf32(v.z), to_tf32(v.w));
}

// ---------------- kernel 1: expand bias table ----------------
__global__ void k_bias_expand(const float* __restrict__ ab,
                              const int* __restrict__ bidx, int n_off) {
    int i = blockIdx.x * blockDim.x + threadIdx.x;
    if (i >= HEADS * Nt * Nt) return;
    int h  = i / (Nt * Nt);
    int ij = i - h * (Nt * Nt);
    g_bias[i] = ab[h * n_off + bidx[ij]];
}

// ---------------- kernel 2: window partition + LayerNorm (tf32 out) --------
__global__ void k_win_ln(const float* __restrict__ x,
                         const float* __restrict__ w,
                         const float* __restrict__ b) {
    int warp = (blockIdx.x * blockDim.x + threadIdx.x) >> 5;
    int lane = threadIdx.x & 31;
    if (warp >= M_ATT) return;
    int wi = warp / Nt, t = warp - wi * Nt;
    int bb = wi / 25; int rem = wi - bb * 25;
    int wy = rem / 5, wx = rem - wy * 5;
    int ty = t / WSs, tx = t - ty * WSs;
    int gy = wy * WSs + ty, gx = wx * WSs + tx;
    bool valid = (gy < Hh) && (gx < Ww);
    const float* src = x + ((size_t)bb * L_ + (size_t)gy * Ww + gx) * Cc;

    float vals[12];
    float s = 0.f, s2 = 0.f;
#pragma unroll
    for (int i = 0; i < 12; i++) {
        float v = valid ? src[lane + i * 32] : 0.f;
        vals[i] = v; s += v; s2 += v * v;
    }
#pragma unroll
    for (int o = 16; o > 0; o >>= 1) {
        s  += __shfl_xor_sync(0xffffffffu, s,  o);
        s2 += __shfl_xor_sync(0xffffffffu, s2, o);
    }
    float mean = s * (1.f / Cc);
    float var  = s2 * (1.f / Cc) - mean * mean;
    float rstd = rsqrtf(var + EPS_F);
    float* dst = g_xn + (size_t)warp * Cc;
#pragma unroll
    for (int i = 0; i < 12; i++) {
        int c = lane + i * 32;
        dst[c] = to_tf32((vals[i] - mean) * rstd * w[c] + b[c]);
    }
}

// ---------------- kernel 7: MLP LayerNorm (tf32 out) ----------------
__global__ void k_ln_mlp(const float* __restrict__ w,
                         const float* __restrict__ b) {
    int warp = (blockIdx.x * blockDim.x + threadIdx.x) >> 5;
    int lane = threadIdx.x & 31;
    if (warp >= M_MLP) return;
    const float* src = g_x2 + (size_t)warp * Cc;
    float vals[12];
    float s = 0.f, s2 = 0.f;
#pragma unroll
    for (int i = 0; i < 12; i++) {
        float v = src[lane + i * 32];
        vals[i] = v; s += v; s2 += v * v;
    }
#pragma unroll
    for (int o = 16; o > 0; o >>= 1) {
        s  += __shfl_xor_sync(0xffffffffu, s,  o);
        s2 += __shfl_xor_sync(0xffffffffu, s2, o);
    }
    float mean = s * (1.f / Cc);
    float var  = s2 * (1.f / Cc) - mean * mean;
    float rstd = rsqrtf(var + EPS_F);
    float* dst = g_xn + (size_t)warp * Cc;
#pragma unroll
    for (int i = 0; i < 12; i++) {
        int c = lane + i * 32;
        dst[c] = to_tf32((vals[i] - mean) * rstd * w[c] + b[c]);
    }
}

// ---------------- tf32 GEMM, cp.async 3-stage pipeline ----------------
// A and Bw are ALREADY tf32-rounded. C[M,N] = A[M,K] @ Bw[N,K]^T + bias.
// EPI: 0 bias, 1 GELU(tf32 out), 2 proj un-window+residual, 3 residual add
template <int EPI, int M, int Nn, int K>
__device__ __forceinline__ void gemm_tc_body(const float* __restrict__ A,
                                             const float* __restrict__ Bw,
                                             const float* __restrict__ bias,
                                             float* __restrict__ Cout,
                                             const float* __restrict__ res) {
    extern __shared__ float smbuf[];
    float* As = smbuf;                 // [3][128*20]
    float* Bs = smbuf + 3 * GSTAGE;    // [3][128*20]

    const int tid = threadIdx.x, lane = tid & 31, wid = tid >> 5;
    const int g = lane >> 2, tig = lane & 3;
    const int warp_m = wid >> 2, warp_n = wid & 3;
    const int bm = blockIdx.y * 128, bn = blockIdx.x * 128;
    const int arow = tid >> 2, kcol = (tid & 3) * 4;

    const int r0 = bm + arow, r1 = r0 + 64;
    const bool v0 = ((M % 128) == 0) || (r0 < M);
    const bool v1 = ((M % 128) == 0) || (r1 < M);
    const int sz0 = v0 ? 16 : 0, sz1 = v1 ? 16 : 0;
    const float* a0b = A  + (size_t)(v0 ? r0 : 0) * K + kcol;
    const float* a1b = A  + (size_t)(v1 ? r1 : 0) * K + kcol;
    const float* b0b = Bw + (size_t)(bn + arow) * K + kcol;
    const float* b1b = Bw + (size_t)(bn + arow + 64) * K + kcol;
    const uint32_t sa0 = (uint32_t)__cvta_generic_to_shared(As + arow * 20 + kcol);
    const uint32_t sa1 = (uint32_t)__cvta_generic_to_shared(As + (arow + 64) * 20 + kcol);
    const uint32_t sb0 = (uint32_t)__cvta_generic_to_shared(Bs + arow * 20 + kcol);
    const uint32_t sb1 = (uint32_t)__cvta_generic_to_shared(Bs + (arow + 64) * 20 + kcol);

    const int KT = K / 16;
    auto load_stage = [&](int s, int kt) {
        int k0 = kt * 16;
        uint32_t so = (uint32_t)(s * GSTAGE * 4);
        cp_async16(sa0 + so, a0b + k0, sz0);
        cp_async16(sa1 + so, a1b + k0, sz1);
        cp_async16(sb0 + so, b0b + k0, 16);
        cp_async16(sb1 + so, b1b + k0, 16);
        asm volatile("cp.async.commit_group;\n");
    };

    float acc[4][4][4];
#pragma unroll
    for (int mt = 0; mt < 4; mt++)
#pragma unroll
        for (int nt = 0; nt < 4; nt++)
#pragma unroll
            for (int r = 0; r < 4; r++) acc[mt][nt][r] = 0.f;

    load_stage(0, 0);
    load_stage(1, 1);

    for (int kt = 0; kt < KT; kt++) {
        if (kt + 1 < KT) {
            asm volatile("cp.async.wait_group 1;\n");
        } else {
            asm volatile("cp.async.wait_group 0;\n");
        }
        __syncthreads();
        if (kt + 2 < KT) load_stage((kt + 2) % 3, kt + 2);

        const float* Ac = As + (kt % 3) * GSTAGE;
        const float* Bc = Bs + (kt % 3) * GSTAGE;
#pragma unroll
        for (int ks = 0; ks < 2; ks++) {
            const int kb = ks * 8;
            uint32_t afr[4][4], bfr[4][2];
#pragma unroll
            for (int mt = 0; mt < 4; mt++) {
                int r = warp_m * 64 + mt * 16;
                afr[mt][0] = __float_as_uint(Ac[(r + g    ) * 20 + kb + tig]);
                afr[mt][1] = __float_as_uint(Ac[(r + g + 8) * 20 + kb + tig]);
                afr[mt][2] = __float_as_uint(Ac[(r + g    ) * 20 + kb + tig + 4]);
                afr[mt][3] = __float_as_uint(Ac[(r + g + 8) * 20 + kb + tig + 4]);
            }
#pragma unroll
            for (int nt = 0; nt < 4; nt++) {
                int n = warp_n * 32 + nt * 8;
                bfr[nt][0] = __float_as_uint(Bc[(n + g) * 20 + kb + tig]);
                bfr[nt][1] = __float_as_uint(Bc[(n + g) * 20 + kb + tig + 4]);
            }
#pragma unroll
            for (int mt = 0; mt < 4; mt++)
#pragma unroll
                for (int nt = 0; nt < 4; nt++)
                    mma_tf32(acc[mt][nt], afr[mt], bfr[nt]);
        }
        __syncthreads();
    }

#pragma unroll
    for (int mt = 0; mt < 4; mt++) {
#pragma unroll
        for (int nt = 0; nt < 4; nt++) {
#pragma unroll
            for (int r = 0; r < 4; r++) {
                int m  = bm + warp_m * 64 + mt * 16 + g + ((r >> 1) ? 8 : 0);
                int nn = bn + warp_n * 32 + nt * 8 + tig * 2 + (r & 1);
                if (((M % 128) != 0) && (m >= M)) continue;
                float v = acc[mt][nt][r] + bias[nn];
                if (EPI == 0) {
                    Cout[(size_t)m * Nn + nn] = v;
                } else if (EPI == 1) {
                    Cout[(size_t)m * Nn + nn] =
                        to_tf32(0.5f * v * (1.f + erff(v * 0.70710678118654752f)));
                } else if (EPI == 2) {
                    int wi = m / Nt, t = m - wi * Nt;
                    int bb2 = wi / 25; int rem = wi - bb2 * 25;
                    int wy = rem / 5, wx = rem - wy * 5;
                    int ty = t / WSs, tx = t - ty * WSs;
                    int gy = wy * WSs + ty, gx = wx * WSs + tx;
                    if (gy < Hh && gx < Ww) {
                        size_t o = ((size_t)bb2 * L_ + (size_t)gy * Ww + gx) * Cc + nn;
                        Cout[o] = res[o] + v;
                    }
                } else {
                    size_t o = (size_t)m * Nn + nn;
                    Cout[o] = v + res[o];
                }
            }
        }
    }
}

__global__ __launch_bounds__(256) void k_gemm_qkv(const float* __restrict__ b) {
    gemm_tc_body<0, M_ATT, QKVW, Cc>(g_xn, g_wq, b, g_qkv, nullptr);
}
__global__ __launch_bounds__(256) void k_gemm_proj(const float* __restrict__ b,
                                                   const float* __restrict__ x) {
    gemm_tc_body<2, M_ATT, Cc, DH>(g_attno, g_wp, b, g_x1, x);
}
__global__ __launch_bounds__(256) void k_gemm_fc1(const float* __restrict__ b) {
    gemm_tc_body<1, M_MLP, HID, Cc>(g_xn, g_w1, b, g_h1, nullptr);
}
__global__ __launch_bounds__(256) void k_gemm_fc2(const float* __restrict__ b,
                                                  float* __restrict__ out) {
    gemm_tc_body<3, M_MLP, Cc, HID>(g_h1, g_w2, b, out, g_x2);
}

// ---------------- kernel 4: tensor-core attention (tf32 out) ---------------
__global__ __launch_bounds__(256) void k_attn() {
    extern __shared__ float sm[];
    float* qs = sm;
    float* ks = sm + NTP * QS_STRIDE;
    float* vt = ks + NTP * QS_STRIDE;

    const int blk = blockIdx.x;
    const int w = blk / HEADS, h = blk - w * HEADS;
    const float* base = g_qkv + (size_t)w * Nt * QKVW + h * 96;
    const int tid = threadIdx.x, lane = tid & 31, wid = tid >> 5;
    const int g = lane >> 2, tig = lane & 3;

    for (int idx = tid; idx < NTP * 8; idx += 256) {
        int r = idx >> 3, d4 = (idx & 7) * 4;
        float4 q4, k4, v4;
        if (r < Nt) {
            const float* rp = base + (size_t)r * QKVW;
            q4 = *(const float4*)(rp + d4);
            k4 = *(const float4*)(rp + 32 + d4);
            v4 = *(const float4*)(rp + 64 + d4);
        } else {
            q4 = k4 = v4 = make_float4(0.f, 0.f, 0.f, 0.f);
        }
        float* qd = qs + r * QS_STRIDE + d4;
        qd[0] = to_tf32(q4.x * SCALE_F); qd[1] = to_tf32(q4.y * SCALE_F);
        qd[2] = to_tf32(q4.z * SCALE_F); qd[3] = to_tf32(q4.w * SCALE_F);
        float* kd = ks + r * QS_STRIDE + d4;
        kd[0] = to_tf32(k4.x); kd[1] = to_tf32(k4.y);
        kd[2] = to_tf32(k4.z); kd[3] = to_tf32(k4.w);
        vt[(d4 + 0) * VT_STRIDE + r] = to_tf32(v4.x);
        vt[(d4 + 1) * VT_STRIDE + r] = to_tf32(v4.y);
        vt[(d4 + 2) * VT_STRIDE + r] = to_tf32(v4.z);
        vt[(d4 + 3) * VT_STRIDE + r] = to_tf32(v4.w);
    }
    __syncthreads();

    const float* bias_h = g_bias + (size_t)h * Nt * Nt;

    for (int tt = wid; tt < 13; tt += 8) {
        const int row0 = tt * 16 + g, row1 = row0 + 8;

        uint32_t aq[4][4];
#pragma unroll
        for (int kk = 0; kk < 4; kk++) {
            aq[kk][0] = __float_as_uint(qs[(tt*16 + g    ) * QS_STRIDE + kk*8 + tig]);
            aq[kk][1] = __float_as_uint(qs[(tt*16 + g + 8) * QS_STRIDE + kk*8 + tig]);
            aq[kk][2] = __float_as_uint(qs[(tt*16 + g    ) * QS_STRIDE + kk*8 + tig + 4]);
            aq[kk][3] = __float_as_uint(qs[(tt*16 + g + 8) * QS_STRIDE + kk*8 + tig + 4]);
        }

        float acc[26][4];
#pragma unroll
        for (int nt = 0; nt < 26; nt++) {
            acc[nt][0] = acc[nt][1] = acc[nt][2] = acc[nt][3] = 0.f;
#pragma unroll
            for (int kk = 0; kk < 4; kk++) {
                uint32_t b[2];
                b[0] = __float_as_uint(ks[(nt*8 + g) * QS_STRIDE + kk*8 + tig]);
                b[1] = __float_as_uint(ks[(nt*8 + g) * QS_STRIDE + kk*8 + tig + 4]);
                mma_tf32(acc[nt], aq[kk], b);
            }
        }

        const bool r0v = row0 < Nt, r1v = row1 < Nt;
        float m0 = -1e30f, m1 = -1e30f;
#pragma unroll
        for (int nt = 0; nt < 26; nt++) {
            int col = nt * 8 + tig * 2;
            bool cv = col < Nt;
            float2 b0 = (cv && r0v) ? *(const float2*)(bias_h + (size_t)row0 * Nt + col)
                                    : make_float2(0.f, 0.f);
            float2 b1 = (cv && r1v) ? *(const float2*)(bias_h + (size_t)row1 * Nt + col)
                                    : make_float2(0.f, 0.f);
            acc[nt][0] = cv ? acc[nt][0] + b0.x : -1e30f;
            acc[nt][1] = cv ? acc[nt][1] + b0.y : -1e30f;
            acc[nt][2] = cv ? acc[nt][2] + b1.x : -1e30f;
            acc[nt][3] = cv ? acc[nt][3] + b1.y : -1e30f;
            m0 = fmaxf(m0, fmaxf(acc[nt][0], acc[nt][1]));
            m1 = fmaxf(m1, fmaxf(acc[nt][2], acc[nt][3]));
        }
        m0 = fmaxf(m0, __shfl_xor_sync(0xffffffffu, m0, 1));
        m0 = fmaxf(m0, __shfl_xor_sync(0xffffffffu, m0, 2));
        m1 = fmaxf(m1, __shfl_xor_sync(0xffffffffu, m1, 1));
        m1 = fmaxf(m1, __shfl_xor_sync(0xffffffffu, m1, 2));

        float l0 = 0.f, l1 = 0.f;
#pragma unroll
        for (int nt = 0; nt < 26; nt++) {
            acc[nt][0] = __expf(acc[nt][0] - m0); l0 += acc[nt][0];
            acc[nt][1] = __expf(acc[nt][1] - m0); l0 += acc[nt][1];
            acc[nt][2] = __expf(acc[nt][2] - m1); l1 += acc[nt][2];
            acc[nt][3] = __expf(acc[nt][3] - m1); l1 += acc[nt][3];
        }
        l0 += __shfl_xor_sync(0xffffffffu, l0, 1);
        l0 += __shfl_xor_sync(0xffffffffu, l0, 2);
        l1 += __shfl_xor_sync(0xffffffffu, l1, 1);
        l1 += __shfl_xor_sync(0xffffffffu, l1, 2);

        float oacc[4][4];
#pragma unroll
        for (int nt = 0; nt < 4; nt++)
            oacc[nt][0] = oacc[nt][1] = oacc[nt][2] = oacc[nt][3] = 0.f;

        const int srcA = (lane & ~3) | (tig >> 1);
        const int srcB = (lane & ~3) | (2 + (tig >> 1));
        const bool odd = (tig & 1) != 0;
#pragma unroll
        for (int kk = 0; kk < 26; kk++) {
            float v00 = __shfl_sync(0xffffffffu, acc[kk][0], srcA);
            float v01 = __shfl_sync(0xffffffffu, acc[kk][1], srcA);
            float v20 = __shfl_sync(0xffffffffu, acc[kk][2], srcA);
            float v21 = __shfl_sync(0xffffffffu, acc[kk][3], srcA);
            float w00 = __shfl_sync(0xffffffffu, acc[kk][0], srcB);
            float w01 = __shfl_sync(0xffffffffu, acc[kk][1], srcB);
            float w20 = __shfl_sync(0xffffffffu, acc[kk][2], srcB);
            float w21 = __shfl_sync(0xffffffffu, acc[kk][3], srcB);
            uint32_t pa[4];
            pa[0] = __float_as_uint(to_tf32(odd ? v01 : v00));
            pa[1] = __float_as_uint(to_tf32(odd ? v21 : v20));
            pa[2] = __float_as_uint(to_tf32(odd ? w01 : w00));
            pa[3] = __float_as_uint(to_tf32(odd ? w21 : w20));
#pragma unroll
            for (int nt = 0; nt < 4; nt++) {
                uint32_t b[2];
                b[0] = __float_as_uint(vt[(nt*8 + g) * VT_STRIDE + kk*8 + tig]);
                b[1] = __float_as_uint(vt[(nt*8 + g) * VT_STRIDE + kk*8 + tig + 4]);
                mma_tf32(oacc[nt], pa, b);
            }
        }

        const float inv0 = 1.f / l0, inv1 = 1.f / l1;
        if (r0v) {
            float* op = g_attno + ((size_t)(w * Nt + row0)) * DH + h * KD;
#pragma unroll
            for (int nt = 0; nt < 4; nt++)
                *(float2*)(op + nt * 8 + tig * 2) =
                    make_float2(to_tf32(oacc[nt][0] * inv0), to_tf32(oacc[nt][1] * inv0));
        }
        if (r1v) {
            float* op = g_attno + ((size_t)(w * Nt + row1)) * DH + h * KD;
#pragma unroll
            for (int nt = 0; nt < 4; nt++)
                *(float2*)(op + nt * 8 + tig * 2) =
                    make_float2(to_tf32(oacc[nt][2] * inv1), to_tf32(oacc[nt][3] * inv1));
        }
    }
}

// ---------------- kernel 5: depthwise 3x3 conv + BN ----------------
__global__ void k_conv_bn(const float* __restrict__ cw,
                          const float* __restrict__ bnw,
                          const float* __restrict__ bnb,
                          const float* __restrict__ bnm,
                          const float* __restrict__ bnv) {
    int idx = blockIdx.x * blockDim.x + threadIdx.x;
    const int C4 = Cc / 4;
    const int total = B_ * Hh * Ww * C4;
    if (idx >= total) return;
    int c4 = idx % C4;
    int x  = (idx / C4) % Ww;
    int y  = (idx / (C4 * Ww)) % Hh;
    int b  = idx / (C4 * Ww * Hh);
    int c0 = c4 * 4;

    float4 acc = make_float4(0.f, 0.f, 0.f, 0.f);
#pragma unroll
    for (int ky = 0; ky < 3; ky++) {
        int yy = y + ky - 1;
        if (yy < 0 || yy >= Hh) continue;
#pragma unroll
        for (int kx = 0; kx < 3; kx++) {
            int xx = x + kx - 1;
            if (xx < 0 || xx >= Ww) continue;
            float4 in = *(const float4*)&g_x1[((size_t)b * L_ + (size_t)yy * Ww + xx) * Cc + c0];
            int wo = ky * 3 + kx;
            acc.x += in.x * cw[(c0 + 0) * 9 + wo];
            acc.y += in.y * cw[(c0 + 1) * 9 + wo];
            acc.z += in.z * cw[(c0 + 2) * 9 + wo];
            acc.w += in.w * cw[(c0 + 3) * 9 + wo];
        }
    }
    float4 outv;
    outv.x = (acc.x - bnm[c0 + 0]) * (rsqrtf(bnv[c0 + 0] + 1e-5f) * bnw[c0 + 0]) + bnb[c0 + 0];
    outv.y = (acc.y - bnm[c0 + 1]) * (rsqrtf(bnv[c0 + 1] + 1e-5f) * bnw[c0 + 1]) + bnb[c0 + 1];
    outv.z = (acc.z - bnm[c0 + 2]) * (rsqrtf(bnv[c0 + 2] + 1e-5f) * bnw[c0 + 2]) + bnb[c0 + 2];
    outv.w = (acc.w - bnm[c0 + 3]) * (rsqrtf(bnv[c0 + 3] + 1e-5f) * bnw[c0 + 3]) + bnb[c0 + 3];
    *(float4*)&g_x2[(size_t)idx * 4] = outv;
}

// ---------------- launcher ----------------
extern "C" void kernel_launch(void* const* d_in, const int* in_sizes, int n_in,
                              void* d_out, int out_size) {
    const float* x        = (const float*)d_in[0];
    const float* ln_aw    = (const float*)d_in[1];
    const float* ln_ab    = (const float*)d_in[2];
    const float* qkv_w    = (const float*)d_in[3];
    const float* qkv_b    = (const float*)d_in[4];
    const float* proj_w   = (const float*)d_in[5];
    const float* proj_b   = (const float*)d_in[6];
    const float* attn_bia = (const float*)d_in[7];
    const float* conv_w   = (const float*)d_in[8];
    const float* bn_w     = (const float*)d_in[9];
    const float* bn_b     = (const float*)d_in[10];
    const float* bn_m     = (const float*)d_in[11];
    const float* bn_v     = (const float*)d_in[12];
    const float* ln_mw    = (const float*)d_in[13];
    const float* ln_mb    = (const float*)d_in[14];
    const float* fc1_w    = (const float*)d_in[15];
    const float* fc1_b    = (const float*)d_in[16];
    const float* fc2_w    = (const float*)d_in[17];
    const float* fc2_b    = (const float*)d_in[18];
    const int*   bias_idx = (const int*)d_in[19];
    float* out = (float*)d_out;

    int n_off = in_sizes[7] / HEADS;

    // pre-round weights to tf32 (device-symbol destinations resolved in device code
    // is not needed here: cudaGetSymbolAddress-free — use kernels writing globals)
    {
        float* wq; cudaGetSymbolAddress((void**)&wq, g_wq);
        float* wp; cudaGetSymbolAddress((void**)&wp, g_wp);
        float* w1; cudaGetSymbolAddress((void**)&w1, g_w1);
        float* w2; cudaGetSymbolAddress((void**)&w2, g_w2);
        k_round4<<<(QKVW * Cc / 4 + 255) / 256, 256>>>((const float4*)qkv_w, (float4*)wq, QKVW * Cc / 4);
        k_round4<<<(Cc * DH / 4 + 255) / 256, 256>>>((const float4*)proj_w, (float4*)wp, Cc * DH / 4);
        k_round4<<<(HID * Cc / 4 + 255) / 256, 256>>>((const float4*)fc1_w, (float4*)w1, HID * Cc / 4);
        k_round4<<<(Cc * HID / 4 + 255) / 256, 256>>>((const float4*)fc2_w, (float4*)w2, Cc * HID / 4);
    }

    {
        int tot = HEADS * Nt * Nt;
        k_bias_expand<<<(tot + 255) / 256, 256>>>(attn_bia, bias_idx, n_off);
    }
    k_win_ln<<<M_ATT / 8, 256>>>(x, ln_aw, ln_ab);

    cudaFuncSetAttribute(k_gemm_qkv,  cudaFuncAttributeMaxDynamicSharedMemorySize, SMEM_GEMM);
    cudaFuncSetAttribute(k_gemm_proj, cudaFuncAttributeMaxDynamicSharedMemorySize, SMEM_GEMM);
    cudaFuncSetAttribute(k_gemm_fc1,  cudaFuncAttributeMaxDynamicSharedMemorySize, SMEM_GEMM);
    cudaFuncSetAttribute(k_gemm_fc2,  cudaFuncAttributeMaxDynamicSharedMemorySize, SMEM_GEMM);
    cudaFuncSetAttribute(k_attn,      cudaFuncAttributeMaxDynamicSharedMemorySize, SMEM_ATTN);

    k_gemm_qkv<<<dim3(QKVW / 128, (M_ATT + 127) / 128), 256, SMEM_GEMM>>>(qkv_b);
    k_attn<<<NW * HEADS, 256, SMEM_ATTN>>>();
    k_gemm_proj<<<dim3(Cc / 128, (M_ATT + 127) / 128), 256, SMEM_GEMM>>>(proj_b, x);
    {
        int tot = B_ * Hh * Ww * (Cc / 4);
        k_conv_bn<<<(tot + 255) / 256, 256>>>(conv_w, bn_w, bn_b, bn_m, bn_v);
    }
    k_ln_mlp<<<M_MLP / 8, 256>>>(ln_mw, ln_mb);
    k_gemm_fc1<<<dim3(HID / 128, M_MLP / 128), 256, SMEM_GEMM>>>(fc1_b);
    k_gemm_fc2<<<dim3(Cc / 128, M_MLP / 128), 256, SMEM_GEMM>>>(fc2_b, out);
}

// round 6
// speedup vs baseline: 2.6858x; 1.0168x over previous
#include <cuda_runtime.h>
#include <math.h>
#include <stdint.h>

// ---------------- problem constants ----------------
#define B_      8
#define Hh      64
#define Ww      64
#define Cc      384
#define HEADS   12
#define WSs     14
#define KD      32
#define Nt      196
#define NW      200
#define M_ATT   39200
#define L_      4096
#define M_MLP   32768
#define HID     1536
#define DH      384
#define QKVW    1152
#define SCALE_F 0.17677669529663687f
#define EPS_F   1e-5f

// attention tiling
#define NTP        208
#define QS_STRIDE  36
#define VT_STRIDE  212
#define SMEM_ATTN  ((2 * NTP * QS_STRIDE + KD * VT_STRIDE) * 4)

// gemm smem: 3 stages x (A[128][20] + B[128][20]) floats
#define GSTAGE      (128 * 20)
#define SMEM_GEMM   (3 * GSTAGE * 2 * 4)

// ---------------- scratch ----------------
__device__ float g_xn[M_ATT * Cc];
__device__ float g_qkv[(size_t)M_ATT * QKVW];
__device__ float g_attno[M_ATT * Cc];
__device__ float g_x1[M_MLP * Cc];
__device__ float g_x2[M_MLP * Cc];
__device__ float g_h1[(size_t)M_MLP * HID];
__device__ float g_bias[HEADS * Nt * Nt];
__device__ float g_wq[QKVW * Cc];
__device__ float g_wp[Cc * DH];
__device__ float g_w1[HID * Cc];
__device__ float g_w2[Cc * HID];

// ---------------- helpers ----------------
__device__ __forceinline__ float to_tf32(float x) {
    float r;
    asm("cvt.rna.tf32.f32 %0, %1;" : "=f"(r) : "f"(x));
    return r;
}

__device__ __forceinline__ void mma_tf32(float* c, const uint32_t* a, const uint32_t* b) {
    asm volatile(
        "mma.sync.aligned.m16n8k8.row.col.f32.tf32.tf32.f32 "
        "{%0,%1,%2,%3}, {%4,%5,%6,%7}, {%8,%9}, {%0,%1,%2,%3};\n"
        : "+f"(c[0]), "+f"(c[1]), "+f"(c[2]), "+f"(c[3])
        : "r"(a[0]), "r"(a[1]), "r"(a[2]), "r"(a[3]), "r"(b[0]), "r"(b[1]));
}

__device__ __forceinline__ void cp_async16(uint32_t saddr, const void* gptr, int srcbytes) {
    asm volatile("cp.async.cg.shared.global [%0], [%1], 16, %2;\n"
                 :: "r"(saddr), "l"(gptr), "r"(srcbytes));
}

// ---------------- weight rounding ----------------
__global__ void k_round4(const float4* __restrict__ src, float4* __restrict__ dst, int n4) {
    int i = blockIdx.x * blockDim.x + threadIdx.x;
    if (i >= n4) return;
    float4 v = src[i];
    dst[i] = make_float4(to_tf32(v.x), to_tf32(v.y), to_tf32(v.z), to_tf32(v.w));
}

// ---------------- kernel 1: expand bias table ----------------
__global__ void k_bias_expand(const float* __restrict__ ab,
                              const int* __restrict__ bidx, int n_off) {
    int i = blockIdx.x * blockDim.x + threadIdx.x;
    if (i >= HEADS * Nt * Nt) return;
    int h  = i / (Nt * Nt);
    int ij = i - h * (Nt * Nt);
    g_bias[i] = ab[h * n_off + bidx[ij]];
}

// ---------------- kernel 2: window partition + LayerNorm (tf32 out) --------
__global__ void k_win_ln(const float* __restrict__ x,
                         const float* __restrict__ w,
                         const float* __restrict__ b) {
    int warp = (blockIdx.x * blockDim.x + threadIdx.x) >> 5;
    int lane = threadIdx.x & 31;
    if (warp >= M_ATT) return;
    int wi = warp / Nt, t = warp - wi * Nt;
    int bb = wi / 25; int rem = wi - bb * 25;
    int wy = rem / 5, wx = rem - wy * 5;
    int ty = t / WSs, tx = t - ty * WSs;
    int gy = wy * WSs + ty, gx = wx * WSs + tx;
    bool valid = (gy < Hh) && (gx < Ww);
    const float* src = x + ((size_t)bb * L_ + (size_t)gy * Ww + gx) * Cc;

    float vals[12];
    float s = 0.f, s2 = 0.f;
#pragma unroll
    for (int i = 0; i < 12; i++) {
        float v = valid ? src[lane + i * 32] : 0.f;
        vals[i] = v; s += v; s2 += v * v;
    }
#pragma unroll
    for (int o = 16; o > 0; o >>= 1) {
        s  += __shfl_xor_sync(0xffffffffu, s,  o);
        s2 += __shfl_xor_sync(0xffffffffu, s2, o);
    }
    float mean = s * (1.f / Cc);
    float var  = s2 * (1.f / Cc) - mean * mean;
    float rstd = rsqrtf(var + EPS_F);
    float* dst = g_xn + (size_t)warp * Cc;
#pragma unroll
    for (int i = 0; i < 12; i++) {
        int c = lane + i * 32;
        dst[c] = to_tf32((vals[i] - mean) * rstd * w[c] + b[c]);
    }
}

// ---------------- kernel 7: MLP LayerNorm (tf32 out) ----------------
__global__ void k_ln_mlp(const float* __restrict__ w,
                         const float* __restrict__ b) {
    int warp = (blockIdx.x * blockDim.x + threadIdx.x) >> 5;
    int lane = threadIdx.x & 31;
    if (warp >= M_MLP) return;
    const float* src = g_x2 + (size_t)warp * Cc;
    float vals[12];
    float s = 0.f, s2 = 0.f;
#pragma unroll
    for (int i = 0; i < 12; i++) {
        float v = src[lane + i * 32];
        vals[i] = v; s += v; s2 += v * v;
    }
#pragma unroll
    for (int o = 16; o > 0; o >>= 1) {
        s  += __shfl_xor_sync(0xffffffffu, s,  o);
        s2 += __shfl_xor_sync(0xffffffffu, s2, o);
    }
    float mean = s * (1.f / Cc);
    float var  = s2 * (1.f / Cc) - mean * mean;
    float rstd = rsqrtf(var + EPS_F);
    float* dst = g_xn + (size_t)warp * Cc;
#pragma unroll
    for (int i = 0; i < 12; i++) {
        int c = lane + i * 32;
        dst[c] = to_tf32((vals[i] - mean) * rstd * w[c] + b[c]);
    }
}

// ---------------- tf32 GEMM: 512 threads, 16 warps (4x4), 32x32 warp tiles -
// A and Bw ALREADY tf32-rounded. C[M,N] = A[M,K] @ Bw[N,K]^T + bias.
// EPI: 0 bias, 1 GELU(tf32 out), 2 proj un-window+residual, 3 residual add
template <int EPI, int M, int Nn, int K>
__device__ __forceinline__ void gemm_tc_body(const float* __restrict__ A,
                                             const float* __restrict__ Bw,
                                             const float* __restrict__ bias,
                                             float* __restrict__ Cout,
                                             const float* __restrict__ res) {
    extern __shared__ float smbuf[];
    float* As = smbuf;                 // [3][128*20]
    float* Bs = smbuf + 3 * GSTAGE;    // [3][128*20]

    const int tid = threadIdx.x, lane = tid & 31, wid = tid >> 5;
    const int g = lane >> 2, tig = lane & 3;
    const int warp_m = wid >> 2, warp_n = wid & 3;    // 4 x 4 warps
    const int bm = blockIdx.y * 128, bn = blockIdx.x * 128;
    const int arow = tid >> 2, kcol = (tid & 3) * 4;  // 512 thr -> 128 rows x 4 chunks

    const int r0 = bm + arow;
    const bool v0 = ((M % 128) == 0) || (r0 < M);
    const int sz0 = v0 ? 16 : 0;
    const float* a0b = A  + (size_t)(v0 ? r0 : 0) * K + kcol;
    const float* b0b = Bw + (size_t)(bn + arow) * K + kcol;
    const uint32_t sa0 = (uint32_t)__cvta_generic_to_shared(As + arow * 20 + kcol);
    const uint32_t sb0 = (uint32_t)__cvta_generic_to_shared(Bs + arow * 20 + kcol);

    const int KT = K / 16;
    auto load_stage = [&](int s, int kt) {
        int k0 = kt * 16;
        uint32_t so = (uint32_t)(s * GSTAGE * 4);
        cp_async16(sa0 + so, a0b + k0, sz0);
        cp_async16(sb0 + so, b0b + k0, 16);
        asm volatile("cp.async.commit_group;\n");
    };

    float acc[2][4][4];
#pragma unroll
    for (int mt = 0; mt < 2; mt++)
#pragma unroll
        for (int nt = 0; nt < 4; nt++)
#pragma unroll
            for (int r = 0; r < 4; r++) acc[mt][nt][r] = 0.f;

    load_stage(0, 0);
    load_stage(1, 1);

    for (int kt = 0; kt < KT; kt++) {
        if (kt + 1 < KT) {
            asm volatile("cp.async.wait_group 1;\n");
        } else {
            asm volatile("cp.async.wait_group 0;\n");
        }
        __syncthreads();                     // single barrier per K-iter
        if (kt + 2 < KT) load_stage((kt + 2) % 3, kt + 2);

        const float* Ac = As + (kt % 3) * GSTAGE;
        const float* Bc = Bs + (kt % 3) * GSTAGE;
#pragma unroll
        for (int ks = 0; ks < 2; ks++) {
            const int kb = ks * 8;
            uint32_t afr[2][4], bfr[4][2];
#pragma unroll
            for (int mt = 0; mt < 2; mt++) {
                int r = warp_m * 32 + mt * 16;
                afr[mt][0] = __float_as_uint(Ac[(r + g    ) * 20 + kb + tig]);
                afr[mt][1] = __float_as_uint(Ac[(r + g + 8) * 20 + kb + tig]);
                afr[mt][2] = __float_as_uint(Ac[(r + g    ) * 20 + kb + tig + 4]);
                afr[mt][3] = __float_as_uint(Ac[(r + g + 8) * 20 + kb + tig + 4]);
            }
#pragma unroll
            for (int nt = 0; nt < 4; nt++) {
                int n = warp_n * 32 + nt * 8;
                bfr[nt][0] = __float_as_uint(Bc[(n + g) * 20 + kb + tig]);
                bfr[nt][1] = __float_as_uint(Bc[(n + g) * 20 + kb + tig + 4]);
            }
#pragma unroll
            for (int mt = 0; mt < 2; mt++)
#pragma unroll
                for (int nt = 0; nt < 4; nt++)
                    mma_tf32(acc[mt][nt], afr[mt], bfr[nt]);
        }
    }

#pragma unroll
    for (int mt = 0; mt < 2; mt++) {
#pragma unroll
        for (int nt = 0; nt < 4; nt++) {
#pragma unroll
            for (int r = 0; r < 4; r++) {
                int m  = bm + warp_m * 32 + mt * 16 + g + ((r >> 1) ? 8 : 0);
                int nn = bn + warp_n * 32 + nt * 8 + tig * 2 + (r & 1);
                if (((M % 128) != 0) && (m >= M)) continue;
                float v = acc[mt][nt][r] + bias[nn];
                if (EPI == 0) {
                    Cout[(size_t)m * Nn + nn] = v;
                } else if (EPI == 1) {
                    Cout[(size_t)m * Nn + nn] =
                        to_tf32(0.5f * v * (1.f + erff(v * 0.70710678118654752f)));
                } else if (EPI == 2) {
                    int wi = m / Nt, t = m - wi * Nt;
                    int bb2 = wi / 25; int rem = wi - bb2 * 25;
                    int wy = rem / 5, wx = rem - wy * 5;
                    int ty = t / WSs, tx = t - ty * WSs;
                    int gy = wy * WSs + ty, gx = wx * WSs + tx;
                    if (gy < Hh && gx < Ww) {
                        size_t o = ((size_t)bb2 * L_ + (size_t)gy * Ww + gx) * Cc + nn;
                        Cout[o] = res[o] + v;
                    }
                } else {
                    size_t o = (size_t)m * Nn + nn;
                    Cout[o] = v + res[o];
                }
            }
        }
    }
}

__global__ __launch_bounds__(512) void k_gemm_qkv(const float* __restrict__ b) {
    gemm_tc_body<0, M_ATT, QKVW, Cc>(g_xn, g_wq, b, g_qkv, nullptr);
}
__global__ __launch_bounds__(512) void k_gemm_proj(const float* __restrict__ b,
                                                   const float* __restrict__ x) {
    gemm_tc_body<2, M_ATT, Cc, DH>(g_attno, g_wp, b, g_x1, x);
}
__global__ __launch_bounds__(512) void k_gemm_fc1(const float* __restrict__ b) {
    gemm_tc_body<1, M_MLP, HID, Cc>(g_xn, g_w1, b, g_h1, nullptr);
}
__global__ __launch_bounds__(512) void k_gemm_fc2(const float* __restrict__ b,
                                                  float* __restrict__ out) {
    gemm_tc_body<3, M_MLP, Cc, HID>(g_h1, g_w2, b, out, g_x2);
}

// ---------------- kernel 4: tensor-core attention (unchanged) --------------
__global__ __launch_bounds__(256) void k_attn() {
    extern __shared__ float sm[];
    float* qs = sm;
    float* ks = sm + NTP * QS_STRIDE;
    float* vt = ks + NTP * QS_STRIDE;

    const int blk = blockIdx.x;
    const int w = blk / HEADS, h = blk - w * HEADS;
    const float* base = g_qkv + (size_t)w * Nt * QKVW + h * 96;
    const int tid = threadIdx.x, lane = tid & 31, wid = tid >> 5;
    const int g = lane >> 2, tig = lane & 3;

    for (int idx = tid; idx < NTP * 8; idx += 256) {
        int r = idx >> 3, d4 = (idx & 7) * 4;
        float4 q4, k4, v4;
        if (r < Nt) {
            const float* rp = base + (size_t)r * QKVW;
            q4 = *(const float4*)(rp + d4);
            k4 = *(const float4*)(rp + 32 + d4);
            v4 = *(const float4*)(rp + 64 + d4);
        } else {
            q4 = k4 = v4 = make_float4(0.f, 0.f, 0.f, 0.f);
        }
        float* qd = qs + r * QS_STRIDE + d4;
        qd[0] = to_tf32(q4.x * SCALE_F); qd[1] = to_tf32(q4.y * SCALE_F);
        qd[2] = to_tf32(q4.z * SCALE_F); qd[3] = to_tf32(q4.w * SCALE_F);
        float* kd = ks + r * QS_STRIDE + d4;
        kd[0] = to_tf32(k4.x); kd[1] = to_tf32(k4.y);
        kd[2] = to_tf32(k4.z); kd[3] = to_tf32(k4.w);
        vt[(d4 + 0) * VT_STRIDE + r] = to_tf32(v4.x);
        vt[(d4 + 1) * VT_STRIDE + r] = to_tf32(v4.y);
        vt[(d4 + 2) * VT_STRIDE + r] = to_tf32(v4.z);
        vt[(d4 + 3) * VT_STRIDE + r] = to_tf32(v4.w);
    }
    __syncthreads();

    const float* bias_h = g_bias + (size_t)h * Nt * Nt;

    for (int tt = wid; tt < 13; tt += 8) {
        const int row0 = tt * 16 + g, row1 = row0 + 8;

        uint32_t aq[4][4];
#pragma unroll
        for (int kk = 0; kk < 4; kk++) {
            aq[kk][0] = __float_as_uint(qs[(tt*16 + g    ) * QS_STRIDE + kk*8 + tig]);
            aq[kk][1] = __float_as_uint(qs[(tt*16 + g + 8) * QS_STRIDE + kk*8 + tig]);
            aq[kk][2] = __float_as_uint(qs[(tt*16 + g    ) * QS_STRIDE + kk*8 + tig + 4]);
            aq[kk][3] = __float_as_uint(qs[(tt*16 + g + 8) * QS_STRIDE + kk*8 + tig + 4]);
        }

        float acc[26][4];
#pragma unroll
        for (int nt = 0; nt < 26; nt++) {
            acc[nt][0] = acc[nt][1] = acc[nt][2] = acc[nt][3] = 0.f;
#pragma unroll
            for (int kk = 0; kk < 4; kk++) {
                uint32_t b[2];
                b[0] = __float_as_uint(ks[(nt*8 + g) * QS_STRIDE + kk*8 + tig]);
                b[1] = __float_as_uint(ks[(nt*8 + g) * QS_STRIDE + kk*8 + tig + 4]);
                mma_tf32(acc[nt], aq[kk], b);
            }
        }

        const bool r0v = row0 < Nt, r1v = row1 < Nt;
        float m0 = -1e30f, m1 = -1e30f;
#pragma unroll
        for (int nt = 0; nt < 26; nt++) {
            int col = nt * 8 + tig * 2;
            bool cv = col < Nt;
            float2 b0 = (cv && r0v) ? *(const float2*)(bias_h + (size_t)row0 * Nt + col)
                                    : make_float2(0.f, 0.f);
            float2 b1 = (cv && r1v) ? *(const float2*)(bias_h + (size_t)row1 * Nt + col)
                                    : make_float2(0.f, 0.f);
            acc[nt][0] = cv ? acc[nt][0] + b0.x : -1e30f;
            acc[nt][1] = cv ? acc[nt][1] + b0.y : -1e30f;
            acc[nt][2] = cv ? acc[nt][2] + b1.x : -1e30f;
            acc[nt][3] = cv ? acc[nt][3] + b1.y : -1e30f;
            m0 = fmaxf(m0, fmaxf(acc[nt][0], acc[nt][1]));
            m1 = fmaxf(m1, fmaxf(acc[nt][2], acc[nt][3]));
        }
        m0 = fmaxf(m0, __shfl_xor_sync(0xffffffffu, m0, 1));
        m0 = fmaxf(m0, __shfl_xor_sync(0xffffffffu, m0, 2));
        m1 = fmaxf(m1, __shfl_xor_sync(0xffffffffu, m1, 1));
        m1 = fmaxf(m1, __shfl_xor_sync(0xffffffffu, m1, 2));

        float l0 = 0.f, l1 = 0.f;
#pragma unroll
        for (int nt = 0; nt < 26; nt++) {
            acc[nt][0] = __expf(acc[nt][0] - m0); l0 += acc[nt][0];
            acc[nt][1] = __expf(acc[nt][1] - m0); l0 += acc[nt][1];
            acc[nt][2] = __expf(acc[nt][2] - m1); l1 += acc[nt][2];
            acc[nt][3] = __expf(acc[nt][3] - m1); l1 += acc[nt][3];
        }
        l0 += __shfl_xor_sync(0xffffffffu, l0, 1);
        l0 += __shfl_xor_sync(0xffffffffu, l0, 2);
        l1 += __shfl_xor_sync(0xffffffffu, l1, 1);
        l1 += __shfl_xor_sync(0xffffffffu, l1, 2);

        float oacc[4][4];
#pragma unroll
        for (int nt = 0; nt < 4; nt++)
            oacc[nt][0] = oacc[nt][1] = oacc[nt][2] = oacc[nt][3] = 0.f;

        const int srcA = (lane & ~3) | (tig >> 1);
        const int srcB = (lane & ~3) | (2 + (tig >> 1));
        const bool odd = (tig & 1) != 0;
#pragma unroll
        for (int kk = 0; kk < 26; kk++) {
            float v00 = __shfl_sync(0xffffffffu, acc[kk][0], srcA);
            float v01 = __shfl_sync(0xffffffffu, acc[kk][1], srcA);
            float v20 = __shfl_sync(0xffffffffu, acc[kk][2], srcA);
            float v21 = __shfl_sync(0xffffffffu, acc[kk][3], srcA);
            float w00 = __shfl_sync(0xffffffffu, acc[kk][0], srcB);
            float w01 = __shfl_sync(0xffffffffu, acc[kk][1], srcB);
            float w20 = __shfl_sync(0xffffffffu, acc[kk][2], srcB);
            float w21 = __shfl_sync(0xffffffffu, acc[kk][3], srcB);
            uint32_t pa[4];
            pa[0] = __float_as_uint(to_tf32(odd ? v01 : v00));
            pa[1] = __float_as_uint(to_tf32(odd ? v21 : v20));
            pa[2] = __float_as_uint(to_tf32(odd ? w01 : w00));
            pa[3] = __float_as_uint(to_tf32(odd ? w21 : w20));
#pragma unroll
            for (int nt = 0; nt < 4; nt++) {
                uint32_t b[2];
                b[0] = __float_as_uint(vt[(nt*8 + g) * VT_STRIDE + kk*8 + tig]);
                b[1] = __float_as_uint(vt[(nt*8 + g) * VT_STRIDE + kk*8 + tig + 4]);
                mma_tf32(oacc[nt], pa, b);
            }
        }

        const float inv0 = 1.f / l0, inv1 = 1.f / l1;
        if (r0v) {
            float* op = g_attno + ((size_t)(w * Nt + row0)) * DH + h * KD;
#pragma unroll
            for (int nt = 0; nt < 4; nt++)
                *(float2*)(op + nt * 8 + tig * 2) =
                    make_float2(to_tf32(oacc[nt][0] * inv0), to_tf32(oacc[nt][1] * inv0));
        }
        if (r1v) {
            float* op = g_attno + ((size_t)(w * Nt + row1)) * DH + h * KD;
#pragma unroll
            for (int nt = 0; nt < 4; nt++)
                *(float2*)(op + nt * 8 + tig * 2) =
                    make_float2(to_tf32(oacc[nt][2] * inv1), to_tf32(oacc[nt][3] * inv1));
        }
    }
}

// ---------------- kernel 5: depthwise 3x3 conv + BN ----------------
__global__ void k_conv_bn(const float* __restrict__ cw,
                          const float* __restrict__ bnw,
                          const float* __restrict__ bnb,
                          const float* __restrict__ bnm,
                          const float* __restrict__ bnv) {
    int idx = blockIdx.x * blockDim.x + threadIdx.x;
    const int C4 = Cc / 4;
    const int total = B_ * Hh * Ww * C4;
    if (idx >= total) return;
    int c4 = idx % C4;
    int x  = (idx / C4) % Ww;
    int y  = (idx / (C4 * Ww)) % Hh;
    int b  = idx / (C4 * Ww * Hh);
    int c0 = c4 * 4;

    float4 acc = make_float4(0.f, 0.f, 0.f, 0.f);
#pragma unroll
    for (int ky = 0; ky < 3; ky++) {
        int yy = y + ky - 1;
        if (yy < 0 || yy >= Hh) continue;
#pragma unroll
        for (int kx = 0; kx < 3; kx++) {
            int xx = x + kx - 1;
            if (xx < 0 || xx >= Ww) continue;
            float4 in = *(const float4*)&g_x1[((size_t)b * L_ + (size_t)yy * Ww + xx) * Cc + c0];
            int wo = ky * 3 + kx;
            acc.x += in.x * cw[(c0 + 0) * 9 + wo];
            acc.y += in.y * cw[(c0 + 1) * 9 + wo];
            acc.z += in.z * cw[(c0 + 2) * 9 + wo];
            acc.w += in.w * cw[(c0 + 3) * 9 + wo];
        }
    }
    float4 outv;
    outv.x = (acc.x - bnm[c0 + 0]) * (rsqrtf(bnv[c0 + 0] + 1e-5f) * bnw[c0 + 0]) + bnb[c0 + 0];
    outv.y = (acc.y - bnm[c0 + 1]) * (rsqrtf(bnv[c0 + 1] + 1e-5f) * bnw[c0 + 1]) + bnb[c0 + 1];
    outv.z = (acc.z - bnm[c0 + 2]) * (rsqrtf(bnv[c0 + 2] + 1e-5f) * bnw[c0 + 2]) + bnb[c0 + 2];
    outv.w = (acc.w - bnm[c0 + 3]) * (rsqrtf(bnv[c0 + 3] + 1e-5f) * bnw[c0 + 3]) + bnb[c0 + 3];
    *(float4*)&g_x2[(size_t)idx * 4] = outv;
}

// ---------------- launcher ----------------
extern "C" void kernel_launch(void* const* d_in, const int* in_sizes, int n_in,
                              void* d_out, int out_size) {
    const float* x        = (const float*)d_in[0];
    const float* ln_aw    = (const float*)d_in[1];
    const float* ln_ab    = (const float*)d_in[2];
    const float* qkv_w    = (const float*)d_in[3];
    const float* qkv_b    = (const float*)d_in[4];
    const float* proj_w   = (const float*)d_in[5];
    const float* proj_b   = (const float*)d_in[6];
    const float* attn_bia = (const float*)d_in[7];
    const float* conv_w   = (const float*)d_in[8];
    const float* bn_w     = (const float*)d_in[9];
    const float* bn_b     = (const float*)d_in[10];
    const float* bn_m     = (const float*)d_in[11];
    const float* bn_v     = (const float*)d_in[12];
    const float* ln_mw    = (const float*)d_in[13];
    const float* ln_mb    = (const float*)d_in[14];
    const float* fc1_w    = (const float*)d_in[15];
    const float* fc1_b    = (const float*)d_in[16];
    const float* fc2_w    = (const float*)d_in[17];
    const float* fc2_b    = (const float*)d_in[18];
    const int*   bias_idx = (const int*)d_in[19];
    float* out = (float*)d_out;

    int n_off = in_sizes[7] / HEADS;

    {
        float* wq; cudaGetSymbolAddress((void**)&wq, g_wq);
        float* wp; cudaGetSymbolAddress((void**)&wp, g_wp);
        float* w1; cudaGetSymbolAddress((void**)&w1, g_w1);
        float* w2; cudaGetSymbolAddress((void**)&w2, g_w2);
        k_round4<<<(QKVW * Cc / 4 + 255) / 256, 256>>>((const float4*)qkv_w, (float4*)wq, QKVW * Cc / 4);
        k_round4<<<(Cc * DH / 4 + 255) / 256, 256>>>((const float4*)proj_w, (float4*)wp, Cc * DH / 4);
        k_round4<<<(HID * Cc / 4 + 255) / 256, 256>>>((const float4*)fc1_w, (float4*)w1, HID * Cc / 4);
        k_round4<<<(Cc * HID / 4 + 255) / 256, 256>>>((const float4*)fc2_w, (float4*)w2, Cc * HID / 4);
    }

    {
        int tot = HEADS * Nt * Nt;
        k_bias_expand<<<(tot + 255) / 256, 256>>>(attn_bia, bias_idx, n_off);
    }
    k_win_ln<<<M_ATT / 8, 256>>>(x, ln_aw, ln_ab);

    cudaFuncSetAttribute(k_gemm_qkv,  cudaFuncAttributeMaxDynamicSharedMemorySize, SMEM_GEMM);
    cudaFuncSetAttribute(k_gemm_proj, cudaFuncAttributeMaxDynamicSharedMemorySize, SMEM_GEMM);
    cudaFuncSetAttribute(k_gemm_fc1,  cudaFuncAttributeMaxDynamicSharedMemorySize, SMEM_GEMM);
    cudaFuncSetAttribute(k_gemm_fc2,  cudaFuncAttributeMaxDynamicSharedMemorySize, SMEM_GEMM);
    cudaFuncSetAttribute(k_attn,      cudaFuncAttributeMaxDynamicSharedMemorySize, SMEM_ATTN);

    k_gemm_qkv<<<dim3(QKVW / 128, (M_ATT + 127) / 128), 512, SMEM_GEMM>>>(qkv_b);
    k_attn<<<NW * HEADS, 256, SMEM_ATTN>>>();
    k_gemm_proj<<<dim3(Cc / 128, (M_ATT + 127) / 128), 512, SMEM_GEMM>>>(proj_b, x);
    {
        int tot = B_ * Hh * Ww * (Cc / 4);
        k_conv_bn<<<(tot + 255) / 256, 256>>>(conv_w, bn_w, bn_b, bn_m, bn_v);
    }
    k_ln_mlp<<<M_MLP / 8, 256>>>(ln_mw, ln_mb);
    k_gemm_fc1<<<dim3(HID / 128, M_MLP / 128), 512, SMEM_GEMM>>>(fc1_b);
    k_gemm_fc2<<<dim3(Cc / 128, M_MLP / 128), 512, SMEM_GEMM>>>(fc2_b, out);
}

// round 8
// speedup vs baseline: 3.7225x; 1.3860x over previous
#include <cuda_runtime.h>
#include <cuda_fp16.h>
#include <math.h>
#include <stdint.h>

// ---------------- problem constants ----------------
#define B_      8
#define Hh      64
#define Ww      64
#define Cc      384
#define HEADS   12
#define WSs     14
#define KD      32
#define Nt      196
#define NW      200
#define M_ATT   39200
#define L_      4096
#define M_MLP   32768
#define HID     1536
#define DH      384
#define QKVW    1152
#define SCALE_F 0.17677669529663687f
#define EPS_F   1e-5f

// attention tiling (unchanged, tf32 mma path)
#define NTP        208
#define QS_STRIDE  36
#define VT_STRIDE  212
#define SMEM_ATTN  ((2 * NTP * QS_STRIDE + KD * VT_STRIDE) * 4)

// fp16 gemm smem: 3 stages x (A[128][40] + B[128][40]) halfs
// one matrix = 128*40*2 = 10240 B; stage = 20480 B; 3 stages = 61440 B
#define GST_BYTES   20480
#define SMEM_GEMM   (3 * GST_BYTES)

// ---------------- scratch ----------------
__device__ __align__(16) __half g_xn[M_ATT * Cc];          // LN outputs (fp16)
__device__ float  g_qkv[(size_t)M_ATT * QKVW];             // qkv (fp32)
__device__ __align__(16) __half g_attno[M_ATT * Cc];       // attn out (fp16)
__device__ float  g_x1[M_MLP * Cc];
__device__ float  g_x2[M_MLP * Cc];
__device__ __align__(16) __half g_h1[(size_t)M_MLP * HID]; // fc1/GELU out (fp16)
__device__ float  g_bias[HEADS * Nt * Nt];
__device__ __align__(16) __half g_wq[QKVW * Cc];
__device__ __align__(16) __half g_wp[Cc * DH];
__device__ __align__(16) __half g_w1[HID * Cc];
__device__ __align__(16) __half g_w2[Cc * HID];

// ---------------- helpers ----------------
__device__ __forceinline__ float to_tf32(float x) {
    float r;
    asm("cvt.rna.tf32.f32 %0, %1;" : "=f"(r) : "f"(x));
    return r;
}

__device__ __forceinline__ void mma_tf32(float* c, const uint32_t* a, const uint32_t* b) {
    asm volatile(
        "mma.sync.aligned.m16n8k8.row.col.f32.tf32.tf32.f32 "
        "{%0,%1,%2,%3}, {%4,%5,%6,%7}, {%8,%9}, {%0,%1,%2,%3};\n"
        : "+f"(c[0]), "+f"(c[1]), "+f"(c[2]), "+f"(c[3])
        : "r"(a[0]), "r"(a[1]), "r"(a[2]), "r"(a[3]), "r"(b[0]), "r"(b[1]));
}

__device__ __forceinline__ void mma_f16(float* c, const uint32_t* a, const uint32_t* b) {
    asm volatile(
        "mma.sync.aligned.m16n8k16.row.col.f32.f16.f16.f32 "
        "{%0,%1,%2,%3}, {%4,%5,%6,%7}, {%8,%9}, {%0,%1,%2,%3};\n"
        : "+f"(c[0]), "+f"(c[1]), "+f"(c[2]), "+f"(c[3])
        : "r"(a[0]), "r"(a[1]), "r"(a[2]), "r"(a[3]), "r"(b[0]), "r"(b[1]));
}

__device__ __forceinline__ void cp_async16(uint32_t saddr, const void* gptr, int srcbytes) {
    asm volatile("cp.async.cg.shared.global [%0], [%1], 16, %2;\n"
                 :: "r"(saddr), "l"(gptr), "r"(srcbytes));
}

__device__ __forceinline__ uint32_t smem_u32(const void* p) {
    uint32_t a;
    asm("{ .reg .u64 t; cvta.to.shared.u64 t, %1; cvt.u32.u64 %0, t; }" : "=r"(a) : "l"(p));
    return a;
}

// ---------------- weight conversion fp32 -> fp16 (single launch) ----------
__global__ void k_half_all(const float4* __restrict__ s0, int n0,
                           const float4* __restrict__ s1, int n1,
                           const float4* __restrict__ s2, int n2,
                           const float4* __restrict__ s3, int n3) {
    int i = blockIdx.x * blockDim.x + threadIdx.x;
    const float4* src; __half* dst; int j = i;
    if (j < n0) { src = s0; dst = g_wq; }
    else if ((j -= n0) < n1) { src = s1; dst = g_wp; }
    else if ((j -= n1) < n2) { src = s2; dst = g_w1; }
    else if ((j -= n2) < n3) { src = s3; dst = g_w2; }
    else return;
    float4 v = src[j];
    __half2* d2 = (__half2*)(dst + 4 * (size_t)j);
    d2[0] = __floats2half2_rn(v.x, v.y);
    d2[1] = __floats2half2_rn(v.z, v.w);
}

// ---------------- kernel: expand bias table ----------------
__global__ void k_bias_expand(const float* __restrict__ ab,
                              const int* __restrict__ bidx, int n_off) {
    int i = blockIdx.x * blockDim.x + threadIdx.x;
    if (i >= HEADS * Nt * Nt) return;
    int h  = i / (Nt * Nt);
    int ij = i - h * (Nt * Nt);
    g_bias[i] = ab[h * n_off + bidx[ij]];
}

// ---------------- kernel: window partition + LayerNorm (fp16 out) ---------
__global__ void k_win_ln(const float* __restrict__ x,
                         const float* __restrict__ w,
                         const float* __restrict__ b) {
    int warp = (blockIdx.x * blockDim.x + threadIdx.x) >> 5;
    int lane = threadIdx.x & 31;
    if (warp >= M_ATT) return;
    int wi = warp / Nt, t = warp - wi * Nt;
    int bb = wi / 25; int rem = wi - bb * 25;
    int wy = rem / 5, wx = rem - wy * 5;
    int ty = t / WSs, tx = t - ty * WSs;
    int gy = wy * WSs + ty, gx = wx * WSs + tx;
    bool valid = (gy < Hh) && (gx < Ww);
    const float* src = x + ((size_t)bb * L_ + (size_t)gy * Ww + gx) * Cc;

    float vals[12];
    float s = 0.f, s2 = 0.f;
#pragma unroll
    for (int i = 0; i < 12; i++) {
        float v = valid ? src[lane + i * 32] : 0.f;
        vals[i] = v; s += v; s2 += v * v;
    }
#pragma unroll
    for (int o = 16; o > 0; o >>= 1) {
        s  += __shfl_xor_sync(0xffffffffu, s,  o);
        s2 += __shfl_xor_sync(0xffffffffu, s2, o);
    }
    float mean = s * (1.f / Cc);
    float var  = s2 * (1.f / Cc) - mean * mean;
    float rstd = rsqrtf(var + EPS_F);
    __half* dst = g_xn + (size_t)warp * Cc;
#pragma unroll
    for (int i = 0; i < 12; i++) {
        int c = lane + i * 32;
        dst[c] = __float2half((vals[i] - mean) * rstd * w[c] + b[c]);
    }
}

// ---------------- kernel: MLP LayerNorm (fp16 out) ----------------
__global__ void k_ln_mlp(const float* __restrict__ w,
                         const float* __restrict__ b) {
    int warp = (blockIdx.x * blockDim.x + threadIdx.x) >> 5;
    int lane = threadIdx.x & 31;
    if (warp >= M_MLP) return;
    const float* src = g_x2 + (size_t)warp * Cc;
    float vals[12];
    float s = 0.f, s2 = 0.f;
#pragma unroll
    for (int i = 0; i < 12; i++) {
        float v = src[lane + i * 32];
        vals[i] = v; s += v; s2 += v * v;
    }
#pragma unroll
    for (int o = 16; o > 0; o >>= 1) {
        s  += __shfl_xor_sync(0xffffffffu, s,  o);
        s2 += __shfl_xor_sync(0xffffffffu, s2, o);
    }
    float mean = s * (1.f / Cc);
    float var  = s2 * (1.f / Cc) - mean * mean;
    float rstd = rsqrtf(var + EPS_F);
    __half* dst = g_xn + (size_t)warp * Cc;
#pragma unroll
    for (int i = 0; i < 12; i++) {
        int c = lane + i * 32;
        dst[c] = __float2half((vals[i] - mean) * rstd * w[c] + b[c]);
    }
}

// ---------------- fp16 GEMM: 512 threads, 16 warps (4x4), 32x32 warp tiles
// C[M,N] = A[M,K] @ Bw[N,K]^T + bias; A,Bw fp16; acc fp32; BK=32.
// EPI: 0 bias (f32 out), 1 GELU (fp16 out), 2 proj un-window+residual, 3 residual
template <int EPI, int M, int Nn, int K>
__device__ __forceinline__ void gemm_f16_body(const __half* __restrict__ A,
                                              const __half* __restrict__ Bw,
                                              const float* __restrict__ bias,
                                              float* __restrict__ Cout,
                                              const float* __restrict__ res) {
    extern __shared__ __align__(16) char smraw[];
    const int tid = threadIdx.x, lane = tid & 31, wid = tid >> 5;
    const int g = lane >> 2, tig = lane & 3;
    const int warp_m = wid >> 2, warp_n = wid & 3;    // 4 x 4 warps
    const int bm = blockIdx.y * 128, bn = blockIdx.x * 128;
    const int arow = tid >> 2, seg = tid & 3;         // 128 rows x 4 x 16B chunks

    const int r0 = bm + arow;
    const bool v0 = ((M % 128) == 0) || (r0 < M);
    const int sz0 = v0 ? 16 : 0;
    const __half* a0b = A  + (size_t)(v0 ? r0 : 0) * K + seg * 8;
    const __half* b0b = Bw + (size_t)(bn + arow) * K + seg * 8;
    const uint32_t sa0 = smem_u32(smraw) + arow * 80 + seg * 16;
    const uint32_t sb0 = sa0 + 10240;

    const int KT = K / 32;
    auto load_stage = [&](int s, int kt) {
        int kc = kt * 32;
        uint32_t so = (uint32_t)(s * GST_BYTES);
        cp_async16(sa0 + so, a0b + kc, sz0);
        cp_async16(sb0 + so, b0b + kc, 16);
        asm volatile("cp.async.commit_group;\n");
    };

    float acc[2][4][4];
#pragma unroll
    for (int mt = 0; mt < 2; mt++)
#pragma unroll
        for (int nt = 0; nt < 4; nt++)
#pragma unroll
            for (int r = 0; r < 4; r++) acc[mt][nt][r] = 0.f;

    load_stage(0, 0);
    load_stage(1, 1);

    for (int kt = 0; kt < KT; kt++) {
        if (kt + 1 < KT) {
            asm volatile("cp.async.wait_group 1;\n");
        } else {
            asm volatile("cp.async.wait_group 0;\n");
        }
        __syncthreads();
        if (kt + 2 < KT) load_stage((kt + 2) % 3, kt + 2);

        const __half* Ac = (const __half*)(smraw + (kt % 3) * GST_BYTES);
        const __half* Bc = Ac + 5120;
#pragma unroll
        for (int ks = 0; ks < 2; ks++) {
            const int kb = ks * 16;
            uint32_t afr[2][4], bfr[4][2];
#pragma unroll
            for (int mt = 0; mt < 2; mt++) {
                int r = warp_m * 32 + mt * 16;
                afr[mt][0] = *(const uint32_t*)(Ac + (r + g    ) * 40 + kb + 2 * tig);
                afr[mt][1] = *(const uint32_t*)(Ac + (r + g + 8) * 40 + kb + 2 * tig);
                afr[mt][2] = *(const uint32_t*)(Ac + (r + g    ) * 40 + kb + 2 * tig + 8);
                afr[mt][3] = *(const uint32_t*)(Ac + (r + g + 8) * 40 + kb + 2 * tig + 8);
            }
#pragma unroll
            for (int nt = 0; nt < 4; nt++) {
                int n = warp_n * 32 + nt * 8;
                bfr[nt][0] = *(const uint32_t*)(Bc + (n + g) * 40 + kb + 2 * tig);
                bfr[nt][1] = *(const uint32_t*)(Bc + (n + g) * 40 + kb + 2 * tig + 8);
            }
#pragma unroll
            for (int mt = 0; mt < 2; mt++)
#pragma unroll
                for (int nt = 0; nt < 4; nt++)
                    mma_f16(acc[mt][nt], afr[mt], bfr[nt]);
        }
    }

#pragma unroll
    for (int mt = 0; mt < 2; mt++) {
#pragma unroll
        for (int nt = 0; nt < 4; nt++) {
#pragma unroll
            for (int r = 0; r < 4; r++) {
                int m  = bm + warp_m * 32 + mt * 16 + g + ((r >> 1) ? 8 : 0);
                int nn = bn + warp_n * 32 + nt * 8 + tig * 2 + (r & 1);
                if (((M % 128) != 0) && (m >= M)) continue;
                float v = acc[mt][nt][r] + bias[nn];
                if (EPI == 0) {
                    Cout[(size_t)m * Nn + nn] = v;
                } else if (EPI == 1) {
                    ((__half*)Cout)[(size_t)m * Nn + nn] =
                        __float2half(0.5f * v * (1.f + erff(v * 0.70710678118654752f)));
                } else if (EPI == 2) {
                    int wi = m / Nt, t = m - wi * Nt;
                    int bb2 = wi / 25; int rem = wi - bb2 * 25;
                    int wy = rem / 5, wx = rem - wy * 5;
                    int ty = t / WSs, tx = t - ty * WSs;
                    int gy = wy * WSs + ty, gx = wx * WSs + tx;
                    if (gy < Hh && gx < Ww) {
                        size_t o = ((size_t)bb2 * L_ + (size_t)gy * Ww + gx) * Cc + nn;
                        Cout[o] = res[o] + v;
                    }
                } else {
                    size_t o = (size_t)m * Nn + nn;
                    Cout[o] = v + res[o];
                }
            }
        }
    }
}

__global__ __launch_bounds__(512) void k_gemm_qkv(const float* __restrict__ b) {
    gemm_f16_body<0, M_ATT, QKVW, Cc>(g_xn, g_wq, b, g_qkv, nullptr);
}
__global__ __launch_bounds__(512) void k_gemm_proj(const float* __restrict__ b,
                                                   const float* __restrict__ x) {
    gemm_f16_body<2, M_ATT, Cc, DH>(g_attno, g_wp, b, g_x1, x);
}
__global__ __launch_bounds__(512) void k_gemm_fc1(const float* __restrict__ b) {
    gemm_f16_body<1, M_MLP, HID, Cc>(g_xn, g_w1, b, (float*)g_h1, nullptr);
}
__global__ __launch_bounds__(512) void k_gemm_fc2(const float* __restrict__ b,
                                                  float* __restrict__ out) {
    gemm_f16_body<3, M_MLP, Cc, HID>(g_h1, g_w2, b, out, g_x2);
}

// ---------------- tensor-core attention (tf32, fp16 output) ----------------
__global__ __launch_bounds__(256) void k_attn() {
    extern __shared__ float sm[];
    float* qs = sm;
    float* ks = sm + NTP * QS_STRIDE;
    float* vt = ks + NTP * QS_STRIDE;

    const int blk = blockIdx.x;
    const int w = blk / HEADS, h = blk - w * HEADS;
    const float* base = g_qkv + (size_t)w * Nt * QKVW + h * 96;
    const int tid = threadIdx.x, lane = tid & 31, wid = tid >> 5;
    const int g = lane >> 2, tig = lane & 3;

    for (int idx = tid; idx < NTP * 8; idx += 256) {
        int r = idx >> 3, d4 = (idx & 7) * 4;
        float4 q4, k4, v4;
        if (r < Nt) {
            const float* rp = base + (size_t)r * QKVW;
            q4 = *(const float4*)(rp + d4);
            k4 = *(const float4*)(rp + 32 + d4);
            v4 = *(const float4*)(rp + 64 + d4);
        } else {
            q4 = k4 = v4 = make_float4(0.f, 0.f, 0.f, 0.f);
        }
        float* qd = qs + r * QS_STRIDE + d4;
        qd[0] = to_tf32(q4.x * SCALE_F); qd[1] = to_tf32(q4.y * SCALE_F);
        qd[2] = to_tf32(q4.z * SCALE_F); qd[3] = to_tf32(q4.w * SCALE_F);
        float* kd = ks + r * QS_STRIDE + d4;
        kd[0] = to_tf32(k4.x); kd[1] = to_tf32(k4.y);
        kd[2] = to_tf32(k4.z); kd[3] = to_tf32(k4.w);
        vt[(d4 + 0) * VT_STRIDE + r] = to_tf32(v4.x);
        vt[(d4 + 1) * VT_STRIDE + r] = to_tf32(v4.y);
        vt[(d4 + 2) * VT_STRIDE + r] = to_tf32(v4.z);
        vt[(d4 + 3) * VT_STRIDE + r] = to_tf32(v4.w);
    }
    __syncthreads();

    const float* bias_h = g_bias + (size_t)h * Nt * Nt;

    for (int tt = wid; tt < 13; tt += 8) {
        const int row0 = tt * 16 + g, row1 = row0 + 8;

        uint32_t aq[4][4];
#pragma unroll
        for (int kk = 0; kk < 4; kk++) {
            aq[kk][0] = __float_as_uint(qs[(tt*16 + g    ) * QS_STRIDE + kk*8 + tig]);
            aq[kk][1] = __float_as_uint(qs[(tt*16 + g + 8) * QS_STRIDE + kk*8 + tig]);
            aq[kk][2] = __float_as_uint(qs[(tt*16 + g    ) * QS_STRIDE + kk*8 + tig + 4]);
            aq[kk][3] = __float_as_uint(qs[(tt*16 + g + 8) * QS_STRIDE + kk*8 + tig + 4]);
        }

        float acc[26][4];
#pragma unroll
        for (int nt = 0; nt < 26; nt++) {
            acc[nt][0] = acc[nt][1] = acc[nt][2] = acc[nt][3] = 0.f;
#pragma unroll
            for (int kk = 0; kk < 4; kk++) {
                uint32_t b[2];
                b[0] = __float_as_uint(ks[(nt*8 + g) * QS_STRIDE + kk*8 + tig]);
                b[1] = __float_as_uint(ks[(nt*8 + g) * QS_STRIDE + kk*8 + tig + 4]);
                mma_tf32(acc[nt], aq[kk], b);
            }
        }

        const bool r0v = row0 < Nt, r1v = row1 < Nt;
        float m0 = -1e30f, m1 = -1e30f;
#pragma unroll
        for (int nt = 0; nt < 26; nt++) {
            int col = nt * 8 + tig * 2;
            bool cv = col < Nt;
            float2 b0 = (cv && r0v) ? *(const float2*)(bias_h + (size_t)row0 * Nt + col)
                                    : make_float2(0.f, 0.f);
            float2 b1 = (cv && r1v) ? *(const float2*)(bias_h + (size_t)row1 * Nt + col)
                                    : make_float2(0.f, 0.f);
            acc[nt][0] = cv ? acc[nt][0] + b0.x : -1e30f;
            acc[nt][1] = cv ? acc[nt][1] + b0.y : -1e30f;
            acc[nt][2] = cv ? acc[nt][2] + b1.x : -1e30f;
            acc[nt][3] = cv ? acc[nt][3] + b1.y : -1e30f;
            m0 = fmaxf(m0, fmaxf(acc[nt][0], acc[nt][1]));
            m1 = fmaxf(m1, fmaxf(acc[nt][2], acc[nt][3]));
        }
        m0 = fmaxf(m0, __shfl_xor_sync(0xffffffffu, m0, 1));
        m0 = fmaxf(m0, __shfl_xor_sync(0xffffffffu, m0, 2));
        m1 = fmaxf(m1, __shfl_xor_sync(0xffffffffu, m1, 1));
        m1 = fmaxf(m1, __shfl_xor_sync(0xffffffffu, m1, 2));

        float l0 = 0.f, l1 = 0.f;
#pragma unroll
        for (int nt = 0; nt < 26; nt++) {
            acc[nt][0] = __expf(acc[nt][0] - m0); l0 += acc[nt][0];
            acc[nt][1] = __expf(acc[nt][1] - m0); l0 += acc[nt][1];
            acc[nt][2] = __expf(acc[nt][2] - m1); l1 += acc[nt][2];
            acc[nt][3] = __expf(acc[nt][3] - m1); l1 += acc[nt][3];
        }
        l0 += __shfl_xor_sync(0xffffffffu, l0, 1);
        l0 += __shfl_xor_sync(0xffffffffu, l0, 2);
        l1 += __shfl_xor_sync(0xffffffffu, l1, 1);
        l1 += __shfl_xor_sync(0xffffffffu, l1, 2);

        float oacc[4][4];
#pragma unroll
        for (int nt = 0; nt < 4; nt++)
            oacc[nt][0] = oacc[nt][1] = oacc[nt][2] = oacc[nt][3] = 0.f;

        const int srcA = (lane & ~3) | (tig >> 1);
        const int srcB = (lane & ~3) | (2 + (tig >> 1));
        const bool odd = (tig & 1) != 0;
#pragma unroll
        for (int kk = 0; kk < 26; kk++) {
            float v00 = __shfl_sync(0xffffffffu, acc[kk][0], srcA);
            float v01 = __shfl_sync(0xffffffffu, acc[kk][1], srcA);
            float v20 = __shfl_sync(0xffffffffu, acc[kk][2], srcA);
            float v21 = __shfl_sync(0xffffffffu, acc[kk][3], srcA);
            float w00 = __shfl_sync(0xffffffffu, acc[kk][0], srcB);
            float w01 = __shfl_sync(0xffffffffu, acc[kk][1], srcB);
            float w20 = __shfl_sync(0xffffffffu, acc[kk][2], srcB);
            float w21 = __shfl_sync(0xffffffffu, acc[kk][3], srcB);
            uint32_t pa[4];
            pa[0] = __float_as_uint(to_tf32(odd ? v01 : v00));
            pa[1] = __float_as_uint(to_tf32(odd ? v21 : v20));
            pa[2] = __float_as_uint(to_tf32(odd ? w01 : w00));
            pa[3] = __float_as_uint(to_tf32(odd ? w21 : w20));
#pragma unroll
            for (int nt = 0; nt < 4; nt++) {
                uint32_t b[2];
                b[0] = __float_as_uint(vt[(nt*8 + g) * VT_STRIDE + kk*8 + tig]);
                b[1] = __float_as_uint(vt[(nt*8 + g) * VT_STRIDE + kk*8 + tig + 4]);
                mma_tf32(oacc[nt], pa, b);
            }
        }

        const float inv0 = 1.f / l0, inv1 = 1.f / l1;
        if (r0v) {
            __half* op = g_attno + ((size_t)(w * Nt + row0)) * DH + h * KD;
#pragma unroll
            for (int nt = 0; nt < 4; nt++)
                *(__half2*)(op + nt * 8 + tig * 2) =
                    __floats2half2_rn(oacc[nt][0] * inv0, oacc[nt][1] * inv0);
        }
        if (r1v) {
            __half* op = g_attno + ((size_t)(w * Nt + row1)) * DH + h * KD;
#pragma unroll
            for (int nt = 0; nt < 4; nt++)
                *(__half2*)(op + nt * 8 + tig * 2) =
                    __floats2half2_rn(oacc[nt][2] * inv1, oacc[nt][3] * inv1);
        }
    }
}

// ---------------- depthwise 3x3 conv + BN ----------------
__global__ void k_conv_bn(const float* __restrict__ cw,
                          const float* __restrict__ bnw,
                          const float* __restrict__ bnb,
                          const float* __restrict__ bnm,
                          const float* __restrict__ bnv) {
    int idx = blockIdx.x * blockDim.x + threadIdx.x;
    const int C4 = Cc / 4;
    const int total = B_ * Hh * Ww * C4;
    if (idx >= total) return;
    int c4 = idx % C4;
    int x  = (idx / C4) % Ww;
    int y  = (idx / (C4 * Ww)) % Hh;
    int b  = idx / (C4 * Ww * Hh);
    int c0 = c4 * 4;

    float4 acc = make_float4(0.f, 0.f, 0.f, 0.f);
#pragma unroll
    for (int ky = 0; ky < 3; ky++) {
        int yy = y + ky - 1;
        if (yy < 0 || yy >= Hh) continue;
#pragma unroll
        for (int kx = 0; kx < 3; kx++) {
            int xx = x + kx - 1;
            if (xx < 0 || xx >= Ww) continue;
            float4 in = *(const float4*)&g_x1[((size_t)b * L_ + (size_t)yy * Ww + xx) * Cc + c0];
            int wo = ky * 3 + kx;
            acc.x += in.x * cw[(c0 + 0) * 9 + wo];
            acc.y += in.y * cw[(c0 + 1) * 9 + wo];
            acc.z += in.z * cw[(c0 + 2) * 9 + wo];
            acc.w += in.w * cw[(c0 + 3) * 9 + wo];
        }
    }
    float4 outv;
    outv.x = (acc.x - bnm[c0 + 0]) * (rsqrtf(bnv[c0 + 0] + 1e-5f) * bnw[c0 + 0]) + bnb[c0 + 0];
    outv.y = (acc.y - bnm[c0 + 1]) * (rsqrtf(bnv[c0 + 1] + 1e-5f) * bnw[c0 + 1]) + bnb[c0 + 1];
    outv.z = (acc.z - bnm[c0 + 2]) * (rsqrtf(bnv[c0 + 2] + 1e-5f) * bnw[c0 + 2]) + bnb[c0 + 2];
    outv.w = (acc.w - bnm[c0 + 3]) * (rsqrtf(bnv[c0 + 3] + 1e-5f) * bnw[c0 + 3]) + bnb[c0 + 3];
    *(float4*)&g_x2[(size_t)idx * 4] = outv;
}

// ---------------- launcher ----------------
extern "C" void kernel_launch(void* const* d_in, const int* in_sizes, int n_in,
                              void* d_out, int out_size) {
    const float* x        = (const float*)d_in[0];
    const float* ln_aw    = (const float*)d_in[1];
    const float* ln_ab    = (const float*)d_in[2];
    const float* qkv_w    = (const float*)d_in[3];
    const float* qkv_b    = (const float*)d_in[4];
    const float* proj_w   = (const float*)d_in[5];
    const float* proj_b   = (const float*)d_in[6];
    const float* attn_bia = (const float*)d_in[7];
    const float* conv_w   = (const float*)d_in[8];
    const float* bn_w     = (const float*)d_in[9];
    const float* bn_b     = (const float*)d_in[10];
    const float* bn_m     = (const float*)d_in[11];
    const float* bn_v     = (const float*)d_in[12];
    const float* ln_mw    = (const float*)d_in[13];
    const float* ln_mb    = (const float*)d_in[14];
    const float* fc1_w    = (const float*)d_in[15];
    const float* fc1_b    = (const float*)d_in[16];
    const float* fc2_w    = (const float*)d_in[17];
    const float* fc2_b    = (const float*)d_in[18];
    const int*   bias_idx = (const int*)d_in[19];
    float* out = (float*)d_out;

    int n_off = in_sizes[7] / HEADS;

    cudaFuncSetAttribute(k_gemm_qkv,  cudaFuncAttributeMaxDynamicSharedMemorySize, SMEM_GEMM);
    cudaFuncSetAttribute(k_gemm_proj, cudaFuncAttributeMaxDynamicSharedMemorySize, SMEM_GEMM);
    cudaFuncSetAttribute(k_gemm_fc1,  cudaFuncAttributeMaxDynamicSharedMemorySize, SMEM_GEMM);
    cudaFuncSetAttribute(k_gemm_fc2,  cudaFuncAttributeMaxDynamicSharedMemorySize, SMEM_GEMM);
    cudaFuncSetAttribute(k_attn,      cudaFuncAttributeMaxDynamicSharedMemorySize, SMEM_ATTN);

    {
        int n0 = QKVW * Cc / 4, n1 = Cc * DH / 4, n2 = HID * Cc / 4, n3 = Cc * HID / 4;
        int tot = n0 + n1 + n2 + n3;
        k_half_all<<<(tot + 255) / 256, 256>>>((const float4*)qkv_w, n0,
                                               (const float4*)proj_w, n1,
                                               (const float4*)fc1_w, n2,
                                               (const float4*)fc2_w, n3);
    }
    {
        int tot = HEADS * Nt * Nt;
        k_bias_expand<<<(tot + 255) / 256, 256>>>(attn_bia, bias_idx, n_off);
    }
    k_win_ln<<<M_ATT / 8, 256>>>(x, ln_aw, ln_ab);
    k_gemm_qkv<<<dim3(QKVW / 128, (M_ATT + 127) / 128), 512, SMEM_GEMM>>>(qkv_b);
    k_attn<<<NW * HEADS, 256, SMEM_ATTN>>>();
    k_gemm_proj<<<dim3(Cc / 128, (M_ATT + 127) / 128), 512, SMEM_GEMM>>>(proj_b, x);
    {
        int tot = B_ * Hh * Ww * (Cc / 4);
        k_conv_bn<<<(tot + 255) / 256, 256>>>(conv_w, bn_w, bn_b, bn_m, bn_v);
    }
    k_ln_mlp<<<M_MLP / 8, 256>>>(ln_mw, ln_mb);
    k_gemm_fc1<<<dim3(HID / 128, M_MLP / 128), 512, SMEM_GEMM>>>(fc1_b);
    k_gemm_fc2<<<dim3(Cc / 128, M_MLP / 128), 512, SMEM_GEMM>>>(fc2_b, out);
}

// round 9
// speedup vs baseline: 4.0466x; 1.0871x over previous
#include <cuda_runtime.h>
#include <cuda_fp16.h>
#include <math.h>
#include <stdint.h>

// ---------------- problem constants ----------------
#define B_      8
#define Hh      64
#define Ww      64
#define Cc      384
#define HEADS   12
#define WSs     14
#define KD      32
#define Nt      196
#define NW      200
#define M_ATT   39200
#define L_      4096
#define M_MLP   32768
#define HID     1536
#define DH      384
#define QKVW    1152
#define SCALE_F 0.17677669529663687f
#define EPS_F   1e-5f

// attention tiling (unchanged, tf32 mma path)
#define NTP        208
#define QS_STRIDE  36
#define VT_STRIDE  212
#define SMEM_ATTN  ((2 * NTP * QS_STRIDE + KD * VT_STRIDE) * 4)

// fp16 gemm smem: 3 stages x (A[128][40] + B[128][40]) halfs
#define GST_BYTES   20480
#define SMEM_GEMM   (3 * GST_BYTES)

// ---------------- scratch ----------------
__device__ __align__(16) __half g_xn[M_ATT * Cc];
__device__ float  g_qkv[(size_t)M_ATT * QKVW];
__device__ __align__(16) __half g_attno[M_ATT * Cc];
__device__ float  g_x1[M_MLP * Cc];
__device__ float  g_x2[M_MLP * Cc];
__device__ __align__(16) __half g_h1[(size_t)M_MLP * HID];
__device__ float  g_bias[HEADS * Nt * Nt];
__device__ __align__(16) __half g_wq[QKVW * Cc];
__device__ __align__(16) __half g_wp[Cc * DH];
__device__ __align__(16) __half g_w1[HID * Cc];
__device__ __align__(16) __half g_w2[Cc * HID];

// ---------------- helpers ----------------
__device__ __forceinline__ float to_tf32(float x) {
    float r;
    asm("cvt.rna.tf32.f32 %0, %1;" : "=f"(r) : "f"(x));
    return r;
}

__device__ __forceinline__ void mma_tf32(float* c, const uint32_t* a, const uint32_t* b) {
    asm volatile(
        "mma.sync.aligned.m16n8k8.row.col.f32.tf32.tf32.f32 "
        "{%0,%1,%2,%3}, {%4,%5,%6,%7}, {%8,%9}, {%0,%1,%2,%3};\n"
        : "+f"(c[0]), "+f"(c[1]), "+f"(c[2]), "+f"(c[3])
        : "r"(a[0]), "r"(a[1]), "r"(a[2]), "r"(a[3]), "r"(b[0]), "r"(b[1]));
}

__device__ __forceinline__ void mma_f16(float* c, const uint32_t* a, const uint32_t* b) {
    asm volatile(
        "mma.sync.aligned.m16n8k16.row.col.f32.f16.f16.f32 "
        "{%0,%1,%2,%3}, {%4,%5,%6,%7}, {%8,%9}, {%0,%1,%2,%3};\n"
        : "+f"(c[0]), "+f"(c[1]), "+f"(c[2]), "+f"(c[3])
        : "r"(a[0]), "r"(a[1]), "r"(a[2]), "r"(a[3]), "r"(b[0]), "r"(b[1]));
}

__device__ __forceinline__ void ldsm_x4(uint32_t* r, uint32_t saddr) {
    asm volatile("ldmatrix.sync.aligned.m8n8.x4.shared.b16 {%0,%1,%2,%3}, [%4];"
                 : "=r"(r[0]), "=r"(r[1]), "=r"(r[2]), "=r"(r[3]) : "r"(saddr));
}

__device__ __forceinline__ void cp_async16(uint32_t saddr, const void* gptr, int srcbytes) {
    asm volatile("cp.async.cg.shared.global [%0], [%1], 16, %2;\n"
                 :: "r"(saddr), "l"(gptr), "r"(srcbytes));
}

__device__ __forceinline__ uint32_t smem_u32(const void* p) {
    uint32_t a;
    asm("{ .reg .u64 t; cvta.to.shared.u64 t, %1; cvt.u32.u64 %0, t; }" : "=r"(a) : "l"(p));
    return a;
}

// ---------------- weight conversion fp32 -> fp16 ----------------
__global__ void k_half_all(const float4* __restrict__ s0, int n0,
                           const float4* __restrict__ s1, int n1,
                           const float4* __restrict__ s2, int n2,
                           const float4* __restrict__ s3, int n3) {
    int i = blockIdx.x * blockDim.x + threadIdx.x;
    const float4* src; __half* dst; int j = i;
    if (j < n0) { src = s0; dst = g_wq; }
    else if ((j -= n0) < n1) { src = s1; dst = g_wp; }
    else if ((j -= n1) < n2) { src = s2; dst = g_w1; }
    else if ((j -= n2) < n3) { src = s3; dst = g_w2; }
    else return;
    float4 v = src[j];
    __half2* d2 = (__half2*)(dst + 4 * (size_t)j);
    d2[0] = __floats2half2_rn(v.x, v.y);
    d2[1] = __floats2half2_rn(v.z, v.w);
}

// ---------------- kernel: expand bias table ----------------
__global__ void k_bias_expand(const float* __restrict__ ab,
                              const int* __restrict__ bidx, int n_off) {
    int i = blockIdx.x * blockDim.x + threadIdx.x;
    if (i >= HEADS * Nt * Nt) return;
    int h  = i / (Nt * Nt);
    int ij = i - h * (Nt * Nt);
    g_bias[i] = ab[h * n_off + bidx[ij]];
}

// ---------------- kernel: window partition + LayerNorm (fp16 out) ---------
__global__ void k_win_ln(const float* __restrict__ x,
                         const float* __restrict__ w,
                         const float* __restrict__ b) {
    int warp = (blockIdx.x * blockDim.x + threadIdx.x) >> 5;
    int lane = threadIdx.x & 31;
    if (warp >= M_ATT) return;
    int wi = warp / Nt, t = warp - wi * Nt;
    int bb = wi / 25; int rem = wi - bb * 25;
    int wy = rem / 5, wx = rem - wy * 5;
    int ty = t / WSs, tx = t - ty * WSs;
    int gy = wy * WSs + ty, gx = wx * WSs + tx;
    bool valid = (gy < Hh) && (gx < Ww);
    const float* src = x + ((size_t)bb * L_ + (size_t)gy * Ww + gx) * Cc;

    float vals[12];
    float s = 0.f, s2 = 0.f;
#pragma unroll
    for (int i = 0; i < 12; i++) {
        float v = valid ? src[lane + i * 32] : 0.f;
        vals[i] = v; s += v; s2 += v * v;
    }
#pragma unroll
    for (int o = 16; o > 0; o >>= 1) {
        s  += __shfl_xor_sync(0xffffffffu, s,  o);
        s2 += __shfl_xor_sync(0xffffffffu, s2, o);
    }
    float mean = s * (1.f / Cc);
    float var  = s2 * (1.f / Cc) - mean * mean;
    float rstd = rsqrtf(var + EPS_F);
    __half* dst = g_xn + (size_t)warp * Cc;
#pragma unroll
    for (int i = 0; i < 12; i++) {
        int c = lane + i * 32;
        dst[c] = __float2half((vals[i] - mean) * rstd * w[c] + b[c]);
    }
}

// ---------------- kernel: MLP LayerNorm (fp16 out) ----------------
__global__ void k_ln_mlp(const float* __restrict__ w,
                         const float* __restrict__ b) {
    int warp = (blockIdx.x * blockDim.x + threadIdx.x) >> 5;
    int lane = threadIdx.x & 31;
    if (warp >= M_MLP) return;
    const float* src = g_x2 + (size_t)warp * Cc;
    float vals[12];
    float s = 0.f, s2 = 0.f;
#pragma unroll
    for (int i = 0; i < 12; i++) {
        float v = src[lane + i * 32];
        vals[i] = v; s += v; s2 += v * v;
    }
#pragma unroll
    for (int o = 16; o > 0; o >>= 1) {
        s  += __shfl_xor_sync(0xffffffffu, s,  o);
        s2 += __shfl_xor_sync(0xffffffffu, s2, o);
    }
    float mean = s * (1.f / Cc);
    float var  = s2 * (1.f / Cc) - mean * mean;
    float rstd = rsqrtf(var + EPS_F);
    __half* dst = g_xn + (size_t)warp * Cc;
#pragma unroll
    for (int i = 0; i < 12; i++) {
        int c = lane + i * 32;
        dst[c] = __float2half((vals[i] - mean) * rstd * w[c] + b[c]);
    }
}

// ---------------- fp16 GEMM: 512 thr, 16 warps, ldmatrix fragments --------
// C[M,N] = A[M,K] @ Bw[N,K]^T + bias; acc fp32; BK=32; 2 CTAs/SM.
template <int EPI, int M, int Nn, int K>
__device__ __forceinline__ void gemm_f16_body(const __half* __restrict__ A,
                                              const __half* __restrict__ Bw,
                                              const float* __restrict__ bias,
                                              float* __restrict__ Cout,
                                              const float* __restrict__ res) {
    extern __shared__ __align__(16) char smraw[];
    const int tid = threadIdx.x, lane = tid & 31, wid = tid >> 5;
    const int g = lane >> 2, tig = lane & 3;
    const int warp_m = wid >> 2, warp_n = wid & 3;    // 4 x 4 warps
    const int bm = blockIdx.y * 128, bn = blockIdx.x * 128;
    const int arow = tid >> 2, seg = tid & 3;

    const int r0 = bm + arow;
    const bool v0 = ((M % 128) == 0) || (r0 < M);
    const int sz0 = v0 ? 16 : 0;
    const __half* a0b = A  + (size_t)(v0 ? r0 : 0) * K + seg * 8;
    const __half* b0b = Bw + (size_t)(bn + arow) * K + seg * 8;
    const uint32_t smb = smem_u32(smraw);
    const uint32_t sa0 = smb + arow * 80 + seg * 16;
    const uint32_t sb0 = sa0 + 10240;

    // ldmatrix per-lane address offsets (in halfs -> bytes via *2)
    const int a_row = (lane & 15), a_k = 8 * (lane >> 4);
    const int b_row = (lane >> 4) * 8 + (lane & 7), b_k = 8 * ((lane >> 3) & 1);
    const uint32_t aA = smb + ((warp_m * 32 + a_row) * 40 + a_k) * 2;
    const uint32_t aB = smb + 10240 + ((warp_n * 32 + b_row) * 40 + b_k) * 2;

    const int KT = K / 32;
    auto load_stage = [&](int s, int kt) {
        int kc = kt * 32;
        uint32_t so = (uint32_t)(s * GST_BYTES);
        cp_async16(sa0 + so, a0b + kc, sz0);
        cp_async16(sb0 + so, b0b + kc, 16);
        asm volatile("cp.async.commit_group;\n");
    };

    float acc[2][4][4];
#pragma unroll
    for (int mt = 0; mt < 2; mt++)
#pragma unroll
        for (int nt = 0; nt < 4; nt++)
#pragma unroll
            for (int r = 0; r < 4; r++) acc[mt][nt][r] = 0.f;

    load_stage(0, 0);
    load_stage(1, 1);

    for (int kt = 0; kt < KT; kt++) {
        if (kt + 1 < KT) {
            asm volatile("cp.async.wait_group 1;\n");
        } else {
            asm volatile("cp.async.wait_group 0;\n");
        }
        __syncthreads();
        if (kt + 2 < KT) load_stage((kt + 2) % 3, kt + 2);

        const uint32_t st = (uint32_t)((kt % 3) * GST_BYTES);
#pragma unroll
        for (int ks = 0; ks < 2; ks++) {
            const int kb = ks * 16;
            uint32_t afr[2][4], bfr2[2][4];
            ldsm_x4(afr[0], aA + st + kb * 2);
            ldsm_x4(afr[1], aA + st + (16 * 40 + kb) * 2);
            ldsm_x4(bfr2[0], aB + st + kb * 2);            // nt 0,1
            ldsm_x4(bfr2[1], aB + st + (16 * 40 + kb) * 2); // nt 2,3
#pragma unroll
            for (int mt = 0; mt < 2; mt++) {
                mma_f16(acc[mt][0], afr[mt], &bfr2[0][0]);
                mma_f16(acc[mt][1], afr[mt], &bfr2[0][2]);
                mma_f16(acc[mt][2], afr[mt], &bfr2[1][0]);
                mma_f16(acc[mt][3], afr[mt], &bfr2[1][2]);
            }
        }
    }

#pragma unroll
    for (int mt = 0; mt < 2; mt++) {
#pragma unroll
        for (int nt = 0; nt < 4; nt++) {
#pragma unroll
            for (int r = 0; r < 4; r++) {
                int m  = bm + warp_m * 32 + mt * 16 + g + ((r >> 1) ? 8 : 0);
                int nn = bn + warp_n * 32 + nt * 8 + tig * 2 + (r & 1);
                if (((M % 128) != 0) && (m >= M)) continue;
                float v = acc[mt][nt][r] + bias[nn];
                if (EPI == 0) {
                    Cout[(size_t)m * Nn + nn] = v;
                } else if (EPI == 1) {
                    ((__half*)Cout)[(size_t)m * Nn + nn] =
                        __float2half(0.5f * v * (1.f + erff(v * 0.70710678118654752f)));
                } else if (EPI == 2) {
                    int wi = m / Nt, t = m - wi * Nt;
                    int bb2 = wi / 25; int rem = wi - bb2 * 25;
                    int wy = rem / 5, wx = rem - wy * 5;
                    int ty = t / WSs, tx = t - ty * WSs;
                    int gy = wy * WSs + ty, gx = wx * WSs + tx;
                    if (gy < Hh && gx < Ww) {
                        size_t o = ((size_t)bb2 * L_ + (size_t)gy * Ww + gx) * Cc + nn;
                        Cout[o] = res[o] + v;
                    }
                } else {
                    size_t o = (size_t)m * Nn + nn;
                    Cout[o] = v + res[o];
                }
            }
        }
    }
}

__global__ __launch_bounds__(512, 2) void k_gemm_qkv(const float* __restrict__ b) {
    gemm_f16_body<0, M_ATT, QKVW, Cc>(g_xn, g_wq, b, g_qkv, nullptr);
}
__global__ __launch_bounds__(512, 2) void k_gemm_proj(const float* __restrict__ b,
                                                      const float* __restrict__ x) {
    gemm_f16_body<2, M_ATT, Cc, DH>(g_attno, g_wp, b, g_x1, x);
}
__global__ __launch_bounds__(512, 2) void k_gemm_fc1(const float* __restrict__ b) {
    gemm_f16_body<1, M_MLP, HID, Cc>(g_xn, g_w1, b, (float*)g_h1, nullptr);
}
__global__ __launch_bounds__(512, 2) void k_gemm_fc2(const float* __restrict__ b,
                                                     float* __restrict__ out) {
    gemm_f16_body<3, M_MLP, Cc, HID>(g_h1, g_w2, b, out, g_x2);
}

// ---------------- tensor-core attention (unchanged) ------------------------
__global__ __launch_bounds__(256) void k_attn() {
    extern __shared__ float sm[];
    float* qs = sm;
    float* ks = sm + NTP * QS_STRIDE;
    float* vt = ks + NTP * QS_STRIDE;

    const int blk = blockIdx.x;
    const int w = blk / HEADS, h = blk - w * HEADS;
    const float* base = g_qkv + (size_t)w * Nt * QKVW + h * 96;
    const int tid = threadIdx.x, lane = tid & 31, wid = tid >> 5;
    const int g = lane >> 2, tig = lane & 3;

    for (int idx = tid; idx < NTP * 8; idx += 256) {
        int r = idx >> 3, d4 = (idx & 7) * 4;
        float4 q4, k4, v4;
        if (r < Nt) {
            const float* rp = base + (size_t)r * QKVW;
            q4 = *(const float4*)(rp + d4);
            k4 = *(const float4*)(rp + 32 + d4);
            v4 = *(const float4*)(rp + 64 + d4);
        } else {
            q4 = k4 = v4 = make_float4(0.f, 0.f, 0.f, 0.f);
        }
        float* qd = qs + r * QS_STRIDE + d4;
        qd[0] = to_tf32(q4.x * SCALE_F); qd[1] = to_tf32(q4.y * SCALE_F);
        qd[2] = to_tf32(q4.z * SCALE_F); qd[3] = to_tf32(q4.w * SCALE_F);
        float* kd = ks + r * QS_STRIDE + d4;
        kd[0] = to_tf32(k4.x); kd[1] = to_tf32(k4.y);
        kd[2] = to_tf32(k4.z); kd[3] = to_tf32(k4.w);
        vt[(d4 + 0) * VT_STRIDE + r] = to_tf32(v4.x);
        vt[(d4 + 1) * VT_STRIDE + r] = to_tf32(v4.y);
        vt[(d4 + 2) * VT_STRIDE + r] = to_tf32(v4.z);
        vt[(d4 + 3) * VT_STRIDE + r] = to_tf32(v4.w);
    }
    __syncthreads();

    const float* bias_h = g_bias + (size_t)h * Nt * Nt;

    for (int tt = wid; tt < 13; tt += 8) {
        const int row0 = tt * 16 + g, row1 = row0 + 8;

        uint32_t aq[4][4];
#pragma unroll
        for (int kk = 0; kk < 4; kk++) {
            aq[kk][0] = __float_as_uint(qs[(tt*16 + g    ) * QS_STRIDE + kk*8 + tig]);
            aq[kk][1] = __float_as_uint(qs[(tt*16 + g + 8) * QS_STRIDE + kk*8 + tig]);
            aq[kk][2] = __float_as_uint(qs[(tt*16 + g    ) * QS_STRIDE + kk*8 + tig + 4]);
            aq[kk][3] = __float_as_uint(qs[(tt*16 + g + 8) * QS_STRIDE + kk*8 + tig + 4]);
        }

        float acc[26][4];
#pragma unroll
        for (int nt = 0; nt < 26; nt++) {
            acc[nt][0] = acc[nt][1] = acc[nt][2] = acc[nt][3] = 0.f;
#pragma unroll
            for (int kk = 0; kk < 4; kk++) {
                uint32_t b[2];
                b[0] = __float_as_uint(ks[(nt*8 + g) * QS_STRIDE + kk*8 + tig]);
                b[1] = __float_as_uint(ks[(nt*8 + g) * QS_STRIDE + kk*8 + tig + 4]);
                mma_tf32(acc[nt], aq[kk], b);
            }
        }

        const bool r0v = row0 < Nt, r1v = row1 < Nt;
        float m0 = -1e30f, m1 = -1e30f;
#pragma unroll
        for (int nt = 0; nt < 26; nt++) {
            int col = nt * 8 + tig * 2;
            bool cv = col < Nt;
            float2 b0 = (cv && r0v) ? *(const float2*)(bias_h + (size_t)row0 * Nt + col)
                                    : make_float2(0.f, 0.f);
            float2 b1 = (cv && r1v) ? *(const float2*)(bias_h + (size_t)row1 * Nt + col)
                                    : make_float2(0.f, 0.f);
            acc[nt][0] = cv ? acc[nt][0] + b0.x : -1e30f;
            acc[nt][1] = cv ? acc[nt][1] + b0.y : -1e30f;
            acc[nt][2] = cv ? acc[nt][2] + b1.x : -1e30f;
            acc[nt][3] = cv ? acc[nt][3] + b1.y : -1e30f;
            m0 = fmaxf(m0, fmaxf(acc[nt][0], acc[nt][1]));
            m1 = fmaxf(m1, fmaxf(acc[nt][2], acc[nt][3]));
        }
        m0 = fmaxf(m0, __shfl_xor_sync(0xffffffffu, m0, 1));
        m0 = fmaxf(m0, __shfl_xor_sync(0xffffffffu, m0, 2));
        m1 = fmaxf(m1, __shfl_xor_sync(0xffffffffu, m1, 1));
        m1 = fmaxf(m1, __shfl_xor_sync(0xffffffffu, m1, 2));

        float l0 = 0.f, l1 = 0.f;
#pragma unroll
        for (int nt = 0; nt < 26; nt++) {
            acc[nt][0] = __expf(acc[nt][0] - m0); l0 += acc[nt][0];
            acc[nt][1] = __expf(acc[nt][1] - m0); l0 += acc[nt][1];
            acc[nt][2] = __expf(acc[nt][2] - m1); l1 += acc[nt][2];
            acc[nt][3] = __expf(acc[nt][3] - m1); l1 += acc[nt][3];
        }
        l0 += __shfl_xor_sync(0xffffffffu, l0, 1);
        l0 += __shfl_xor_sync(0xffffffffu, l0, 2);
        l1 += __shfl_xor_sync(0xffffffffu, l1, 1);
        l1 += __shfl_xor_sync(0xffffffffu, l1, 2);

        float oacc[4][4];
#pragma unroll
        for (int nt = 0; nt < 4; nt++)
            oacc[nt][0] = oacc[nt][1] = oacc[nt][2] = oacc[nt][3] = 0.f;

        const int srcA = (lane & ~3) | (tig >> 1);
        const int srcB = (lane & ~3) | (2 + (tig >> 1));
        const bool odd = (tig & 1) != 0;
#pragma unroll
        for (int kk = 0; kk < 26; kk++) {
            float v00 = __shfl_sync(0xffffffffu, acc[kk][0], srcA);
            float v01 = __shfl_sync(0xffffffffu, acc[kk][1], srcA);
            float v20 = __shfl_sync(0xffffffffu, acc[kk][2], srcA);
            float v21 = __shfl_sync(0xffffffffu, acc[kk][3], srcA);
            float w00 = __shfl_sync(0xffffffffu, acc[kk][0], srcB);
            float w01 = __shfl_sync(0xffffffffu, acc[kk][1], srcB);
            float w20 = __shfl_sync(0xffffffffu, acc[kk][2], srcB);
            float w21 = __shfl_sync(0xffffffffu, acc[kk][3], srcB);
            uint32_t pa[4];
            pa[0] = __float_as_uint(to_tf32(odd ? v01 : v00));
            pa[1] = __float_as_uint(to_tf32(odd ? v21 : v20));
            pa[2] = __float_as_uint(to_tf32(odd ? w01 : w00));
            pa[3] = __float_as_uint(to_tf32(odd ? w21 : w20));
#pragma unroll
            for (int nt = 0; nt < 4; nt++) {
                uint32_t b[2];
                b[0] = __float_as_uint(vt[(nt*8 + g) * VT_STRIDE + kk*8 + tig]);
                b[1] = __float_as_uint(vt[(nt*8 + g) * VT_STRIDE + kk*8 + tig + 4]);
                mma_tf32(oacc[nt], pa, b);
            }
        }

        const float inv0 = 1.f / l0, inv1 = 1.f / l1;
        if (r0v) {
            __half* op = g_attno + ((size_t)(w * Nt + row0)) * DH + h * KD;
#pragma unroll
            for (int nt = 0; nt < 4; nt++)
                *(__half2*)(op + nt * 8 + tig * 2) =
                    __floats2half2_rn(oacc[nt][0] * inv0, oacc[nt][1] * inv0);
        }
        if (r1v) {
            __half* op = g_attno + ((size_t)(w * Nt + row1)) * DH + h * KD;
#pragma unroll
            for (int nt = 0; nt < 4; nt++)
                *(__half2*)(op + nt * 8 + tig * 2) =
                    __floats2half2_rn(oacc[nt][2] * inv1, oacc[nt][3] * inv1);
        }
    }
}

// ---------------- depthwise 3x3 conv + BN ----------------
__global__ void k_conv_bn(const float* __restrict__ cw,
                          const float* __restrict__ bnw,
                          const float* __restrict__ bnb,
                          const float* __restrict__ bnm,
                          const float* __restrict__ bnv) {
    int idx = blockIdx.x * blockDim.x + threadIdx.x;
    const int C4 = Cc / 4;
    const int total = B_ * Hh * Ww * C4;
    if (idx >= total) return;
    int c4 = idx % C4;
    int x  = (idx / C4) % Ww;
    int y  = (idx / (C4 * Ww)) % Hh;
    int b  = idx / (C4 * Ww * Hh);
    int c0 = c4 * 4;

    float4 acc = make_float4(0.f, 0.f, 0.f, 0.f);
#pragma unroll
    for (int ky = 0; ky < 3; ky++) {
        int yy = y + ky - 1;
        if (yy < 0 || yy >= Hh) continue;
#pragma unroll
        for (int kx = 0; kx < 3; kx++) {
            int xx = x + kx - 1;
            if (xx < 0 || xx >= Ww) continue;
            float4 in = *(const float4*)&g_x1[((size_t)b * L_ + (size_t)yy * Ww + xx) * Cc + c0];
            int wo = ky * 3 + kx;
            acc.x += in.x * cw[(c0 + 0) * 9 + wo];
            acc.y += in.y * cw[(c0 + 1) * 9 + wo];
            acc.z += in.z * cw[(c0 + 2) * 9 + wo];
            acc.w += in.w * cw[(c0 + 3) * 9 + wo];
        }
    }
    float4 outv;
    outv.x = (acc.x - bnm[c0 + 0]) * (rsqrtf(bnv[c0 + 0] + 1e-5f) * bnw[c0 + 0]) + bnb[c0 + 0];
    outv.y = (acc.y - bnm[c0 + 1]) * (rsqrtf(bnv[c0 + 1] + 1e-5f) * bnw[c0 + 1]) + bnb[c0 + 1];
    outv.z = (acc.z - bnm[c0 + 2]) * (rsqrtf(bnv[c0 + 2] + 1e-5f) * bnw[c0 + 2]) + bnb[c0 + 2];
    outv.w = (acc.w - bnm[c0 + 3]) * (rsqrtf(bnv[c0 + 3] + 1e-5f) * bnw[c0 + 3]) + bnb[c0 + 3];
    *(float4*)&g_x2[(size_t)idx * 4] = outv;
}

// ---------------- launcher ----------------
extern "C" void kernel_launch(void* const* d_in, const int* in_sizes, int n_in,
                              void* d_out, int out_size) {
    const float* x        = (const float*)d_in[0];
    const float* ln_aw    = (const float*)d_in[1];
    const float* ln_ab    = (const float*)d_in[2];
    const float* qkv_w    = (const float*)d_in[3];
    const float* qkv_b    = (const float*)d_in[4];
    const float* proj_w   = (const float*)d_in[5];
    const float* proj_b   = (const float*)d_in[6];
    const float* attn_bia = (const float*)d_in[7];
    const float* conv_w   = (const float*)d_in[8];
    const float* bn_w     = (const float*)d_in[9];
    const float* bn_b     = (const float*)d_in[10];
    const float* bn_m     = (const float*)d_in[11];
    const float* bn_v     = (const float*)d_in[12];
    const float* ln_mw    = (const float*)d_in[13];
    const float* ln_mb    = (const float*)d_in[14];
    const float* fc1_w    = (const float*)d_in[15];
    const float* fc1_b    = (const float*)d_in[16];
    const float* fc2_w    = (const float*)d_in[17];
    const float* fc2_b    = (const float*)d_in[18];
    const int*   bias_idx = (const int*)d_in[19];
    float* out = (float*)d_out;

    int n_off = in_sizes[7] / HEADS;

    cudaFuncSetAttribute(k_gemm_qkv,  cudaFuncAttributeMaxDynamicSharedMemorySize, SMEM_GEMM);
    cudaFuncSetAttribute(k_gemm_proj, cudaFuncAttributeMaxDynamicSharedMemorySize, SMEM_GEMM);
    cudaFuncSetAttribute(k_gemm_fc1,  cudaFuncAttributeMaxDynamicSharedMemorySize, SMEM_GEMM);
    cudaFuncSetAttribute(k_gemm_fc2,  cudaFuncAttributeMaxDynamicSharedMemorySize, SMEM_GEMM);
    cudaFuncSetAttribute(k_attn,      cudaFuncAttributeMaxDynamicSharedMemorySize, SMEM_ATTN);

    {
        int n0 = QKVW * Cc / 4, n1 = Cc * DH / 4, n2 = HID * Cc / 4, n3 = Cc * HID / 4;
        int tot = n0 + n1 + n2 + n3;
        k_half_all<<<(tot + 255) / 256, 256>>>((const float4*)qkv_w, n0,
                                               (const float4*)proj_w, n1,
                                               (const float4*)fc1_w, n2,
                                               (const float4*)fc2_w, n3);
    }
    {
        int tot = HEADS * Nt * Nt;
        k_bias_expand<<<(tot + 255) / 256, 256>>>(attn_bia, bias_idx, n_off);
    }
    k_win_ln<<<M_ATT / 8, 256>>>(x, ln_aw, ln_ab);
    k_gemm_qkv<<<dim3(QKVW / 128, (M_ATT + 127) / 128), 512, SMEM_GEMM>>>(qkv_b);
    k_attn<<<NW * HEADS, 256, SMEM_ATTN>>>();
    k_gemm_proj<<<dim3(Cc / 128, (M_ATT + 127) / 128), 512, SMEM_GEMM>>>(proj_b, x);
    {
        int tot = B_ * Hh * Ww * (Cc / 4);
        k_conv_bn<<<(tot + 255) / 256, 256>>>(conv_w, bn_w, bn_b, bn_m, bn_v);
    }
    k_ln_mlp<<<M_MLP / 8, 256>>>(ln_mw, ln_mb);
    k_gemm_fc1<<<dim3(HID / 128, M_MLP / 128), 512, SMEM_GEMM>>>(fc1_b);
    k_gemm_fc2<<<dim3(Cc / 128, M_MLP / 128), 512, SMEM_GEMM>>>(fc2_b, out);
}

// round 10
// speedup vs baseline: 4.2030x; 1.0387x over previous
#include <cuda_runtime.h>
#include <cuda_fp16.h>
#include <math.h>
#include <stdint.h>

// ---------------- problem constants ----------------
#define B_      8
#define Hh      64
#define Ww      64
#define Cc      384
#define HEADS   12
#define WSs     14
#define KD      32
#define Nt      196
#define NW      200
#define M_ATT   39200
#define L_      4096
#define M_MLP   32768
#define HID     1536
#define DH      384
#define QKVW    1152
#define SCALE_F 0.17677669529663687f
#define EPS_F   1e-5f

// attention tiling: fp16 smem, 208 rows x 40-half stride, q/k/v
#define NTP        208
#define AQ_STR     40
#define SMEM_ATTN  (3 * NTP * AQ_STR * 2)

// fp16 gemm smem: 3 stages x (A[128][40] + B[128][40]) halfs
#define GST_BYTES   20480
#define SMEM_GEMM   (3 * GST_BYTES)

// ---------------- scratch ----------------
__device__ __align__(16) __half g_xn[M_ATT * Cc];
__device__ float  g_qkv[(size_t)M_ATT * QKVW];
__device__ __align__(16) __half g_attno[M_ATT * Cc];
__device__ float  g_x1[M_MLP * Cc];
__device__ float  g_x2[M_MLP * Cc];
__device__ __align__(16) __half g_h1[(size_t)M_MLP * HID];
__device__ float  g_bias[HEADS * Nt * Nt];
__device__ __align__(16) __half g_wq[QKVW * Cc];
__device__ __align__(16) __half g_wp[Cc * DH];
__device__ __align__(16) __half g_w1[HID * Cc];
__device__ __align__(16) __half g_w2[Cc * HID];

// ---------------- helpers ----------------
__device__ __forceinline__ void mma_f16(float* c, const uint32_t* a, const uint32_t* b) {
    asm volatile(
        "mma.sync.aligned.m16n8k16.row.col.f32.f16.f16.f32 "
        "{%0,%1,%2,%3}, {%4,%5,%6,%7}, {%8,%9}, {%0,%1,%2,%3};\n"
        : "+f"(c[0]), "+f"(c[1]), "+f"(c[2]), "+f"(c[3])
        : "r"(a[0]), "r"(a[1]), "r"(a[2]), "r"(a[3]), "r"(b[0]), "r"(b[1]));
}

__device__ __forceinline__ void ldsm_x4(uint32_t* r, uint32_t saddr) {
    asm volatile("ldmatrix.sync.aligned.m8n8.x4.shared.b16 {%0,%1,%2,%3}, [%4];"
                 : "=r"(r[0]), "=r"(r[1]), "=r"(r[2]), "=r"(r[3]) : "r"(saddr));
}

__device__ __forceinline__ void ldsm_x4_t(uint32_t* r, uint32_t saddr) {
    asm volatile("ldmatrix.sync.aligned.m8n8.x4.trans.shared.b16 {%0,%1,%2,%3}, [%4];"
                 : "=r"(r[0]), "=r"(r[1]), "=r"(r[2]), "=r"(r[3]) : "r"(saddr));
}

__device__ __forceinline__ void cp_async16(uint32_t saddr, const void* gptr, int srcbytes) {
    asm volatile("cp.async.cg.shared.global [%0], [%1], 16, %2;\n"
                 :: "r"(saddr), "l"(gptr), "r"(srcbytes));
}

__device__ __forceinline__ uint32_t smem_u32(const void* p) {
    uint32_t a;
    asm("{ .reg .u64 t; cvta.to.shared.u64 t, %1; cvt.u32.u64 %0, t; }" : "=r"(a) : "l"(p));
    return a;
}

__device__ __forceinline__ uint32_t h2u(__half2 h) {
    return *(uint32_t*)&h;
}

// ---------------- weight conversion fp32 -> fp16 ----------------
__global__ void k_half_all(const float4* __restrict__ s0, int n0,
                           const float4* __restrict__ s1, int n1,
                           const float4* __restrict__ s2, int n2,
                           const float4* __restrict__ s3, int n3) {
    int i = blockIdx.x * blockDim.x + threadIdx.x;
    const float4* src; __half* dst; int j = i;
    if (j < n0) { src = s0; dst = g_wq; }
    else if ((j -= n0) < n1) { src = s1; dst = g_wp; }
    else if ((j -= n1) < n2) { src = s2; dst = g_w1; }
    else if ((j -= n2) < n3) { src = s3; dst = g_w2; }
    else return;
    float4 v = src[j];
    __half2* d2 = (__half2*)(dst + 4 * (size_t)j);
    d2[0] = __floats2half2_rn(v.x, v.y);
    d2[1] = __floats2half2_rn(v.z, v.w);
}

// ---------------- kernel: expand bias table ----------------
__global__ void k_bias_expand(const float* __restrict__ ab,
                              const int* __restrict__ bidx, int n_off) {
    int i = blockIdx.x * blockDim.x + threadIdx.x;
    if (i >= HEADS * Nt * Nt) return;
    int h  = i / (Nt * Nt);
    int ij = i - h * (Nt * Nt);
    g_bias[i] = ab[h * n_off + bidx[ij]];
}

// ---------------- kernel: window partition + LayerNorm (fp16 out) ---------
__global__ void k_win_ln(const float* __restrict__ x,
                         const float* __restrict__ w,
                         const float* __restrict__ b) {
    int warp = (blockIdx.x * blockDim.x + threadIdx.x) >> 5;
    int lane = threadIdx.x & 31;
    if (warp >= M_ATT) return;
    int wi = warp / Nt, t = warp - wi * Nt;
    int bb = wi / 25; int rem = wi - bb * 25;
    int wy = rem / 5, wx = rem - wy * 5;
    int ty = t / WSs, tx = t - ty * WSs;
    int gy = wy * WSs + ty, gx = wx * WSs + tx;
    bool valid = (gy < Hh) && (gx < Ww);
    const float* src = x + ((size_t)bb * L_ + (size_t)gy * Ww + gx) * Cc;

    float vals[12];
    float s = 0.f, s2 = 0.f;
#pragma unroll
    for (int i = 0; i < 12; i++) {
        float v = valid ? src[lane + i * 32] : 0.f;
        vals[i] = v; s += v; s2 += v * v;
    }
#pragma unroll
    for (int o = 16; o > 0; o >>= 1) {
        s  += __shfl_xor_sync(0xffffffffu, s,  o);
        s2 += __shfl_xor_sync(0xffffffffu, s2, o);
    }
    float mean = s * (1.f / Cc);
    float var  = s2 * (1.f / Cc) - mean * mean;
    float rstd = rsqrtf(var + EPS_F);
    __half* dst = g_xn + (size_t)warp * Cc;
#pragma unroll
    for (int i = 0; i < 12; i++) {
        int c = lane + i * 32;
        dst[c] = __float2half((vals[i] - mean) * rstd * w[c] + b[c]);
    }
}

// ---------------- kernel: MLP LayerNorm (fp16 out) ----------------
__global__ void k_ln_mlp(const float* __restrict__ w,
                         const float* __restrict__ b) {
    int warp = (blockIdx.x * blockDim.x + threadIdx.x) >> 5;
    int lane = threadIdx.x & 31;
    if (warp >= M_MLP) return;
    const float* src = g_x2 + (size_t)warp * Cc;
    float vals[12];
    float s = 0.f, s2 = 0.f;
#pragma unroll
    for (int i = 0; i < 12; i++) {
        float v = src[lane + i * 32];
        vals[i] = v; s += v; s2 += v * v;
    }
#pragma unroll
    for (int o = 16; o > 0; o >>= 1) {
        s  += __shfl_xor_sync(0xffffffffu, s,  o);
        s2 += __shfl_xor_sync(0xffffffffu, s2, o);
    }
    float mean = s * (1.f / Cc);
    float var  = s2 * (1.f / Cc) - mean * mean;
    float rstd = rsqrtf(var + EPS_F);
    __half* dst = g_xn + (size_t)warp * Cc;
#pragma unroll
    for (int i = 0; i < 12; i++) {
        int c = lane + i * 32;
        dst[c] = __float2half((vals[i] - mean) * rstd * w[c] + b[c]);
    }
}

// ---------------- fp16 GEMM (unchanged from round 9) ----------------
template <int EPI, int M, int Nn, int K>
__device__ __forceinline__ void gemm_f16_body(const __half* __restrict__ A,
                                              const __half* __restrict__ Bw,
                                              const float* __restrict__ bias,
                                              float* __restrict__ Cout,
                                              const float* __restrict__ res) {
    extern __shared__ __align__(16) char smraw[];
    const int tid = threadIdx.x, lane = tid & 31, wid = tid >> 5;
    const int g = lane >> 2, tig = lane & 3;
    const int warp_m = wid >> 2, warp_n = wid & 3;
    const int bm = blockIdx.y * 128, bn = blockIdx.x * 128;
    const int arow = tid >> 2, seg = tid & 3;

    const int r0 = bm + arow;
    const bool v0 = ((M % 128) == 0) || (r0 < M);
    const int sz0 = v0 ? 16 : 0;
    const __half* a0b = A  + (size_t)(v0 ? r0 : 0) * K + seg * 8;
    const __half* b0b = Bw + (size_t)(bn + arow) * K + seg * 8;
    const uint32_t smb = smem_u32(smraw);
    const uint32_t sa0 = smb + arow * 80 + seg * 16;
    const uint32_t sb0 = sa0 + 10240;

    const int a_row = (lane & 15), a_k = 8 * (lane >> 4);
    const int b_row = (lane >> 4) * 8 + (lane & 7), b_k = 8 * ((lane >> 3) & 1);
    const uint32_t aA = smb + ((warp_m * 32 + a_row) * 40 + a_k) * 2;
    const uint32_t aB = smb + 10240 + ((warp_n * 32 + b_row) * 40 + b_k) * 2;

    const int KT = K / 32;
    auto load_stage = [&](int s, int kt) {
        int kc = kt * 32;
        uint32_t so = (uint32_t)(s * GST_BYTES);
        cp_async16(sa0 + so, a0b + kc, sz0);
        cp_async16(sb0 + so, b0b + kc, 16);
        asm volatile("cp.async.commit_group;\n");
    };

    float acc[2][4][4];
#pragma unroll
    for (int mt = 0; mt < 2; mt++)
#pragma unroll
        for (int nt = 0; nt < 4; nt++)
#pragma unroll
            for (int r = 0; r < 4; r++) acc[mt][nt][r] = 0.f;

    load_stage(0, 0);
    load_stage(1, 1);

    for (int kt = 0; kt < KT; kt++) {
        if (kt + 1 < KT) {
            asm volatile("cp.async.wait_group 1;\n");
        } else {
            asm volatile("cp.async.wait_group 0;\n");
        }
        __syncthreads();
        if (kt + 2 < KT) load_stage((kt + 2) % 3, kt + 2);

        const uint32_t st = (uint32_t)((kt % 3) * GST_BYTES);
#pragma unroll
        for (int ks = 0; ks < 2; ks++) {
            const int kb = ks * 16;
            uint32_t afr[2][4], bfr2[2][4];
            ldsm_x4(afr[0], aA + st + kb * 2);
            ldsm_x4(afr[1], aA + st + (16 * 40 + kb) * 2);
            ldsm_x4(bfr2[0], aB + st + kb * 2);
            ldsm_x4(bfr2[1], aB + st + (16 * 40 + kb) * 2);
#pragma unroll
            for (int mt = 0; mt < 2; mt++) {
                mma_f16(acc[mt][0], afr[mt], &bfr2[0][0]);
                mma_f16(acc[mt][1], afr[mt], &bfr2[0][2]);
                mma_f16(acc[mt][2], afr[mt], &bfr2[1][0]);
                mma_f16(acc[mt][3], afr[mt], &bfr2[1][2]);
            }
        }
    }

#pragma unroll
    for (int mt = 0; mt < 2; mt++) {
#pragma unroll
        for (int nt = 0; nt < 4; nt++) {
#pragma unroll
            for (int r = 0; r < 4; r++) {
                int m  = bm + warp_m * 32 + mt * 16 + g + ((r >> 1) ? 8 : 0);
                int nn = bn + warp_n * 32 + nt * 8 + tig * 2 + (r & 1);
                if (((M % 128) != 0) && (m >= M)) continue;
                float v = acc[mt][nt][r] + bias[nn];
                if (EPI == 0) {
                    Cout[(size_t)m * Nn + nn] = v;
                } else if (EPI == 1) {
                    ((__half*)Cout)[(size_t)m * Nn + nn] =
                        __float2half(0.5f * v * (1.f + erff(v * 0.70710678118654752f)));
                } else if (EPI == 2) {
                    int wi = m / Nt, t = m - wi * Nt;
                    int bb2 = wi / 25; int rem = wi - bb2 * 25;
                    int wy = rem / 5, wx = rem - wy * 5;
                    int ty = t / WSs, tx = t - ty * WSs;
                    int gy = wy * WSs + ty, gx = wx * WSs + tx;
                    if (gy < Hh && gx < Ww) {
                        size_t o = ((size_t)bb2 * L_ + (size_t)gy * Ww + gx) * Cc + nn;
                        Cout[o] = res[o] + v;
                    }
                } else {
                    size_t o = (size_t)m * Nn + nn;
                    Cout[o] = v + res[o];
                }
            }
        }
    }
}

__global__ __launch_bounds__(512, 2) void k_gemm_qkv(const float* __restrict__ b) {
    gemm_f16_body<0, M_ATT, QKVW, Cc>(g_xn, g_wq, b, g_qkv, nullptr);
}
__global__ __launch_bounds__(512, 2) void k_gemm_proj(const float* __restrict__ b,
                                                      const float* __restrict__ x) {
    gemm_f16_body<2, M_ATT, Cc, DH>(g_attno, g_wp, b, g_x1, x);
}
__global__ __launch_bounds__(512, 2) void k_gemm_fc1(const float* __restrict__ b) {
    gemm_f16_body<1, M_MLP, HID, Cc>(g_xn, g_w1, b, (float*)g_h1, nullptr);
}
__global__ __launch_bounds__(512, 2) void k_gemm_fc2(const float* __restrict__ b,
                                                     float* __restrict__ out) {
    gemm_f16_body<3, M_MLP, Cc, HID>(g_h1, g_w2, b, out, g_x2);
}

// ---------------- fp16 tensor-core attention ----------------
// One block per (window, head); 8 warps; full-row softmax; zero-shuffle P->A.
__global__ __launch_bounds__(256) void k_attn() {
    extern __shared__ __align__(16) __half smh[];
    __half* qs = smh;                       // [208][40] q*scale
    __half* ks = smh + NTP * AQ_STR;        // [208][40]
    __half* vs = smh + 2 * NTP * AQ_STR;    // [208][40]

    const int blk = blockIdx.x;
    const int w = blk / HEADS, h = blk - w * HEADS;
    const float* base = g_qkv + (size_t)w * Nt * QKVW + h * 96;
    const int tid = threadIdx.x, lane = tid & 31, wid = tid >> 5;
    const int g = lane >> 2, tig = lane & 3;
    const uint32_t smb = smem_u32(smh);

    // stage: fp32 qkv -> fp16 smem (zero pad rows >= 196)
    for (int idx = tid; idx < NTP * 8; idx += 256) {
        int r = idx >> 3, d4 = (idx & 7) * 4;
        float4 q4, k4, v4;
        if (r < Nt) {
            const float* rp = base + (size_t)r * QKVW;
            q4 = *(const float4*)(rp + d4);
            k4 = *(const float4*)(rp + 32 + d4);
            v4 = *(const float4*)(rp + 64 + d4);
        } else {
            q4 = k4 = v4 = make_float4(0.f, 0.f, 0.f, 0.f);
        }
        __half2* qd = (__half2*)(qs + r * AQ_STR + d4);
        qd[0] = __floats2half2_rn(q4.x * SCALE_F, q4.y * SCALE_F);
        qd[1] = __floats2half2_rn(q4.z * SCALE_F, q4.w * SCALE_F);
        __half2* kd = (__half2*)(ks + r * AQ_STR + d4);
        kd[0] = __floats2half2_rn(k4.x, k4.y);
        kd[1] = __floats2half2_rn(k4.z, k4.w);
        __half2* vd = (__half2*)(vs + r * AQ_STR + d4);
        vd[0] = __floats2half2_rn(v4.x, v4.y);
        vd[1] = __floats2half2_rn(v4.z, v4.w);
    }
    __syncthreads();

    const float* bias_h = g_bias + (size_t)h * Nt * Nt;

    // ldmatrix lane offsets
    const int a_row = (lane & 15), a_k = 8 * (lane >> 4);
    const int b_row = (lane >> 4) * 8 + (lane & 7), b_k = 8 * ((lane >> 3) & 1);
    const uint32_t vs_off = (uint32_t)(2 * NTP * AQ_STR * 2);
    // V trans addresses: rows kk*16 + (lane&15), col chunk + 8*(lane>>4)
    const uint32_t vaddr0 = smb + vs_off + (((lane & 15)) * AQ_STR + 8 * (lane >> 4)) * 2;

    for (int tt = wid; tt < 13; tt += 8) {
        const int row0 = tt * 16 + g, row1 = row0 + 8;

        // Q A-fragments: 2 k-chunks of 16
        uint32_t aq[2][4];
        {
            uint32_t qa = smb + ((tt * 16 + a_row) * AQ_STR + a_k) * 2;
            ldsm_x4(aq[0], qa);
            ldsm_x4(aq[1], qa + 32);   // +16 halfs
        }

        // S = Q @ K^T : 26 col-tiles of 8, processed as 13 pairs
        float acc[26][4];
#pragma unroll
        for (int np = 0; np < 13; np++) {
            uint32_t ka = smb + (uint32_t)(NTP * AQ_STR * 2) +
                          ((np * 16 + b_row) * AQ_STR + b_k) * 2;
            uint32_t bf0[4], bf1[4];
            ldsm_x4(bf0, ka);
            ldsm_x4(bf1, ka + 32);
            float* a0 = acc[2 * np];
            float* a1 = acc[2 * np + 1];
            a0[0] = a0[1] = a0[2] = a0[3] = 0.f;
            a1[0] = a1[1] = a1[2] = a1[3] = 0.f;
            mma_f16(a0, aq[0], &bf0[0]);
            mma_f16(a0, aq[1], &bf1[0]);
            mma_f16(a1, aq[0], &bf0[2]);
            mma_f16(a1, aq[1], &bf1[2]);
        }

        // bias + mask + row max
        const bool r0v = row0 < Nt, r1v = row1 < Nt;
        float m0 = -1e30f, m1 = -1e30f;
#pragma unroll
        for (int nt = 0; nt < 26; nt++) {
            int col = nt * 8 + tig * 2;
            bool cv = col < Nt;
            float2 b0 = (cv && r0v) ? *(const float2*)(bias_h + (size_t)row0 * Nt + col)
                                    : make_float2(0.f, 0.f);
            float2 b1 = (cv && r1v) ? *(const float2*)(bias_h + (size_t)row1 * Nt + col)
                                    : make_float2(0.f, 0.f);
            acc[nt][0] = cv ? acc[nt][0] + b0.x : -1e30f;
            acc[nt][1] = cv ? acc[nt][1] + b0.y : -1e30f;
            acc[nt][2] = cv ? acc[nt][2] + b1.x : -1e30f;
            acc[nt][3] = cv ? acc[nt][3] + b1.y : -1e30f;
            m0 = fmaxf(m0, fmaxf(acc[nt][0], acc[nt][1]));
            m1 = fmaxf(m1, fmaxf(acc[nt][2], acc[nt][3]));
        }
        m0 = fmaxf(m0, __shfl_xor_sync(0xffffffffu, m0, 1));
        m0 = fmaxf(m0, __shfl_xor_sync(0xffffffffu, m0, 2));
        m1 = fmaxf(m1, __shfl_xor_sync(0xffffffffu, m1, 1));
        m1 = fmaxf(m1, __shfl_xor_sync(0xffffffffu, m1, 2));

        // exp + row sums
        float l0 = 0.f, l1 = 0.f;
#pragma unroll
        for (int nt = 0; nt < 26; nt++) {
            acc[nt][0] = __expf(acc[nt][0] - m0); l0 += acc[nt][0];
            acc[nt][1] = __expf(acc[nt][1] - m0); l0 += acc[nt][1];
            acc[nt][2] = __expf(acc[nt][2] - m1); l1 += acc[nt][2];
            acc[nt][3] = __expf(acc[nt][3] - m1); l1 += acc[nt][3];
        }
        l0 += __shfl_xor_sync(0xffffffffu, l0, 1);
        l0 += __shfl_xor_sync(0xffffffffu, l0, 2);
        l1 += __shfl_xor_sync(0xffffffffu, l1, 1);
        l1 += __shfl_xor_sync(0xffffffffu, l1, 2);

        // O = P @ V : P A-frags directly from S C-frags (no shuffles)
        float oacc[4][4];
#pragma unroll
        for (int nt = 0; nt < 4; nt++)
            oacc[nt][0] = oacc[nt][1] = oacc[nt][2] = oacc[nt][3] = 0.f;

#pragma unroll
        for (int kk = 0; kk < 13; kk++) {
            uint32_t pa[4];
            pa[0] = h2u(__floats2half2_rn(acc[2*kk  ][0], acc[2*kk  ][1]));
            pa[1] = h2u(__floats2half2_rn(acc[2*kk  ][2], acc[2*kk  ][3]));
            pa[2] = h2u(__floats2half2_rn(acc[2*kk+1][0], acc[2*kk+1][1]));
            pa[3] = h2u(__floats2half2_rn(acc[2*kk+1][2], acc[2*kk+1][3]));
            uint32_t vb0[4], vb1[4];
            uint32_t va = vaddr0 + (uint32_t)(kk * 16 * AQ_STR * 2);
            ldsm_x4_t(vb0, va);        // d 0..15
            ldsm_x4_t(vb1, va + 32);   // d 16..31
            mma_f16(oacc[0], pa, &vb0[0]);
            mma_f16(oacc[1], pa, &vb0[2]);
            mma_f16(oacc[2], pa, &vb1[0]);
            mma_f16(oacc[3], pa, &vb1[2]);
        }

        const float inv0 = 1.f / l0, inv1 = 1.f / l1;
        if (r0v) {
            __half* op = g_attno + ((size_t)(w * Nt + row0)) * DH + h * KD;
#pragma unroll
            for (int nt = 0; nt < 4; nt++)
                *(__half2*)(op + nt * 8 + tig * 2) =
                    __floats2half2_rn(oacc[nt][0] * inv0, oacc[nt][1] * inv0);
        }
        if (r1v) {
            __half* op = g_attno + ((size_t)(w * Nt + row1)) * DH + h * KD;
#pragma unroll
            for (int nt = 0; nt < 4; nt++)
                *(__half2*)(op + nt * 8 + tig * 2) =
                    __floats2half2_rn(oacc[nt][2] * inv1, oacc[nt][3] * inv1);
        }
    }
}

// ---------------- depthwise 3x3 conv + BN ----------------
__global__ void k_conv_bn(const float* __restrict__ cw,
                          const float* __restrict__ bnw,
                          const float* __restrict__ bnb,
                          const float* __restrict__ bnm,
                          const float* __restrict__ bnv) {
    int idx = blockIdx.x * blockDim.x + threadIdx.x;
    const int C4 = Cc / 4;
    const int total = B_ * Hh * Ww * C4;
    if (idx >= total) return;
    int c4 = idx % C4;
    int x  = (idx / C4) % Ww;
    int y  = (idx / (C4 * Ww)) % Hh;
    int b  = idx / (C4 * Ww * Hh);
    int c0 = c4 * 4;

    float4 acc = make_float4(0.f, 0.f, 0.f, 0.f);
#pragma unroll
    for (int ky = 0; ky < 3; ky++) {
        int yy = y + ky - 1;
        if (yy < 0 || yy >= Hh) continue;
#pragma unroll
        for (int kx = 0; kx < 3; kx++) {
            int xx = x + kx - 1;
            if (xx < 0 || xx >= Ww) continue;
            float4 in = *(const float4*)&g_x1[((size_t)b * L_ + (size_t)yy * Ww + xx) * Cc + c0];
            int wo = ky * 3 + kx;
            acc.x += in.x * cw[(c0 + 0) * 9 + wo];
            acc.y += in.y * cw[(c0 + 1) * 9 + wo];
            acc.z += in.z * cw[(c0 + 2) * 9 + wo];
            acc.w += in.w * cw[(c0 + 3) * 9 + wo];
        }
    }
    float4 outv;
    outv.x = (acc.x - bnm[c0 + 0]) * (rsqrtf(bnv[c0 + 0] + 1e-5f) * bnw[c0 + 0]) + bnb[c0 + 0];
    outv.y = (acc.y - bnm[c0 + 1]) * (rsqrtf(bnv[c0 + 1] + 1e-5f) * bnw[c0 + 1]) + bnb[c0 + 1];
    outv.z = (acc.z - bnm[c0 + 2]) * (rsqrtf(bnv[c0 + 2] + 1e-5f) * bnw[c0 + 2]) + bnb[c0 + 2];
    outv.w = (acc.w - bnm[c0 + 3]) * (rsqrtf(bnv[c0 + 3] + 1e-5f) * bnw[c0 + 3]) + bnb[c0 + 3];
    *(float4*)&g_x2[(size_t)idx * 4] = outv;
}

// ---------------- launcher ----------------
extern "C" void kernel_launch(void* const* d_in, const int* in_sizes, int n_in,
                              void* d_out, int out_size) {
    const float* x        = (const float*)d_in[0];
    const float* ln_aw    = (const float*)d_in[1];
    const float* ln_ab    = (const float*)d_in[2];
    const float* qkv_w    = (const float*)d_in[3];
    const float* qkv_b    = (const float*)d_in[4];
    const float* proj_w   = (const float*)d_in[5];
    const float* proj_b   = (const float*)d_in[6];
    const float* attn_bia = (const float*)d_in[7];
    const float* conv_w   = (const float*)d_in[8];
    const float* bn_w     = (const float*)d_in[9];
    const float* bn_b     = (const float*)d_in[10];
    const float* bn_m     = (const float*)d_in[11];
    const float* bn_v     = (const float*)d_in[12];
    const float* ln_mw    = (const float*)d_in[13];
    const float* ln_mb    = (const float*)d_in[14];
    const float* fc1_w    = (const float*)d_in[15];
    const float* fc1_b    = (const float*)d_in[16];
    const float* fc2_w    = (const float*)d_in[17];
    const float* fc2_b    = (const float*)d_in[18];
    const int*   bias_idx = (const int*)d_in[19];
    float* out = (float*)d_out;

    int n_off = in_sizes[7] / HEADS;

    cudaFuncSetAttribute(k_gemm_qkv,  cudaFuncAttributeMaxDynamicSharedMemorySize, SMEM_GEMM);
    cudaFuncSetAttribute(k_gemm_proj, cudaFuncAttributeMaxDynamicSharedMemorySize, SMEM_GEMM);
    cudaFuncSetAttribute(k_gemm_fc1,  cudaFuncAttributeMaxDynamicSharedMemorySize, SMEM_GEMM);
    cudaFuncSetAttribute(k_gemm_fc2,  cudaFuncAttributeMaxDynamicSharedMemorySize, SMEM_GEMM);
    cudaFuncSetAttribute(k_attn,      cudaFuncAttributeMaxDynamicSharedMemorySize, SMEM_ATTN);

    {
        int n0 = QKVW * Cc / 4, n1 = Cc * DH / 4, n2 = HID * Cc / 4, n3 = Cc * HID / 4;
        int tot = n0 + n1 + n2 + n3;
        k_half_all<<<(tot + 255) / 256, 256>>>((const float4*)qkv_w, n0,
                                               (const float4*)proj_w, n1,
                                               (const float4*)fc1_w, n2,
                                               (const float4*)fc2_w, n3);
    }
    {
        int tot = HEADS * Nt * Nt;
        k_bias_expand<<<(tot + 255) / 256, 256>>>(attn_bia, bias_idx, n_off);
    }
    k_win_ln<<<M_ATT / 8, 256>>>(x, ln_aw, ln_ab);
    k_gemm_qkv<<<dim3(QKVW / 128, (M_ATT + 127) / 128), 512, SMEM_GEMM>>>(qkv_b);
    k_attn<<<NW * HEADS, 256, SMEM_ATTN>>>();
    k_gemm_proj<<<dim3(Cc / 128, (M_ATT + 127) / 128), 512, SMEM_GEMM>>>(proj_b, x);
    {
        int tot = B_ * Hh * Ww * (Cc / 4);
        k_conv_bn<<<(tot + 255) / 256, 256>>>(conv_w, bn_w, bn_b, bn_m, bn_v);
    }
    k_ln_mlp<<<M_MLP / 8, 256>>>(ln_mw, ln_mb);
    k_gemm_fc1<<<dim3(HID / 128, M_MLP / 128), 512, SMEM_GEMM>>>(fc1_b);
    k_gemm_fc2<<<dim3(Cc / 128, M_MLP / 128), 512, SMEM_GEMM>>>(fc2_b, out);
}

// round 11
// speedup vs baseline: 4.3608x; 1.0375x over previous
#include <cuda_runtime.h>
#include <cuda_fp16.h>
#include <math.h>
#include <stdint.h>

// ---------------- problem constants ----------------
#define B_      8
#define Hh      64
#define Ww      64
#define Cc      384
#define HEADS   12
#define WSs     14
#define KD      32
#define Nt      196
#define NW      200
#define M_ATT   39200
#define L_      4096
#define M_MLP   32768
#define HID     1536
#define DH      384
#define QKVW    1152
#define SCALE_F 0.17677669529663687f
#define EPS_F   1e-5f

// attention tiling: fp16 smem, 208 rows x 40-half stride, q/k/v
#define NTP        208
#define AQ_STR     40
#define SMEM_ATTN  (3 * NTP * AQ_STR * 2)

// fp16 gemm smem: 3 stages x (A[128][40] + B[128][40]) halfs
#define GST_BYTES   20480
#define SMEM_GEMM   (3 * GST_BYTES)

// ---------------- scratch ----------------
__device__ __align__(16) __half g_xn[M_ATT * Cc];
__device__ __align__(16) __half g_qkv[(size_t)M_ATT * QKVW];   // fp16 now, q pre-scaled
__device__ __align__(16) __half g_attno[M_ATT * Cc];
__device__ float  g_x1[M_MLP * Cc];
__device__ float  g_x2[M_MLP * Cc];
__device__ __align__(16) __half g_h1[(size_t)M_MLP * HID];
__device__ float  g_bias[HEADS * Nt * Nt];
__device__ __align__(16) __half g_wq[QKVW * Cc];
__device__ __align__(16) __half g_wp[Cc * DH];
__device__ __align__(16) __half g_w1[HID * Cc];
__device__ __align__(16) __half g_w2[Cc * HID];

// ---------------- helpers ----------------
__device__ __forceinline__ void mma_f16(float* c, const uint32_t* a, const uint32_t* b) {
    asm volatile(
        "mma.sync.aligned.m16n8k16.row.col.f32.f16.f16.f32 "
        "{%0,%1,%2,%3}, {%4,%5,%6,%7}, {%8,%9}, {%0,%1,%2,%3};\n"
        : "+f"(c[0]), "+f"(c[1]), "+f"(c[2]), "+f"(c[3])
        : "r"(a[0]), "r"(a[1]), "r"(a[2]), "r"(a[3]), "r"(b[0]), "r"(b[1]));
}

__device__ __forceinline__ void ldsm_x4(uint32_t* r, uint32_t saddr) {
    asm volatile("ldmatrix.sync.aligned.m8n8.x4.shared.b16 {%0,%1,%2,%3}, [%4];"
                 : "=r"(r[0]), "=r"(r[1]), "=r"(r[2]), "=r"(r[3]) : "r"(saddr));
}

__device__ __forceinline__ void ldsm_x4_t(uint32_t* r, uint32_t saddr) {
    asm volatile("ldmatrix.sync.aligned.m8n8.x4.trans.shared.b16 {%0,%1,%2,%3}, [%4];"
                 : "=r"(r[0]), "=r"(r[1]), "=r"(r[2]), "=r"(r[3]) : "r"(saddr));
}

__device__ __forceinline__ void cp_async16(uint32_t saddr, const void* gptr, int srcbytes) {
    asm volatile("cp.async.cg.shared.global [%0], [%1], 16, %2;\n"
                 :: "r"(saddr), "l"(gptr), "r"(srcbytes));
}

__device__ __forceinline__ uint32_t smem_u32(const void* p) {
    uint32_t a;
    asm("{ .reg .u64 t; cvta.to.shared.u64 t, %1; cvt.u32.u64 %0, t; }" : "=r"(a) : "l"(p));
    return a;
}

__device__ __forceinline__ uint32_t h2u(__half2 h) {
    return *(uint32_t*)&h;
}

// ---------------- weight conversion fp32 -> fp16 ----------------
__global__ void k_half_all(const float4* __restrict__ s0, int n0,
                           const float4* __restrict__ s1, int n1,
                           const float4* __restrict__ s2, int n2,
                           const float4* __restrict__ s3, int n3) {
    int i = blockIdx.x * blockDim.x + threadIdx.x;
    const float4* src; __half* dst; int j = i;
    if (j < n0) { src = s0; dst = g_wq; }
    else if ((j -= n0) < n1) { src = s1; dst = g_wp; }
    else if ((j -= n1) < n2) { src = s2; dst = g_w1; }
    else if ((j -= n2) < n3) { src = s3; dst = g_w2; }
    else return;
    float4 v = src[j];
    __half2* d2 = (__half2*)(dst + 4 * (size_t)j);
    d2[0] = __floats2half2_rn(v.x, v.y);
    d2[1] = __floats2half2_rn(v.z, v.w);
}

// ---------------- kernel: expand bias table ----------------
__global__ void k_bias_expand(const float* __restrict__ ab,
                              const int* __restrict__ bidx, int n_off) {
    int i = blockIdx.x * blockDim.x + threadIdx.x;
    if (i >= HEADS * Nt * Nt) return;
    int h  = i / (Nt * Nt);
    int ij = i - h * (Nt * Nt);
    g_bias[i] = ab[h * n_off + bidx[ij]];
}

// ---------------- kernel: window partition + LayerNorm (fp16 out) ---------
__global__ void k_win_ln(const float* __restrict__ x,
                         const float* __restrict__ w,
                         const float* __restrict__ b) {
    int warp = (blockIdx.x * blockDim.x + threadIdx.x) >> 5;
    int lane = threadIdx.x & 31;
    if (warp >= M_ATT) return;
    int wi = warp / Nt, t = warp - wi * Nt;
    int bb = wi / 25; int rem = wi - bb * 25;
    int wy = rem / 5, wx = rem - wy * 5;
    int ty = t / WSs, tx = t - ty * WSs;
    int gy = wy * WSs + ty, gx = wx * WSs + tx;
    bool valid = (gy < Hh) && (gx < Ww);
    const float* src = x + ((size_t)bb * L_ + (size_t)gy * Ww + gx) * Cc;

    float vals[12];
    float s = 0.f, s2 = 0.f;
#pragma unroll
    for (int i = 0; i < 12; i++) {
        float v = valid ? src[lane + i * 32] : 0.f;
        vals[i] = v; s += v; s2 += v * v;
    }
#pragma unroll
    for (int o = 16; o > 0; o >>= 1) {
        s  += __shfl_xor_sync(0xffffffffu, s,  o);
        s2 += __shfl_xor_sync(0xffffffffu, s2, o);
    }
    float mean = s * (1.f / Cc);
    float var  = s2 * (1.f / Cc) - mean * mean;
    float rstd = rsqrtf(var + EPS_F);
    __half* dst = g_xn + (size_t)warp * Cc;
#pragma unroll
    for (int i = 0; i < 12; i++) {
        int c = lane + i * 32;
        dst[c] = __float2half((vals[i] - mean) * rstd * w[c] + b[c]);
    }
}

// ---------------- kernel: MLP LayerNorm (fp16 out) ----------------
__global__ void k_ln_mlp(const float* __restrict__ w,
                         const float* __restrict__ b) {
    int warp = (blockIdx.x * blockDim.x + threadIdx.x) >> 5;
    int lane = threadIdx.x & 31;
    if (warp >= M_MLP) return;
    const float* src = g_x2 + (size_t)warp * Cc;
    float vals[12];
    float s = 0.f, s2 = 0.f;
#pragma unroll
    for (int i = 0; i < 12; i++) {
        float v = src[lane + i * 32];
        vals[i] = v; s += v; s2 += v * v;
    }
#pragma unroll
    for (int o = 16; o > 0; o >>= 1) {
        s  += __shfl_xor_sync(0xffffffffu, s,  o);
        s2 += __shfl_xor_sync(0xffffffffu, s2, o);
    }
    float mean = s * (1.f / Cc);
    float var  = s2 * (1.f / Cc) - mean * mean;
    float rstd = rsqrtf(var + EPS_F);
    __half* dst = g_xn + (size_t)warp * Cc;
#pragma unroll
    for (int i = 0; i < 12; i++) {
        int c = lane + i * 32;
        dst[c] = __float2half((vals[i] - mean) * rstd * w[c] + b[c]);
    }
}

// ---------------- fp16 GEMM (mainloop unchanged) ----------------
// EPI: 0 = qkv fp16 out with q-scale, 1 = GELU fp16 out,
//      2 = proj un-window+residual, 3 = residual add
template <int EPI, int M, int Nn, int K>
__device__ __forceinline__ void gemm_f16_body(const __half* __restrict__ A,
                                              const __half* __restrict__ Bw,
                                              const float* __restrict__ bias,
                                              float* __restrict__ Cout,
                                              const float* __restrict__ res) {
    extern __shared__ __align__(16) char smraw[];
    const int tid = threadIdx.x, lane = tid & 31, wid = tid >> 5;
    const int g = lane >> 2, tig = lane & 3;
    const int warp_m = wid >> 2, warp_n = wid & 3;
    const int bm = blockIdx.y * 128, bn = blockIdx.x * 128;
    const int arow = tid >> 2, seg = tid & 3;

    const int r0 = bm + arow;
    const bool v0 = ((M % 128) == 0) || (r0 < M);
    const int sz0 = v0 ? 16 : 0;
    const __half* a0b = A  + (size_t)(v0 ? r0 : 0) * K + seg * 8;
    const __half* b0b = Bw + (size_t)(bn + arow) * K + seg * 8;
    const uint32_t smb = smem_u32(smraw);
    const uint32_t sa0 = smb + arow * 80 + seg * 16;
    const uint32_t sb0 = sa0 + 10240;

    const int a_row = (lane & 15), a_k = 8 * (lane >> 4);
    const int b_row = (lane >> 4) * 8 + (lane & 7), b_k = 8 * ((lane >> 3) & 1);
    const uint32_t aA = smb + ((warp_m * 32 + a_row) * 40 + a_k) * 2;
    const uint32_t aB = smb + 10240 + ((warp_n * 32 + b_row) * 40 + b_k) * 2;

    const int KT = K / 32;
    auto load_stage = [&](int s, int kt) {
        int kc = kt * 32;
        uint32_t so = (uint32_t)(s * GST_BYTES);
        cp_async16(sa0 + so, a0b + kc, sz0);
        cp_async16(sb0 + so, b0b + kc, 16);
        asm volatile("cp.async.commit_group;\n");
    };

    float acc[2][4][4];
#pragma unroll
    for (int mt = 0; mt < 2; mt++)
#pragma unroll
        for (int nt = 0; nt < 4; nt++)
#pragma unroll
            for (int r = 0; r < 4; r++) acc[mt][nt][r] = 0.f;

    load_stage(0, 0);
    load_stage(1, 1);

    for (int kt = 0; kt < KT; kt++) {
        if (kt + 1 < KT) {
            asm volatile("cp.async.wait_group 1;\n");
        } else {
            asm volatile("cp.async.wait_group 0;\n");
        }
        __syncthreads();
        if (kt + 2 < KT) load_stage((kt + 2) % 3, kt + 2);

        const uint32_t st = (uint32_t)((kt % 3) * GST_BYTES);
#pragma unroll
        for (int ks = 0; ks < 2; ks++) {
            const int kb = ks * 16;
            uint32_t afr[2][4], bfr2[2][4];
            ldsm_x4(afr[0], aA + st + kb * 2);
            ldsm_x4(afr[1], aA + st + (16 * 40 + kb) * 2);
            ldsm_x4(bfr2[0], aB + st + kb * 2);
            ldsm_x4(bfr2[1], aB + st + (16 * 40 + kb) * 2);
#pragma unroll
            for (int mt = 0; mt < 2; mt++) {
                mma_f16(acc[mt][0], afr[mt], &bfr2[0][0]);
                mma_f16(acc[mt][1], afr[mt], &bfr2[0][2]);
                mma_f16(acc[mt][2], afr[mt], &bfr2[1][0]);
                mma_f16(acc[mt][3], afr[mt], &bfr2[1][2]);
            }
        }
    }

#pragma unroll
    for (int mt = 0; mt < 2; mt++) {
#pragma unroll
        for (int nt = 0; nt < 4; nt++) {
#pragma unroll
            for (int r = 0; r < 4; r++) {
                int m  = bm + warp_m * 32 + mt * 16 + g + ((r >> 1) ? 8 : 0);
                int nn = bn + warp_n * 32 + nt * 8 + tig * 2 + (r & 1);
                if (((M % 128) != 0) && (m >= M)) continue;
                float v = acc[mt][nt][r] + bias[nn];
                if (EPI == 0) {
                    // qkv: fp16 out, fold q*SCALE (cols nn%96 < 32 are q)
                    float sc = ((nn % 96) < 32) ? SCALE_F : 1.f;
                    ((__half*)Cout)[(size_t)m * Nn + nn] = __float2half(v * sc);
                } else if (EPI == 1) {
                    ((__half*)Cout)[(size_t)m * Nn + nn] =
                        __float2half(0.5f * v * (1.f + erff(v * 0.70710678118654752f)));
                } else if (EPI == 2) {
                    int wi = m / Nt, t = m - wi * Nt;
                    int bb2 = wi / 25; int rem = wi - bb2 * 25;
                    int wy = rem / 5, wx = rem - wy * 5;
                    int ty = t / WSs, tx = t - ty * WSs;
                    int gy = wy * WSs + ty, gx = wx * WSs + tx;
                    if (gy < Hh && gx < Ww) {
                        size_t o = ((size_t)bb2 * L_ + (size_t)gy * Ww + gx) * Cc + nn;
                        Cout[o] = res[o] + v;
                    }
                } else {
                    size_t o = (size_t)m * Nn + nn;
                    Cout[o] = v + res[o];
                }
            }
        }
    }
}

__global__ __launch_bounds__(512, 2) void k_gemm_qkv(const float* __restrict__ b) {
    gemm_f16_body<0, M_ATT, QKVW, Cc>(g_xn, g_wq, b, (float*)g_qkv, nullptr);
}
__global__ __launch_bounds__(512, 2) void k_gemm_proj(const float* __restrict__ b,
                                                      const float* __restrict__ x) {
    gemm_f16_body<2, M_ATT, Cc, DH>(g_attno, g_wp, b, g_x1, x);
}
__global__ __launch_bounds__(512, 2) void k_gemm_fc1(const float* __restrict__ b) {
    gemm_f16_body<1, M_MLP, HID, Cc>(g_xn, g_w1, b, (float*)g_h1, nullptr);
}
__global__ __launch_bounds__(512, 2) void k_gemm_fc2(const float* __restrict__ b,
                                                     float* __restrict__ out) {
    gemm_f16_body<3, M_MLP, Cc, HID>(g_h1, g_w2, b, out, g_x2);
}

// ---------------- attention chunk step (online softmax) ----------------
template <int NTILES>
__device__ __forceinline__ void attn_chunk(
    int colbase, uint32_t smb, const uint32_t (&aq)[2][4],
    const float* __restrict__ bias_h, int row0, int row1, bool r0v, bool r1v,
    int lane, uint32_t vaddr0,
    float& m0, float& m1, float& l0, float& l1, float (&oacc)[4][4])
{
    const int tig = lane & 3;
    const int b_row = (lane >> 4) * 8 + (lane & 7), b_k = 8 * ((lane >> 3) & 1);

    float acc[NTILES][4];
#pragma unroll
    for (int np = 0; np < NTILES / 2; np++) {
        uint32_t ka = smb + (uint32_t)(NTP * AQ_STR * 2) +
                      ((colbase + np * 16 + b_row) * AQ_STR + b_k) * 2;
        uint32_t bf0[4], bf1[4];
        ldsm_x4(bf0, ka);
        ldsm_x4(bf1, ka + 32);
        float* a0 = acc[2 * np];
        float* a1 = acc[2 * np + 1];
        a0[0] = a0[1] = a0[2] = a0[3] = 0.f;
        a1[0] = a1[1] = a1[2] = a1[3] = 0.f;
        mma_f16(a0, aq[0], &bf0[0]);
        mma_f16(a0, aq[1], &bf1[0]);
        mma_f16(a1, aq[0], &bf0[2]);
        mma_f16(a1, aq[1], &bf1[2]);
    }

    // bias + mask + chunk max
    float cm0 = -1e30f, cm1 = -1e30f;
#pragma unroll
    for (int nt = 0; nt < NTILES; nt++) {
        int col = colbase + nt * 8 + tig * 2;
        bool cv = col < Nt;
        float2 b0 = (cv && r0v) ? *(const float2*)(bias_h + (size_t)row0 * Nt + col)
                                : make_float2(0.f, 0.f);
        float2 b1 = (cv && r1v) ? *(const float2*)(bias_h + (size_t)row1 * Nt + col)
                                : make_float2(0.f, 0.f);
        acc[nt][0] = cv ? acc[nt][0] + b0.x : -1e30f;
        acc[nt][1] = cv ? acc[nt][1] + b0.y : -1e30f;
        acc[nt][2] = cv ? acc[nt][2] + b1.x : -1e30f;
        acc[nt][3] = cv ? acc[nt][3] + b1.y : -1e30f;
        cm0 = fmaxf(cm0, fmaxf(acc[nt][0], acc[nt][1]));
        cm1 = fmaxf(cm1, fmaxf(acc[nt][2], acc[nt][3]));
    }
    cm0 = fmaxf(cm0, __shfl_xor_sync(0xffffffffu, cm0, 1));
    cm0 = fmaxf(cm0, __shfl_xor_sync(0xffffffffu, cm0, 2));
    cm1 = fmaxf(cm1, __shfl_xor_sync(0xffffffffu, cm1, 1));
    cm1 = fmaxf(cm1, __shfl_xor_sync(0xffffffffu, cm1, 2));

    float mn0 = fmaxf(m0, cm0), mn1 = fmaxf(m1, cm1);
    float c0 = __expf(m0 - mn0), c1 = __expf(m1 - mn1);

    float s0 = 0.f, s1 = 0.f;
#pragma unroll
    for (int nt = 0; nt < NTILES; nt++) {
        acc[nt][0] = __expf(acc[nt][0] - mn0); s0 += acc[nt][0];
        acc[nt][1] = __expf(acc[nt][1] - mn0); s0 += acc[nt][1];
        acc[nt][2] = __expf(acc[nt][2] - mn1); s1 += acc[nt][2];
        acc[nt][3] = __expf(acc[nt][3] - mn1); s1 += acc[nt][3];
    }
    s0 += __shfl_xor_sync(0xffffffffu, s0, 1);
    s0 += __shfl_xor_sync(0xffffffffu, s0, 2);
    s1 += __shfl_xor_sync(0xffffffffu, s1, 1);
    s1 += __shfl_xor_sync(0xffffffffu, s1, 2);
    l0 = l0 * c0 + s0;
    l1 = l1 * c1 + s1;
    m0 = mn0; m1 = mn1;

#pragma unroll
    for (int nt = 0; nt < 4; nt++) {
        oacc[nt][0] *= c0; oacc[nt][1] *= c0;
        oacc[nt][2] *= c1; oacc[nt][3] *= c1;
    }

    // O += P @ V  (P A-frags directly from S C-frags)
#pragma unroll
    for (int kk = 0; kk < NTILES / 2; kk++) {
        uint32_t pa[4];
        pa[0] = h2u(__floats2half2_rn(acc[2*kk  ][0], acc[2*kk  ][1]));
        pa[1] = h2u(__floats2half2_rn(acc[2*kk  ][2], acc[2*kk  ][3]));
        pa[2] = h2u(__floats2half2_rn(acc[2*kk+1][0], acc[2*kk+1][1]));
        pa[3] = h2u(__floats2half2_rn(acc[2*kk+1][2], acc[2*kk+1][3]));
        uint32_t vb0[4], vb1[4];
        uint32_t va = vaddr0 + (uint32_t)((colbase + kk * 16) * AQ_STR * 2);
        ldsm_x4_t(vb0, va);
        ldsm_x4_t(vb1, va + 32);
        mma_f16(oacc[0], pa, &vb0[0]);
        mma_f16(oacc[1], pa, &vb0[2]);
        mma_f16(oacc[2], pa, &vb1[0]);
        mma_f16(oacc[3], pa, &vb1[2]);
    }
}

// ---------------- fp16 tensor-core attention, 2-chunk online softmax ------
__global__ __launch_bounds__(256, 2) void k_attn() {
    extern __shared__ __align__(16) __half smh[];
    __half* qs = smh;                       // [208][40] q (pre-scaled)
    __half* ks = smh + NTP * AQ_STR;        // [208][40]
    __half* vs = smh + 2 * NTP * AQ_STR;    // [208][40]

    const int blk = blockIdx.x;
    const int w = blk / HEADS, h = blk - w * HEADS;
    const __half* base = g_qkv + (size_t)w * Nt * QKVW + h * 96;
    const int tid = threadIdx.x, lane = tid & 31, wid = tid >> 5;
    const int g = lane >> 2, tig = lane & 3;
    const uint32_t smb = smem_u32(smh);

    // stage: fp16 qkv -> smem (16B copies; zero pad rows >= 196)
    for (int idx = tid; idx < NTP * 4; idx += 256) {
        int r = idx >> 2, d8 = (idx & 3) * 8;
        uint4 q4, k4, v4;
        if (r < Nt) {
            const __half* rp = base + (size_t)r * QKVW;
            q4 = *(const uint4*)(rp + d8);
            k4 = *(const uint4*)(rp + 32 + d8);
            v4 = *(const uint4*)(rp + 64 + d8);
        } else {
            q4 = k4 = v4 = make_uint4(0, 0, 0, 0);
        }
        *(uint4*)(qs + r * AQ_STR + d8) = q4;
        *(uint4*)(ks + r * AQ_STR + d8) = k4;
        *(uint4*)(vs + r * AQ_STR + d8) = v4;
    }
    __syncthreads();

    const float* bias_h = g_bias + (size_t)h * Nt * Nt;

    const int a_row = (lane & 15), a_k = 8 * (lane >> 4);
    const uint32_t vs_off = (uint32_t)(2 * NTP * AQ_STR * 2);
    const uint32_t vaddr0 = smb + vs_off + (((lane & 15)) * AQ_STR + 8 * (lane >> 4)) * 2;

    for (int tt = wid; tt < 13; tt += 8) {
        const int row0 = tt * 16 + g, row1 = row0 + 8;
        const bool r0v = row0 < Nt, r1v = row1 < Nt;

        uint32_t aq[2][4];
        {
            uint32_t qa = smb + ((tt * 16 + a_row) * AQ_STR + a_k) * 2;
            ldsm_x4(aq[0], qa);
            ldsm_x4(aq[1], qa + 32);
        }

        float m0 = -1e30f, m1 = -1e30f, l0 = 0.f, l1 = 0.f;
        float oacc[4][4];
#pragma unroll
        for (int nt = 0; nt < 4; nt++)
            oacc[nt][0] = oacc[nt][1] = oacc[nt][2] = oacc[nt][3] = 0.f;

        attn_chunk<14>(0,   smb, aq, bias_h, row0, row1, r0v, r1v, lane, vaddr0,
                       m0, m1, l0, l1, oacc);
        attn_chunk<12>(112, smb, aq, bias_h, row0, row1, r0v, r1v, lane, vaddr0,
                       m0, m1, l0, l1, oacc);

        const float inv0 = 1.f / l0, inv1 = 1.f / l1;
        if (r0v) {
            __half* op = g_attno + ((size_t)(w * Nt + row0)) * DH + h * KD;
#pragma unroll
            for (int nt = 0; nt < 4; nt++)
                *(__half2*)(op + nt * 8 + tig * 2) =
                    __floats2half2_rn(oacc[nt][0] * inv0, oacc[nt][1] * inv0);
        }
        if (r1v) {
            __half* op = g_attno + ((size_t)(w * Nt + row1)) * DH + h * KD;
#pragma unroll
            for (int nt = 0; nt < 4; nt++)
                *(__half2*)(op + nt * 8 + tig * 2) =
                    __floats2half2_rn(oacc[nt][2] * inv1, oacc[nt][3] * inv1);
        }
    }
}

// ---------------- depthwise 3x3 conv + BN ----------------
__global__ void k_conv_bn(const float* __restrict__ cw,
                          const float* __restrict__ bnw,
                          const float* __restrict__ bnb,
                          const float* __restrict__ bnm,
                          const float* __restrict__ bnv) {
    int idx = blockIdx.x * blockDim.x + threadIdx.x;
    const int C4 = Cc / 4;
    const int total = B_ * Hh * Ww * C4;
    if (idx >= total) return;
    int c4 = idx % C4;
    int x  = (idx / C4) % Ww;
    int y  = (idx / (C4 * Ww)) % Hh;
    int b  = idx / (C4 * Ww * Hh);
    int c0 = c4 * 4;

    float4 acc = make_float4(0.f, 0.f, 0.f, 0.f);
#pragma unroll
    for (int ky = 0; ky < 3; ky++) {
        int yy = y + ky - 1;
        if (yy < 0 || yy >= Hh) continue;
#pragma unroll
        for (int kx = 0; kx < 3; kx++) {
            int xx = x + kx - 1;
            if (xx < 0 || xx >= Ww) continue;
            float4 in = *(const float4*)&g_x1[((size_t)b * L_ + (size_t)yy * Ww + xx) * Cc + c0];
            int wo = ky * 3 + kx;
            acc.x += in.x * cw[(c0 + 0) * 9 + wo];
            acc.y += in.y * cw[(c0 + 1) * 9 + wo];
            acc.z += in.z * cw[(c0 + 2) * 9 + wo];
            acc.w += in.w * cw[(c0 + 3) * 9 + wo];
        }
    }
    float4 outv;
    outv.x = (acc.x - bnm[c0 + 0]) * (rsqrtf(bnv[c0 + 0] + 1e-5f) * bnw[c0 + 0]) + bnb[c0 + 0];
    outv.y = (acc.y - bnm[c0 + 1]) * (rsqrtf(bnv[c0 + 1] + 1e-5f) * bnw[c0 + 1]) + bnb[c0 + 1];
    outv.z = (acc.z - bnm[c0 + 2]) * (rsqrtf(bnv[c0 + 2] + 1e-5f) * bnw[c0 + 2]) + bnb[c0 + 2];
    outv.w = (acc.w - bnm[c0 + 3]) * (rsqrtf(bnv[c0 + 3] + 1e-5f) * bnw[c0 + 3]) + bnb[c0 + 3];
    *(float4*)&g_x2[(size_t)idx * 4] = outv;
}

// ---------------- launcher ----------------
extern "C" void kernel_launch(void* const* d_in, const int* in_sizes, int n_in,
                              void* d_out, int out_size) {
    const float* x        = (const float*)d_in[0];
    const float* ln_aw    = (const float*)d_in[1];
    const float* ln_ab    = (const float*)d_in[2];
    const float* qkv_w    = (const float*)d_in[3];
    const float* qkv_b    = (const float*)d_in[4];
    const float* proj_w   = (const float*)d_in[5];
    const float* proj_b   = (const float*)d_in[6];
    const float* attn_bia = (const float*)d_in[7];
    const float* conv_w   = (const float*)d_in[8];
    const float* bn_w     = (const float*)d_in[9];
    const float* bn_b     = (const float*)d_in[10];
    const float* bn_m     = (const float*)d_in[11];
    const float* bn_v     = (const float*)d_in[12];
    const float* ln_mw    = (const float*)d_in[13];
    const float* ln_mb    = (const float*)d_in[14];
    const float* fc1_w    = (const float*)d_in[15];
    const float* fc1_b    = (const float*)d_in[16];
    const float* fc2_w    = (const float*)d_in[17];
    const float* fc2_b    = (const float*)d_in[18];
    const int*   bias_idx = (const int*)d_in[19];
    float* out = (float*)d_out;

    int n_off = in_sizes[7] / HEADS;

    cudaFuncSetAttribute(k_gemm_qkv,  cudaFuncAttributeMaxDynamicSharedMemorySize, SMEM_GEMM);
    cudaFuncSetAttribute(k_gemm_proj, cudaFuncAttributeMaxDynamicSharedMemorySize, SMEM_GEMM);
    cudaFuncSetAttribute(k_gemm_fc1,  cudaFuncAttributeMaxDynamicSharedMemorySize, SMEM_GEMM);
    cudaFuncSetAttribute(k_gemm_fc2,  cudaFuncAttributeMaxDynamicSharedMemorySize, SMEM_GEMM);
    cudaFuncSetAttribute(k_attn,      cudaFuncAttributeMaxDynamicSharedMemorySize, SMEM_ATTN);

    {
        int n0 = QKVW * Cc / 4, n1 = Cc * DH / 4, n2 = HID * Cc / 4, n3 = Cc * HID / 4;
        int tot = n0 + n1 + n2 + n3;
        k_half_all<<<(tot + 255) / 256, 256>>>((const float4*)qkv_w, n0,
                                               (const float4*)proj_w, n1,
                                               (const float4*)fc1_w, n2,
                                               (const float4*)fc2_w, n3);
    }
    {
        int tot = HEADS * Nt * Nt;
        k_bias_expand<<<(tot + 255) / 256, 256>>>(attn_bia, bias_idx, n_off);
    }
    k_win_ln<<<M_ATT / 8, 256>>>(x, ln_aw, ln_ab);
    k_gemm_qkv<<<dim3(QKVW / 128, (M_ATT + 127) / 128), 512, SMEM_GEMM>>>(qkv_b);
    k_attn<<<NW * HEADS, 256, SMEM_ATTN>>>();
    k_gemm_proj<<<dim3(Cc / 128, (M_ATT + 127) / 128), 512, SMEM_GEMM>>>(proj_b, x);
    {
        int tot = B_ * Hh * Ww * (Cc / 4);
        k_conv_bn<<<(tot + 255) / 256, 256>>>(conv_w, bn_w, bn_b, bn_m, bn_v);
    }
    k_ln_mlp<<<M_MLP / 8, 256>>>(ln_mw, ln_mb);
    k_gemm_fc1<<<dim3(HID / 128, M_MLP / 128), 512, SMEM_GEMM>>>(fc1_b);
    k_gemm_fc2<<<dim3(Cc / 128, M_MLP / 128), 512, SMEM_GEMM>>>(fc2_b, out);
}

// round 12
// speedup vs baseline: 5.3460x; 1.2259x over previous
#include <cuda_runtime.h>
#include <cuda_fp16.h>
#include <math.h>
#include <stdint.h>

// ---------------- problem constants ----------------
#define B_      8
#define Hh      64
#define Ww      64
#define Cc      384
#define HEADS   12
#define WSs     14
#define KD      32
#define Nt      196
#define NW      200
#define M_ATT   39200
#define L_      4096
#define M_MLP   32768
#define HID     1536
#define DH      384
#define QKVW    1152
#define SCALE_F 0.17677669529663687f
#define EPS_F   1e-5f

// attention tiling: fp16 smem, 208 rows x 40-half stride, q/k/v
#define NTP        208
#define AQ_STR     40
#define SMEM_ATTN  (3 * NTP * AQ_STR * 2)

// fp16 gemm smem: 3 stages x (A[128][40] + B[128][40]) halfs
#define GST_BYTES   20480
#define SMEM_GEMM   (3 * GST_BYTES)

// ---------------- scratch ----------------
__device__ __align__(16) __half g_xn[M_ATT * Cc];
__device__ __align__(16) __half g_qkv[(size_t)M_ATT * QKVW];   // fp16, q pre-scaled
__device__ __align__(16) __half g_attno[M_ATT * Cc];
__device__ float  g_x1[M_MLP * Cc];
__device__ float  g_x2[M_MLP * Cc];
__device__ __align__(16) __half g_h1[(size_t)M_MLP * HID];
__device__ float  g_bias[HEADS * Nt * Nt];
__device__ __align__(16) __half g_wq[QKVW * Cc];
__device__ __align__(16) __half g_wp[Cc * DH];
__device__ __align__(16) __half g_w1[HID * Cc];
__device__ __align__(16) __half g_w2[Cc * HID];

// ---------------- helpers ----------------
__device__ __forceinline__ void mma_f16(float* c, const uint32_t* a, const uint32_t* b) {
    asm volatile(
        "mma.sync.aligned.m16n8k16.row.col.f32.f16.f16.f32 "
        "{%0,%1,%2,%3}, {%4,%5,%6,%7}, {%8,%9}, {%0,%1,%2,%3};\n"
        : "+f"(c[0]), "+f"(c[1]), "+f"(c[2]), "+f"(c[3])
        : "r"(a[0]), "r"(a[1]), "r"(a[2]), "r"(a[3]), "r"(b[0]), "r"(b[1]));
}

__device__ __forceinline__ void ldsm_x4(uint32_t* r, uint32_t saddr) {
    asm volatile("ldmatrix.sync.aligned.m8n8.x4.shared.b16 {%0,%1,%2,%3}, [%4];"
                 : "=r"(r[0]), "=r"(r[1]), "=r"(r[2]), "=r"(r[3]) : "r"(saddr));
}

__device__ __forceinline__ void ldsm_x4_t(uint32_t* r, uint32_t saddr) {
    asm volatile("ldmatrix.sync.aligned.m8n8.x4.trans.shared.b16 {%0,%1,%2,%3}, [%4];"
                 : "=r"(r[0]), "=r"(r[1]), "=r"(r[2]), "=r"(r[3]) : "r"(saddr));
}

__device__ __forceinline__ void cp_async16(uint32_t saddr, const void* gptr, int srcbytes) {
    asm volatile("cp.async.cg.shared.global [%0], [%1], 16, %2;\n"
                 :: "r"(saddr), "l"(gptr), "r"(srcbytes));
}

__device__ __forceinline__ uint32_t smem_u32(const void* p) {
    uint32_t a;
    asm("{ .reg .u64 t; cvta.to.shared.u64 t, %1; cvt.u32.u64 %0, t; }" : "=r"(a) : "l"(p));
    return a;
}

__device__ __forceinline__ uint32_t h2u(__half2 h) {
    return *(uint32_t*)&h;
}

// ---------------- weight conversion fp32 -> fp16 ----------------
__global__ void k_half_all(const float4* __restrict__ s0, int n0,
                           const float4* __restrict__ s1, int n1,
                           const float4* __restrict__ s2, int n2,
                           const float4* __restrict__ s3, int n3) {
    int i = blockIdx.x * blockDim.x + threadIdx.x;
    const float4* src; __half* dst; int j = i;
    if (j < n0) { src = s0; dst = g_wq; }
    else if ((j -= n0) < n1) { src = s1; dst = g_wp; }
    else if ((j -= n1) < n2) { src = s2; dst = g_w1; }
    else if ((j -= n2) < n3) { src = s3; dst = g_w2; }
    else return;
    float4 v = src[j];
    __half2* d2 = (__half2*)(dst + 4 * (size_t)j);
    d2[0] = __floats2half2_rn(v.x, v.y);
    d2[1] = __floats2half2_rn(v.z, v.w);
}

// ---------------- kernel: expand bias table ----------------
__global__ void k_bias_expand(const float* __restrict__ ab,
                              const int* __restrict__ bidx, int n_off) {
    int i = blockIdx.x * blockDim.x + threadIdx.x;
    if (i >= HEADS * Nt * Nt) return;
    int h  = i / (Nt * Nt);
    int ij = i - h * (Nt * Nt);
    g_bias[i] = ab[h * n_off + bidx[ij]];
}

// ---------------- kernel: window partition + LayerNorm (fp16 out) ---------
__global__ void k_win_ln(const float* __restrict__ x,
                         const float* __restrict__ w,
                         const float* __restrict__ b) {
    int warp = (blockIdx.x * blockDim.x + threadIdx.x) >> 5;
    int lane = threadIdx.x & 31;
    if (warp >= M_ATT) return;
    int wi = warp / Nt, t = warp - wi * Nt;
    int bb = wi / 25; int rem = wi - bb * 25;
    int wy = rem / 5, wx = rem - wy * 5;
    int ty = t / WSs, tx = t - ty * WSs;
    int gy = wy * WSs + ty, gx = wx * WSs + tx;
    bool valid = (gy < Hh) && (gx < Ww);
    const float* src = x + ((size_t)bb * L_ + (size_t)gy * Ww + gx) * Cc;

    float vals[12];
    float s = 0.f, s2 = 0.f;
#pragma unroll
    for (int i = 0; i < 12; i++) {
        float v = valid ? src[lane + i * 32] : 0.f;
        vals[i] = v; s += v; s2 += v * v;
    }
#pragma unroll
    for (int o = 16; o > 0; o >>= 1) {
        s  += __shfl_xor_sync(0xffffffffu, s,  o);
        s2 += __shfl_xor_sync(0xffffffffu, s2, o);
    }
    float mean = s * (1.f / Cc);
    float var  = s2 * (1.f / Cc) - mean * mean;
    float rstd = rsqrtf(var + EPS_F);
    __half* dst = g_xn + (size_t)warp * Cc;
#pragma unroll
    for (int i = 0; i < 12; i++) {
        int c = lane + i * 32;
        dst[c] = __float2half((vals[i] - mean) * rstd * w[c] + b[c]);
    }
}

// ---------------- kernel: MLP LayerNorm (fp16 out) ----------------
__global__ void k_ln_mlp(const float* __restrict__ w,
                         const float* __restrict__ b) {
    int warp = (blockIdx.x * blockDim.x + threadIdx.x) >> 5;
    int lane = threadIdx.x & 31;
    if (warp >= M_MLP) return;
    const float* src = g_x2 + (size_t)warp * Cc;
    float vals[12];
    float s = 0.f, s2 = 0.f;
#pragma unroll
    for (int i = 0; i < 12; i++) {
        float v = src[lane + i * 32];
        vals[i] = v; s += v; s2 += v * v;
    }
#pragma unroll
    for (int o = 16; o > 0; o >>= 1) {
        s  += __shfl_xor_sync(0xffffffffu, s,  o);
        s2 += __shfl_xor_sync(0xffffffffu, s2, o);
    }
    float mean = s * (1.f / Cc);
    float var  = s2 * (1.f / Cc) - mean * mean;
    float rstd = rsqrtf(var + EPS_F);
    __half* dst = g_xn + (size_t)warp * Cc;
#pragma unroll
    for (int i = 0; i < 12; i++) {
        int c = lane + i * 32;
        dst[c] = __float2half((vals[i] - mean) * rstd * w[c] + b[c]);
    }
}

// ---------------- fp16 GEMM (mainloop unchanged; vectorized epilogue) -----
// EPI: 0 = qkv fp16 out with q-scale, 1 = GELU fp16 out,
//      2 = proj un-window+residual, 3 = residual add
template <int EPI, int M, int Nn, int K>
__device__ __forceinline__ void gemm_f16_body(const __half* __restrict__ A,
                                              const __half* __restrict__ Bw,
                                              const float* __restrict__ bias,
                                              float* __restrict__ Cout,
                                              const float* __restrict__ res) {
    extern __shared__ __align__(16) char smraw[];
    const int tid = threadIdx.x, lane = tid & 31, wid = tid >> 5;
    const int g = lane >> 2, tig = lane & 3;
    const int warp_m = wid >> 2, warp_n = wid & 3;
    const int bm = blockIdx.y * 128, bn = blockIdx.x * 128;
    const int arow = tid >> 2, seg = tid & 3;

    const int r0 = bm + arow;
    const bool v0 = ((M % 128) == 0) || (r0 < M);
    const int sz0 = v0 ? 16 : 0;
    const __half* a0b = A  + (size_t)(v0 ? r0 : 0) * K + seg * 8;
    const __half* b0b = Bw + (size_t)(bn + arow) * K + seg * 8;
    const uint32_t smb = smem_u32(smraw);
    const uint32_t sa0 = smb + arow * 80 + seg * 16;
    const uint32_t sb0 = sa0 + 10240;

    const int a_row = (lane & 15), a_k = 8 * (lane >> 4);
    const int b_row = (lane >> 4) * 8 + (lane & 7), b_k = 8 * ((lane >> 3) & 1);
    const uint32_t aA = smb + ((warp_m * 32 + a_row) * 40 + a_k) * 2;
    const uint32_t aB = smb + 10240 + ((warp_n * 32 + b_row) * 40 + b_k) * 2;

    const int KT = K / 32;
    auto load_stage = [&](int s, int kt) {
        int kc = kt * 32;
        uint32_t so = (uint32_t)(s * GST_BYTES);
        cp_async16(sa0 + so, a0b + kc, sz0);
        cp_async16(sb0 + so, b0b + kc, 16);
        asm volatile("cp.async.commit_group;\n");
    };

    float acc[2][4][4];
#pragma unroll
    for (int mt = 0; mt < 2; mt++)
#pragma unroll
        for (int nt = 0; nt < 4; nt++)
#pragma unroll
            for (int r = 0; r < 4; r++) acc[mt][nt][r] = 0.f;

    load_stage(0, 0);
    load_stage(1, 1);

    for (int kt = 0; kt < KT; kt++) {
        if (kt + 1 < KT) {
            asm volatile("cp.async.wait_group 1;\n");
        } else {
            asm volatile("cp.async.wait_group 0;\n");
        }
        __syncthreads();
        if (kt + 2 < KT) load_stage((kt + 2) % 3, kt + 2);

        const uint32_t st = (uint32_t)((kt % 3) * GST_BYTES);
#pragma unroll
        for (int ks = 0; ks < 2; ks++) {
            const int kb = ks * 16;
            uint32_t afr[2][4], bfr2[2][4];
            ldsm_x4(afr[0], aA + st + kb * 2);
            ldsm_x4(afr[1], aA + st + (16 * 40 + kb) * 2);
            ldsm_x4(bfr2[0], aB + st + kb * 2);
            ldsm_x4(bfr2[1], aB + st + (16 * 40 + kb) * 2);
#pragma unroll
            for (int mt = 0; mt < 2; mt++) {
                mma_f16(acc[mt][0], afr[mt], &bfr2[0][0]);
                mma_f16(acc[mt][1], afr[mt], &bfr2[0][2]);
                mma_f16(acc[mt][2], afr[mt], &bfr2[1][0]);
                mma_f16(acc[mt][3], afr[mt], &bfr2[1][2]);
            }
        }
    }

    // ---------- vectorized epilogue: one 2-col pair per store ----------
#pragma unroll
    for (int mt = 0; mt < 2; mt++) {
        const int m0 = bm + warp_m * 32 + mt * 16 + g;
        const int m1 = m0 + 8;
        const bool m0v = ((M % 128) == 0) || (m0 < M);
        const bool m1v = ((M % 128) == 0) || (m1 < M);
#pragma unroll
        for (int nt = 0; nt < 4; nt++) {
            const int nn = bn + warp_n * 32 + nt * 8 + tig * 2;
            const float2 bv = *(const float2*)&bias[nn];
            float p00 = acc[mt][nt][0] + bv.x, p01 = acc[mt][nt][1] + bv.y;
            float p10 = acc[mt][nt][2] + bv.x, p11 = acc[mt][nt][3] + bv.y;
            if (EPI == 0) {
                const float sc = ((nn % 96) < 32) ? SCALE_F : 1.f;
                if (m0v) *(__half2*)((__half*)Cout + (size_t)m0 * Nn + nn) =
                             __floats2half2_rn(p00 * sc, p01 * sc);
                if (m1v) *(__half2*)((__half*)Cout + (size_t)m1 * Nn + nn) =
                             __floats2half2_rn(p10 * sc, p11 * sc);
            } else if (EPI == 1) {
                float g00 = 0.5f * p00 * (1.f + erff(p00 * 0.70710678118654752f));
                float g01 = 0.5f * p01 * (1.f + erff(p01 * 0.70710678118654752f));
                float g10 = 0.5f * p10 * (1.f + erff(p10 * 0.70710678118654752f));
                float g11 = 0.5f * p11 * (1.f + erff(p11 * 0.70710678118654752f));
                if (m0v) *(__half2*)((__half*)Cout + (size_t)m0 * Nn + nn) =
                             __floats2half2_rn(g00, g01);
                if (m1v) *(__half2*)((__half*)Cout + (size_t)m1 * Nn + nn) =
                             __floats2half2_rn(g10, g11);
            } else if (EPI == 2) {
#pragma unroll
                for (int rr = 0; rr < 2; rr++) {
                    int m = rr ? m1 : m0;
                    if (((M % 128) != 0) && (m >= M)) continue;
                    int wi = m / Nt, t = m - wi * Nt;
                    int bb2 = wi / 25; int rem = wi - bb2 * 25;
                    int wy = rem / 5, wx = rem - wy * 5;
                    int ty = t / WSs, tx = t - ty * WSs;
                    int gy = wy * WSs + ty, gx = wx * WSs + tx;
                    if (gy < Hh && gx < Ww) {
                        size_t o = ((size_t)bb2 * L_ + (size_t)gy * Ww + gx) * Cc + nn;
                        float2 rv = *(const float2*)&res[o];
                        float2 ov;
                        ov.x = rv.x + (rr ? p10 : p00);
                        ov.y = rv.y + (rr ? p11 : p01);
                        *(float2*)&Cout[o] = ov;
                    }
                }
            } else {
                if (m0v) {
                    size_t o = (size_t)m0 * Nn + nn;
                    float2 rv = *(const float2*)&res[o];
                    *(float2*)&Cout[o] = make_float2(p00 + rv.x, p01 + rv.y);
                }
                if (m1v) {
                    size_t o = (size_t)m1 * Nn + nn;
                    float2 rv = *(const float2*)&res[o];
                    *(float2*)&Cout[o] = make_float2(p10 + rv.x, p11 + rv.y);
                }
            }
        }
    }
}

__global__ __launch_bounds__(512, 2) void k_gemm_qkv(const float* __restrict__ b) {
    gemm_f16_body<0, M_ATT, QKVW, Cc>(g_xn, g_wq, b, (float*)g_qkv, nullptr);
}
__global__ __launch_bounds__(512, 2) void k_gemm_proj(const float* __restrict__ b,
                                                      const float* __restrict__ x) {
    gemm_f16_body<2, M_ATT, Cc, DH>(g_attno, g_wp, b, g_x1, x);
}
__global__ __launch_bounds__(512, 2) void k_gemm_fc1(const float* __restrict__ b) {
    gemm_f16_body<1, M_MLP, HID, Cc>(g_xn, g_w1, b, (float*)g_h1, nullptr);
}
__global__ __launch_bounds__(512, 2) void k_gemm_fc2(const float* __restrict__ b,
                                                     float* __restrict__ out) {
    gemm_f16_body<3, M_MLP, Cc, HID>(g_h1, g_w2, b, out, g_x2);
}

// ---------------- attention chunk step (online softmax) ----------------
template <int NTILES>
__device__ __forceinline__ void attn_chunk(
    int colbase, uint32_t smb, const uint32_t (&aq)[2][4],
    const float* __restrict__ bias_h, int row0, int row1, bool r0v, bool r1v,
    int lane, uint32_t vaddr0,
    float& m0, float& m1, float& l0, float& l1, float (&oacc)[4][4])
{
    const int tig = lane & 3;
    const int b_row = (lane >> 4) * 8 + (lane & 7), b_k = 8 * ((lane >> 3) & 1);

    float acc[NTILES][4];
#pragma unroll
    for (int np = 0; np < NTILES / 2; np++) {
        uint32_t ka = smb + (uint32_t)(NTP * AQ_STR * 2) +
                      ((colbase + np * 16 + b_row) * AQ_STR + b_k) * 2;
        uint32_t bf0[4], bf1[4];
        ldsm_x4(bf0, ka);
        ldsm_x4(bf1, ka + 32);
        float* a0 = acc[2 * np];
        float* a1 = acc[2 * np + 1];
        a0[0] = a0[1] = a0[2] = a0[3] = 0.f;
        a1[0] = a1[1] = a1[2] = a1[3] = 0.f;
        mma_f16(a0, aq[0], &bf0[0]);
        mma_f16(a0, aq[1], &bf1[0]);
        mma_f16(a1, aq[0], &bf0[2]);
        mma_f16(a1, aq[1], &bf1[2]);
    }

    float cm0 = -1e30f, cm1 = -1e30f;
#pragma unroll
    for (int nt = 0; nt < NTILES; nt++) {
        int col = colbase + nt * 8 + tig * 2;
        bool cv = col < Nt;
        float2 b0 = (cv && r0v) ? *(const float2*)(bias_h + (size_t)row0 * Nt + col)
                                : make_float2(0.f, 0.f);
        float2 b1 = (cv && r1v) ? *(const float2*)(bias_h + (size_t)row1 * Nt + col)
                                : make_float2(0.f, 0.f);
        acc[nt][0] = cv ? acc[nt][0] + b0.x : -1e30f;
        acc[nt][1] = cv ? acc[nt][1] + b0.y : -1e30f;
        acc[nt][2] = cv ? acc[nt][2] + b1.x : -1e30f;
        acc[nt][3] = cv ? acc[nt][3] + b1.y : -1e30f;
        cm0 = fmaxf(cm0, fmaxf(acc[nt][0], acc[nt][1]));
        cm1 = fmaxf(cm1, fmaxf(acc[nt][2], acc[nt][3]));
    }
    cm0 = fmaxf(cm0, __shfl_xor_sync(0xffffffffu, cm0, 1));
    cm0 = fmaxf(cm0, __shfl_xor_sync(0xffffffffu, cm0, 2));
    cm1 = fmaxf(cm1, __shfl_xor_sync(0xffffffffu, cm1, 1));
    cm1 = fmaxf(cm1, __shfl_xor_sync(0xffffffffu, cm1, 2));

    float mn0 = fmaxf(m0, cm0), mn1 = fmaxf(m1, cm1);
    float c0 = __expf(m0 - mn0), c1 = __expf(m1 - mn1);

    float s0 = 0.f, s1 = 0.f;
#pragma unroll
    for (int nt = 0; nt < NTILES; nt++) {
        acc[nt][0] = __expf(acc[nt][0] - mn0); s0 += acc[nt][0];
        acc[nt][1] = __expf(acc[nt][1] - mn0); s0 += acc[nt][1];
        acc[nt][2] = __expf(acc[nt][2] - mn1); s1 += acc[nt][2];
        acc[nt][3] = __expf(acc[nt][3] - mn1); s1 += acc[nt][3];
    }
    s0 += __shfl_xor_sync(0xffffffffu, s0, 1);
    s0 += __shfl_xor_sync(0xffffffffu, s0, 2);
    s1 += __shfl_xor_sync(0xffffffffu, s1, 1);
    s1 += __shfl_xor_sync(0xffffffffu, s1, 2);
    l0 = l0 * c0 + s0;
    l1 = l1 * c1 + s1;
    m0 = mn0; m1 = mn1;

#pragma unroll
    for (int nt = 0; nt < 4; nt++) {
        oacc[nt][0] *= c0; oacc[nt][1] *= c0;
        oacc[nt][2] *= c1; oacc[nt][3] *= c1;
    }

#pragma unroll
    for (int kk = 0; kk < NTILES / 2; kk++) {
        uint32_t pa[4];
        pa[0] = h2u(__floats2half2_rn(acc[2*kk  ][0], acc[2*kk  ][1]));
        pa[1] = h2u(__floats2half2_rn(acc[2*kk  ][2], acc[2*kk  ][3]));
        pa[2] = h2u(__floats2half2_rn(acc[2*kk+1][0], acc[2*kk+1][1]));
        pa[3] = h2u(__floats2half2_rn(acc[2*kk+1][2], acc[2*kk+1][3]));
        uint32_t vb0[4], vb1[4];
        uint32_t va = vaddr0 + (uint32_t)((colbase + kk * 16) * AQ_STR * 2);
        ldsm_x4_t(vb0, va);
        ldsm_x4_t(vb1, va + 32);
        mma_f16(oacc[0], pa, &vb0[0]);
        mma_f16(oacc[1], pa, &vb0[2]);
        mma_f16(oacc[2], pa, &vb1[0]);
        mma_f16(oacc[3], pa, &vb1[2]);
    }
}

// ---------------- fp16 tensor-core attention, 2-chunk online softmax ------
__global__ __launch_bounds__(256, 2) void k_attn() {
    extern __shared__ __align__(16) __half smh[];
    __half* qs = smh;
    __half* ks = smh + NTP * AQ_STR;
    __half* vs = smh + 2 * NTP * AQ_STR;

    const int blk = blockIdx.x;
    const int w = blk / HEADS, h = blk - w * HEADS;
    const __half* base = g_qkv + (size_t)w * Nt * QKVW + h * 96;
    const int tid = threadIdx.x, lane = tid & 31, wid = tid >> 5;
    const int g = lane >> 2, tig = lane & 3;
    const uint32_t smb = smem_u32(smh);

    for (int idx = tid; idx < NTP * 4; idx += 256) {
        int r = idx >> 2, d8 = (idx & 3) * 8;
        uint4 q4, k4, v4;
        if (r < Nt) {
            const __half* rp = base + (size_t)r * QKVW;
            q4 = *(const uint4*)(rp + d8);
            k4 = *(const uint4*)(rp + 32 + d8);
            v4 = *(const uint4*)(rp + 64 + d8);
        } else {
            q4 = k4 = v4 = make_uint4(0, 0, 0, 0);
        }
        *(uint4*)(qs + r * AQ_STR + d8) = q4;
        *(uint4*)(ks + r * AQ_STR + d8) = k4;
        *(uint4*)(vs + r * AQ_STR + d8) = v4;
    }
    __syncthreads();

    const float* bias_h = g_bias + (size_t)h * Nt * Nt;

    const int a_row = (lane & 15), a_k = 8 * (lane >> 4);
    const uint32_t vs_off = (uint32_t)(2 * NTP * AQ_STR * 2);
    const uint32_t vaddr0 = smb + vs_off + (((lane & 15)) * AQ_STR + 8 * (lane >> 4)) * 2;

    for (int tt = wid; tt < 13; tt += 8) {
        const int row0 = tt * 16 + g, row1 = row0 + 8;
        const bool r0v = row0 < Nt, r1v = row1 < Nt;

        uint32_t aq[2][4];
        {
            uint32_t qa = smb + ((tt * 16 + a_row) * AQ_STR + a_k) * 2;
            ldsm_x4(aq[0], qa);
            ldsm_x4(aq[1], qa + 32);
        }

        float m0 = -1e30f, m1 = -1e30f, l0 = 0.f, l1 = 0.f;
        float oacc[4][4];
#pragma unroll
        for (int nt = 0; nt < 4; nt++)
            oacc[nt][0] = oacc[nt][1] = oacc[nt][2] = oacc[nt][3] = 0.f;

        attn_chunk<14>(0,   smb, aq, bias_h, row0, row1, r0v, r1v, lane, vaddr0,
                       m0, m1, l0, l1, oacc);
        attn_chunk<12>(112, smb, aq, bias_h, row0, row1, r0v, r1v, lane, vaddr0,
                       m0, m1, l0, l1, oacc);

        const float inv0 = 1.f / l0, inv1 = 1.f / l1;
        if (r0v) {
            __half* op = g_attno + ((size_t)(w * Nt + row0)) * DH + h * KD;
#pragma unroll
            for (int nt = 0; nt < 4; nt++)
                *(__half2*)(op + nt * 8 + tig * 2) =
                    __floats2half2_rn(oacc[nt][0] * inv0, oacc[nt][1] * inv0);
        }
        if (r1v) {
            __half* op = g_attno + ((size_t)(w * Nt + row1)) * DH + h * KD;
#pragma unroll
            for (int nt = 0; nt < 4; nt++)
                *(__half2*)(op + nt * 8 + tig * 2) =
                    __floats2half2_rn(oacc[nt][2] * inv1, oacc[nt][3] * inv1);
        }
    }
}

// ---------------- depthwise 3x3 conv + BN ----------------
__global__ void k_conv_bn(const float* __restrict__ cw,
                          const float* __restrict__ bnw,
                          const float* __restrict__ bnb,
                          const float* __restrict__ bnm,
                          const float* __restrict__ bnv) {
    int idx = blockIdx.x * blockDim.x + threadIdx.x;
    const int C4 = Cc / 4;
    const int total = B_ * Hh * Ww * C4;
    if (idx >= total) return;
    int c4 = idx % C4;
    int x  = (idx / C4) % Ww;
    int y  = (idx / (C4 * Ww)) % Hh;
    int b  = idx / (C4 * Ww * Hh);
    int c0 = c4 * 4;

    float4 acc = make_float4(0.f, 0.f, 0.f, 0.f);
#pragma unroll
    for (int ky = 0; ky < 3; ky++) {
        int yy = y + ky - 1;
        if (yy < 0 || yy >= Hh) continue;
#pragma unroll
        for (int kx = 0; kx < 3; kx++) {
            int xx = x + kx - 1;
            if (xx < 0 || xx >= Ww) continue;
            float4 in = *(const float4*)&g_x1[((size_t)b * L_ + (size_t)yy * Ww + xx) * Cc + c0];
            int wo = ky * 3 + kx;
            acc.x += in.x * cw[(c0 + 0) * 9 + wo];
            acc.y += in.y * cw[(c0 + 1) * 9 + wo];
            acc.z += in.z * cw[(c0 + 2) * 9 + wo];
            acc.w += in.w * cw[(c0 + 3) * 9 + wo];
        }
    }
    float4 outv;
    outv.x = (acc.x - bnm[c0 + 0]) * (rsqrtf(bnv[c0 + 0] + 1e-5f) * bnw[c0 + 0]) + bnb[c0 + 0];
    outv.y = (acc.y - bnm[c0 + 1]) * (rsqrtf(bnv[c0 + 1] + 1e-5f) * bnw[c0 + 1]) + bnb[c0 + 1];
    outv.z = (acc.z - bnm[c0 + 2]) * (rsqrtf(bnv[c0 + 2] + 1e-5f) * bnw[c0 + 2]) + bnb[c0 + 2];
    outv.w = (acc.w - bnm[c0 + 3]) * (rsqrtf(bnv[c0 + 3] + 1e-5f) * bnw[c0 + 3]) + bnb[c0 + 3];
    *(float4*)&g_x2[(size_t)idx * 4] = outv;
}

// ---------------- launcher ----------------
extern "C" void kernel_launch(void* const* d_in, const int* in_sizes, int n_in,
                              void* d_out, int out_size) {
    const float* x        = (const float*)d_in[0];
    const float* ln_aw    = (const float*)d_in[1];
    const float* ln_ab    = (const float*)d_in[2];
    const float* qkv_w    = (const float*)d_in[3];
    const float* qkv_b    = (const float*)d_in[4];
    const float* proj_w   = (const float*)d_in[5];
    const float* proj_b   = (const float*)d_in[6];
    const float* attn_bia = (const float*)d_in[7];
    const float* conv_w   = (const float*)d_in[8];
    const float* bn_w     = (const float*)d_in[9];
    const float* bn_b     = (const float*)d_in[10];
    const float* bn_m     = (const float*)d_in[11];
    const float* bn_v     = (const float*)d_in[12];
    const float* ln_mw    = (const float*)d_in[13];
    const float* ln_mb    = (const float*)d_in[14];
    const float* fc1_w    = (const float*)d_in[15];
    const float* fc1_b    = (const float*)d_in[16];
    const float* fc2_w    = (const float*)d_in[17];
    const float* fc2_b    = (const float*)d_in[18];
    const int*   bias_idx = (const int*)d_in[19];
    float* out = (float*)d_out;

    int n_off = in_sizes[7] / HEADS;

    cudaFuncSetAttribute(k_gemm_qkv,  cudaFuncAttributeMaxDynamicSharedMemorySize, SMEM_GEMM);
    cudaFuncSetAttribute(k_gemm_proj, cudaFuncAttributeMaxDynamicSharedMemorySize, SMEM_GEMM);
    cudaFuncSetAttribute(k_gemm_fc1,  cudaFuncAttributeMaxDynamicSharedMemorySize, SMEM_GEMM);
    cudaFuncSetAttribute(k_gemm_fc2,  cudaFuncAttributeMaxDynamicSharedMemorySize, SMEM_GEMM);
    cudaFuncSetAttribute(k_attn,      cudaFuncAttributeMaxDynamicSharedMemorySize, SMEM_ATTN);

    {
        int n0 = QKVW * Cc / 4, n1 = Cc * DH / 4, n2 = HID * Cc / 4, n3 = Cc * HID / 4;
        int tot = n0 + n1 + n2 + n3;
        k_half_all<<<(tot + 255) / 256, 256>>>((const float4*)qkv_w, n0,
                                               (const float4*)proj_w, n1,
                                               (const float4*)fc1_w, n2,
                                               (const float4*)fc2_w, n3);
    }
    {
        int tot = HEADS * Nt * Nt;
        k_bias_expand<<<(tot + 255) / 256, 256>>>(attn_bia, bias_idx, n_off);
    }
    k_win_ln<<<M_ATT / 8, 256>>>(x, ln_aw, ln_ab);
    k_gemm_qkv<<<dim3(QKVW / 128, (M_ATT + 127) / 128), 512, SMEM_GEMM>>>(qkv_b);
    k_attn<<<NW * HEADS, 256, SMEM_ATTN>>>();
    k_gemm_proj<<<dim3(Cc / 128, (M_ATT + 127) / 128), 512, SMEM_GEMM>>>(proj_b, x);
    {
        int tot = B_ * Hh * Ww * (Cc / 4);
        k_conv_bn<<<(tot + 255) / 256, 256>>>(conv_w, bn_w, bn_b, bn_m, bn_v);
    }
    k_ln_mlp<<<M_MLP / 8, 256>>>(ln_mw, ln_mb);
    k_gemm_fc1<<<dim3(HID / 128, M_MLP / 128), 512, SMEM_GEMM>>>(fc1_b);
    k_gemm_fc2<<<dim3(Cc / 128, M_MLP / 128), 512, SMEM_GEMM>>>(fc2_b, out);
}